// round 11
// baseline (speedup 1.0000x reference)
#include <cuda_runtime.h>
#include <cuda_bf16.h>
#include <cuda_fp16.h>
#include <math.h>
#include <cstdint>

// Problem constants
#define BATCH 4
#define TSEQ  1024
#define DMODEL 1024
#define NH 16
#define DHEAD 64
#define QKV_N 3072   // 3*DMODEL
#define MROWS 4096   // BATCH*TSEQ
#define KDIM 1024    // K is 1024 for both GEMMs
#define NT64 16      // k64-tiles (KDIM/64)

// Q scale: 1/sqrt(64) * log2(e)  (softmax done in exp2 domain)
#define QSCALE (0.125f * 1.44269504088896f)

// ---------------------------------------------------------------------------
// Scratch (device globals: allocation-free)
// ---------------------------------------------------------------------------
__device__ __half g_x16[(size_t)MROWS * DMODEL];         // x fp16 row-major
__device__ __half g_wq16[(size_t)QKV_N * DMODEL];        // Wqkv^T fp16 [N][K]
__device__ __half g_wp16[(size_t)DMODEL * DMODEL];       // Wproj^T fp16 [N][K]
__device__ __half g_ao16[(size_t)MROWS * DMODEL];        // attn out fp16
__device__ __half g_qf[(size_t)MROWS * DMODEL];          // Q scaled, single fp16
__device__ __half g_k16h[(size_t)MROWS * DMODEL];        // K fp16 hi
__device__ __half g_k16l[(size_t)MROWS * DMODEL];        // K fp16 lo
__device__ __nv_bfloat16 g_vh[(size_t)MROWS * DMODEL];   // V [row][h*64+dh]
__device__ __nv_bfloat16 g_vl[(size_t)MROWS * DMODEL];
__device__ __nv_bfloat16 g_vth[(size_t)MROWS * DMODEL];  // V^T [bh][dh][t]
__device__ __nv_bfloat16 g_vtl[(size_t)MROWS * DMODEL];

// ---------------------------------------------------------------------------
// PTX helpers (base ISA only — compute_103 virtual arch, no tcgen05)
// ---------------------------------------------------------------------------
__device__ __forceinline__ uint32_t smem_to_u32(const void* p) {
    uint32_t a;
    asm("{ .reg .u64 t; cvta.to.shared.u64 t, %1; cvt.u32.u64 %0, t; }"
        : "=r"(a) : "l"(p));
    return a;
}

#define CP_ASYNC16(smem, gptr) \
    asm volatile("cp.async.cg.shared.global [%0], [%1], 16;" \
        :: "r"(smem), "l"(gptr) : "memory")
#define CP_COMMIT() asm volatile("cp.async.commit_group;" ::: "memory")
#define CP_WAIT(n)  asm volatile("cp.async.wait_group %0;" :: "n"(n) : "memory")

#define LDSM_X4(r0, r1, r2, r3, addr) \
    asm volatile("ldmatrix.sync.aligned.m8n8.x4.shared.b16 {%0,%1,%2,%3}, [%4];" \
        : "=r"(r0), "=r"(r1), "=r"(r2), "=r"(r3) : "r"(addr))

#define MMA16816(c, a, b0, b1) \
    asm volatile("mma.sync.aligned.m16n8k16.row.col.f32.bf16.bf16.f32 " \
        "{%0,%1,%2,%3}, {%4,%5,%6,%7}, {%8,%9}, {%0,%1,%2,%3};" \
        : "+f"((c)[0]), "+f"((c)[1]), "+f"((c)[2]), "+f"((c)[3]) \
        : "r"((a)[0]), "r"((a)[1]), "r"((a)[2]), "r"((a)[3]), \
          "r"(b0), "r"(b1))

#define MMAF16(c, a, b0, b1) \
    asm volatile("mma.sync.aligned.m16n8k16.row.col.f32.f16.f16.f32 " \
        "{%0,%1,%2,%3}, {%4,%5,%6,%7}, {%8,%9}, {%0,%1,%2,%3};" \
        : "+f"((c)[0]), "+f"((c)[1]), "+f"((c)[2]), "+f"((c)[3]) \
        : "r"((a)[0]), "r"((a)[1]), "r"((a)[2]), "r"((a)[3]), \
          "r"(b0), "r"(b1))

// pack two floats to bf16x2 / f16x2 (lo addr half = first arg)
__device__ __forceinline__ uint32_t packbf(float lo, float hi) {
    uint32_t r;
    asm("cvt.rn.bf16x2.f32 %0, %1, %2;" : "=r"(r) : "f"(hi), "f"(lo));
    return r;
}
__device__ __forceinline__ uint32_t packhf(float lo, float hi) {
    uint32_t r;
    asm("cvt.rn.f16x2.f32 %0, %1, %2;" : "=r"(r) : "f"(hi), "f"(lo));
    return r;
}
__device__ __forceinline__ float ex2(float x) {
    float r;
    asm("ex2.approx.f32 %0, %1;" : "=f"(r) : "f"(x));
    return r;
}

// Swizzled byte offset within one 8KB matrix sub-tile (128 rows x 32 fp16):
// row-pair lines of 128B, chunk3 = (r&1)*4 + ch, XOR (r>>1)&7. (verified R7+)
__device__ __forceinline__ uint32_t sw_off(int r, int ch) {
    const uint32_t chunk3 = (uint32_t)(((r & 1) << 2) | ch);
    return (uint32_t)((r >> 1) * 128) + ((chunk3 ^ ((uint32_t)(r >> 1) & 7u)) << 4);
}

// ---------------------------------------------------------------------------
// FP16 single-product HMMA GEMM: C = A[M,K] @ (B[N,K])^T + bias
// CTA 128x128, K-tile 64 (two 8KB swizzled sub-tiles per matrix),
// 3-stage cp.async (32KB/stage), 2 CTAs/SM, 4 warps (2x2), warp tile 64x64.
// MODE 0: fp32 C out.  MODE 1: QKV epilogue -> qf16 / K split-f16 / V split-bf16
// ---------------------------------------------------------------------------
#define SUBB   8192
#define STAGEB 32768
#define NSTAGE 3
#define GEMM_SMEM (NSTAGE * STAGEB)

template <int MODE>
__global__ __launch_bounds__(128, 2) void gemm_f16(
    const __half* __restrict__ A, const __half* __restrict__ B,
    const float* __restrict__ bias, float* __restrict__ C,
    __half* __restrict__ qf,
    __half* __restrict__ kfh, __half* __restrict__ kfl,
    __nv_bfloat16* __restrict__ vh, __nv_bfloat16* __restrict__ vl,
    int Ntot)
{
    extern __shared__ char dsm[];
    const uint32_t sb = smem_to_u32(dsm);

    const int t    = threadIdx.x;
    const int lane = t & 31;
    const int wid  = t >> 5;
    const int wm   = wid >> 1;
    const int wn   = wid & 1;
    const int bm   = blockIdx.y << 7;
    const int bn   = blockIdx.x << 7;

    // cp.async plan: 2 matrices x 2 subtiles x 512 chunks / 128 thr = 16/thread
    const int rbase = t >> 2;
    const int ch0   = t & 3;
    uint32_t soff[16];
    const __half* gp[16];
#pragma unroll
    for (int m = 0; m < 2; m++)
#pragma unroll
        for (int sub = 0; sub < 2; sub++)
#pragma unroll
            for (int hh = 0; hh < 4; hh++) {
                const int r = rbase + hh * 32;
                const int i = m * 8 + sub * 4 + hh;
                soff[i] = (uint32_t)(m * 16384 + sub * SUBB) + sw_off(r, ch0);
                gp[i]   = (m ? B : A) +
                    (size_t)((m ? bn : bm) + r) * KDIM + sub * 32 + ch0 * 8;
            }

    const uint32_t a_base = sw_off(wm * 64 + (lane & 15), lane >> 4);
    const uint32_t b_base = sw_off(wn * 64 + (lane & 7) + ((lane >> 4) << 3),
                                   (lane >> 3) & 1);

    float acc[4][8][4];
#pragma unroll
    for (int mi = 0; mi < 4; mi++)
#pragma unroll
        for (int ni = 0; ni < 8; ni++)
#pragma unroll
            for (int e = 0; e < 4; e++) acc[mi][ni][e] = 0.0f;

    // prologue: stages 0 and 1
#pragma unroll
    for (int s = 0; s < NSTAGE - 1; s++) {
        const uint32_t st = sb + (uint32_t)s * STAGEB;
        const int ko = s * 64;
#pragma unroll
        for (int i = 0; i < 16; i++) CP_ASYNC16(st + soff[i], gp[i] + ko);
        CP_COMMIT();
    }

    int buf = 0, nbuf = NSTAGE - 1;
#pragma unroll 1
    for (int kt = 0; kt < NT64; kt++) {
        CP_WAIT(NSTAGE - 2);
        __syncthreads();

        if (kt + NSTAGE - 1 < NT64) {
            const uint32_t st = sb + (uint32_t)nbuf * STAGEB;
            const int ko = (kt + NSTAGE - 1) * 64;
#pragma unroll
            for (int i = 0; i < 16; i++) CP_ASYNC16(st + soff[i], gp[i] + ko);
        }
        CP_COMMIT();

        const uint32_t stg = sb + (uint32_t)buf * STAGEB;
        buf = (buf == NSTAGE - 1) ? 0 : buf + 1;
        nbuf = (nbuf == NSTAGE - 1) ? 0 : nbuf + 1;

#pragma unroll
        for (int ks = 0; ks < 4; ks++) {
            const uint32_t sub = (uint32_t)((ks >> 1) * SUBB);
            const uint32_t ksx = (uint32_t)((ks & 1) << 5);
            uint32_t ah[4][4];
#pragma unroll
            for (int mi = 0; mi < 4; mi++) {
                const uint32_t ao = sub + ((a_base + (uint32_t)(mi * 1024)) ^ ksx);
                LDSM_X4(ah[mi][0], ah[mi][1], ah[mi][2], ah[mi][3], stg + ao);
            }
            uint32_t rbh[4][4];
#pragma unroll
            for (int g = 0; g < 4; g++) {
                const uint32_t bo = 16384 + sub +
                    ((b_base + (uint32_t)(g * 1024)) ^ ksx);
                LDSM_X4(rbh[g][0], rbh[g][1], rbh[g][2], rbh[g][3], stg + bo);
            }
#pragma unroll
            for (int mi = 0; mi < 4; mi++)
#pragma unroll
                for (int ni = 0; ni < 8; ni++) {
                    const int g = ni >> 1, u = (ni & 1) * 2;
                    MMAF16(acc[mi][ni], ah[mi], rbh[g][u], rbh[g][u + 1]);
                }
        }
    }

    // ---- epilogue ----
    const int er = bm + wm * 64 + (lane >> 2);
    const int ec = bn + wn * 64 + (lane & 3) * 2;

    if (MODE == 0) {
#pragma unroll
        for (int ni = 0; ni < 8; ni++) {
            const int col = ec + ni * 8;
            const float2 bv = *reinterpret_cast<const float2*>(bias + col);
#pragma unroll
            for (int mi = 0; mi < 4; mi++) {
                const int r0 = er + mi * 16;
                float2 o0, o1;
                o0.x = acc[mi][ni][0] + bv.x;
                o0.y = acc[mi][ni][1] + bv.y;
                o1.x = acc[mi][ni][2] + bv.x;
                o1.y = acc[mi][ni][3] + bv.y;
                *reinterpret_cast<float2*>(C + (size_t)r0 * Ntot + col) = o0;
                *reinterpret_cast<float2*>(C + (size_t)(r0 + 8) * Ntot + col) = o1;
            }
        }
    } else {
        // seg 0 = Q (scaled, single fp16); 1 = K (split fp16); 2 = V (split bf16)
        const int seg = bn >> 10;
        const int ecl = ec & 1023;
#pragma unroll
        for (int ni = 0; ni < 8; ni++) {
            const int col = ec + ni * 8;
            const float2 bv = *reinterpret_cast<const float2*>(bias + col);
            const int cl = ecl + ni * 8;
#pragma unroll
            for (int mi = 0; mi < 4; mi++) {
                const int r0 = er + mi * 16;
                float v00 = acc[mi][ni][0] + bv.x;
                float v01 = acc[mi][ni][1] + bv.y;
                float v10 = acc[mi][ni][2] + bv.x;
                float v11 = acc[mi][ni][3] + bv.y;
                if (seg == 0) {
                    v00 *= QSCALE; v01 *= QSCALE; v10 *= QSCALE; v11 *= QSCALE;
                    *reinterpret_cast<uint32_t*>(qf + (size_t)r0 * 1024 + cl) =
                        packhf(v00, v01);
                    *reinterpret_cast<uint32_t*>(qf + (size_t)(r0 + 8) * 1024 + cl) =
                        packhf(v10, v11);
                } else if (seg == 1) {
                    const float h00 = __half2float(__float2half_rn(v00));
                    const float h01 = __half2float(__float2half_rn(v01));
                    const float h10 = __half2float(__float2half_rn(v10));
                    const float h11 = __half2float(__float2half_rn(v11));
                    *reinterpret_cast<uint32_t*>(kfh + (size_t)r0 * 1024 + cl) =
                        packhf(v00, v01);
                    *reinterpret_cast<uint32_t*>(kfl + (size_t)r0 * 1024 + cl) =
                        packhf(v00 - h00, v01 - h01);
                    *reinterpret_cast<uint32_t*>(kfh + (size_t)(r0 + 8) * 1024 + cl) =
                        packhf(v10, v11);
                    *reinterpret_cast<uint32_t*>(kfl + (size_t)(r0 + 8) * 1024 + cl) =
                        packhf(v10 - h10, v11 - h11);
                } else {
                    const float h00 = __bfloat162float(__float2bfloat16(v00));
                    const float h01 = __bfloat162float(__float2bfloat16(v01));
                    const float h10 = __bfloat162float(__float2bfloat16(v10));
                    const float h11 = __bfloat162float(__float2bfloat16(v11));
                    *reinterpret_cast<uint32_t*>(vh + (size_t)r0 * 1024 + cl) =
                        packbf(v00, v01);
                    *reinterpret_cast<uint32_t*>(vl + (size_t)r0 * 1024 + cl) =
                        packbf(v00 - h00, v01 - h01);
                    *reinterpret_cast<uint32_t*>(vh + (size_t)(r0 + 8) * 1024 + cl) =
                        packbf(v10, v11);
                    *reinterpret_cast<uint32_t*>(vl + (size_t)(r0 + 8) * 1024 + cl) =
                        packbf(v10 - h10, v11 - h11);
                }
            }
        }
    }
}

// ---------------------------------------------------------------------------
// fp32 -> fp16 convert, 4 elems/thread
// ---------------------------------------------------------------------------
__global__ __launch_bounds__(256) void convert_h(
    const float* __restrict__ A, __half* __restrict__ H)
{
    const int i = blockIdx.x * blockDim.x + threadIdx.x;
    const float4 v = reinterpret_cast<const float4*>(A)[i];
    uint2 o;
    o.x = packhf(v.x, v.y);
    o.y = packhf(v.z, v.w);
    *reinterpret_cast<uint2*>(H + (size_t)i * 4) = o;
}

// ---------------------------------------------------------------------------
// W[K][N] fp32 -> W^T[N][K] fp16 (transpose + convert), block (32,8)
// ---------------------------------------------------------------------------
__global__ __launch_bounds__(256) void convert_wT(
    const float* __restrict__ W, __half* __restrict__ T, int K, int N)
{
    __shared__ float tile[32][33];
    const int tx = threadIdx.x, ty = threadIdx.y;
    const int n0 = blockIdx.x * 32, k0 = blockIdx.y * 32;
#pragma unroll
    for (int i = 0; i < 4; i++)
        tile[ty + i * 8][tx] = W[(size_t)(k0 + ty + i * 8) * N + n0 + tx];
    __syncthreads();
#pragma unroll
    for (int i = 0; i < 4; i++) {
        const float v = tile[tx][ty + i * 8];
        T[(size_t)(n0 + ty + i * 8) * K + k0 + tx] = __float2half_rn(v);
    }
}

// ---------------------------------------------------------------------------
// V transpose: vh/vl [B*T][1024] -> vth/vtl [(b*16+h)*64+dh][1024] (col = t)
// ---------------------------------------------------------------------------
__global__ __launch_bounds__(256) void transpose_v(
    const __nv_bfloat16* __restrict__ vh, const __nv_bfloat16* __restrict__ vl,
    __nv_bfloat16* __restrict__ vth, __nv_bfloat16* __restrict__ vtl)
{
    __shared__ __nv_bfloat16 th[32][33], tl[32][33];
    const int tx = threadIdx.x, ty = threadIdx.y;
    const int c0 = blockIdx.x * 32;
    const int r0 = blockIdx.y * 32;
#pragma unroll
    for (int i = 0; i < 4; i++) {
        const size_t src = (size_t)(r0 + ty + i * 8) * 1024 + c0 + tx;
        th[ty + i * 8][tx] = vh[src];
        tl[ty + i * 8][tx] = vl[src];
    }
    __syncthreads();
    const int b = r0 >> 10;
    const int tbase = (r0 & 1023) + tx;
#pragma unroll
    for (int i = 0; i < 4; i++) {
        const int cp = c0 + ty + i * 8;
        const int hh = cp >> 6, dh = cp & 63;
        const size_t dst = (size_t)(((b * 16 + hh) * 64) + dh) * 1024 + tbase;
        vth[dst] = th[tx][ty + i * 8];
        vtl[dst] = tl[tx][ty + i * 8];
    }
}

// ---------------------------------------------------------------------------
// HMMA flash attention. S = q_f16 x (Kh+Kl)_f16 (2 products);
// PV = bf16 3-product (unchanged). Double-buffered K/V, exp2 softmax.
// Output: single fp16 row-major. Grid (4, B*H), q-tile pairs {7-bx, bx}.
// ---------------------------------------------------------------------------
#define ASTR 144
#define Q_OFF  0             // 18432: Q single fp16 (scaled)
#define K_OFF  18432         // 2 bufs x (Kh 9216 + Kl 9216)
#define V_OFF  55296         // 2 bufs x (Vth 9216 + Vtl 9216)
#define KVBUF  18432
#define MSK_OFF 92160
#define ATTN_SMEM (92160 + 512)

__global__ __launch_bounds__(256, 2) void attn_hmma(
    const __half* __restrict__ qf,
    const __half* __restrict__ kfh, const __half* __restrict__ kfl,
    const __nv_bfloat16* __restrict__ vth, const __nv_bfloat16* __restrict__ vtl,
    const int* __restrict__ mask,
    __half* __restrict__ ao)
{
    extern __shared__ char smc[];
    const uint32_t sb = smem_to_u32(smc);

    const int t    = threadIdx.x;
    const int lane = t & 31;
    const int w    = t >> 5;
    const int bh   = blockIdx.y;
    const int b    = bh >> 4;
    const int h    = bh & 15;
    float* msk_s = (float*)(smc + MSK_OFF);

    const uint32_t aq_base = sb + Q_OFF +
        (uint32_t)((16 * w + (lane & 15)) * ASTR + (lane >> 4) * 16);
    const uint32_t bk_base = sb + K_OFF +
        (uint32_t)(((lane & 7) + ((lane >> 4) << 3)) * ASTR + ((lane >> 3) & 1) * 16);
    const uint32_t bv_base = sb + V_OFF +
        (uint32_t)(((lane & 7) + ((lane >> 4) << 3)) * ASTR + ((lane >> 3) & 1) * 16);

#pragma unroll 1
    for (int pass = 0; pass < 2; pass++) {
        const int qt = pass ? (int)blockIdx.x : 7 - (int)blockIdx.x;
        __syncthreads();

        // ---- Q tile: 128 rows x 64 fp16 = 1024 chunks ----
#pragma unroll
        for (int p = 0; p < 4; p++) {
            const int idx = t + (p << 8);        // 0..1023
            const int row = idx >> 3;
            const int ch  = idx & 7;
            const __half* src = qf +
                (size_t)(b * 1024 + qt * 128 + row) * 1024 + h * 64 + ch * 8;
            CP_ASYNC16(sb + Q_OFF + row * ASTR + ch * 16, src);
        }
        CP_COMMIT();

        const int kmax = 2 * qt + 1;

        // ---- prologue: K/V for kt=0 into buffer 0, mask[0] ----
#pragma unroll
        for (int p = 0; p < 8; p++) {
            const int c   = t + (p << 8);    // 0..2047
            const int m   = c >> 9;          // 0=Kh 1=Kl 2=Vth 3=Vtl
            const int idx = c & 511;
            const int row = idx >> 3;
            const int ch  = idx & 7;
            const void* src;
            uint32_t dst;
            if (m == 0) {
                src = kfh + (size_t)(b * 1024 + row) * 1024 + h * 64 + ch * 8;
                dst = sb + K_OFF + row * ASTR + ch * 16;
            } else if (m == 1) {
                src = kfl + (size_t)(b * 1024 + row) * 1024 + h * 64 + ch * 8;
                dst = sb + K_OFF + 9216 + row * ASTR + ch * 16;
            } else if (m == 2) {
                src = vth + (size_t)(bh * 64 + row) * 1024 + ch * 8;
                dst = sb + V_OFF + row * ASTR + ch * 16;
            } else {
                src = vtl + (size_t)(bh * 64 + row) * 1024 + ch * 8;
                dst = sb + V_OFF + 9216 + row * ASTR + ch * 16;
            }
            CP_ASYNC16(dst, src);
        }
        if (t < 64)
            msk_s[t] = (mask[b * TSEQ + t] != 0) ? 0.0f : -1e30f;
        CP_COMMIT();

        float m0 = -1e30f, m1 = -1e30f, l0 = 0.0f, l1 = 0.0f;
        float of[8][4];
#pragma unroll
        for (int j = 0; j < 8; j++)
#pragma unroll
            for (int e = 0; e < 4; e++) of[j][e] = 0.0f;

        const int qrow_w = qt * 128 + 16 * w;
        const int r0g = qrow_w + (lane >> 2);

#pragma unroll 1
        for (int kt = 0; kt <= kmax; kt++) {
            CP_WAIT(0);
            __syncthreads();

            if (kt < kmax) {
                const uint32_t kb = (uint32_t)(((kt + 1) & 1) * KVBUF);
#pragma unroll
                for (int p = 0; p < 8; p++) {
                    const int c   = t + (p << 8);
                    const int m   = c >> 9;
                    const int idx = c & 511;
                    const int row = idx >> 3;
                    const int ch  = idx & 7;
                    const void* src;
                    uint32_t dst;
                    if (m == 0) {
                        src = kfh + (size_t)(b * 1024 + (kt + 1) * 64 + row) * 1024 + h * 64 + ch * 8;
                        dst = sb + K_OFF + kb + row * ASTR + ch * 16;
                    } else if (m == 1) {
                        src = kfl + (size_t)(b * 1024 + (kt + 1) * 64 + row) * 1024 + h * 64 + ch * 8;
                        dst = sb + K_OFF + kb + 9216 + row * ASTR + ch * 16;
                    } else if (m == 2) {
                        src = vth + (size_t)(bh * 64 + row) * 1024 + (kt + 1) * 64 + ch * 8;
                        dst = sb + V_OFF + kb + row * ASTR + ch * 16;
                    } else {
                        src = vtl + (size_t)(bh * 64 + row) * 1024 + (kt + 1) * 64 + ch * 8;
                        dst = sb + V_OFF + kb + 9216 + row * ASTR + ch * 16;
                    }
                    CP_ASYNC16(dst, src);
                }
                if (t < 64)
                    msk_s[((kt + 1) & 1) * 64 + t] =
                        (mask[b * TSEQ + (kt + 1) * 64 + t] != 0) ? 0.0f : -1e30f;
            }
            CP_COMMIT();

            const uint32_t kb = (uint32_t)((kt & 1) * KVBUF);
            const float* msk = msk_s + (kt & 1) * 64;

            // ---- S = q_f16 @ (Kh + Kl)^T (2 products) ----
            float s[8][4];
#pragma unroll
            for (int j = 0; j < 8; j++)
#pragma unroll
                for (int e = 0; e < 4; e++) s[j][e] = 0.0f;

#pragma unroll
            for (int ks = 0; ks < 4; ks++) {
                uint32_t aq[4];
                LDSM_X4(aq[0], aq[1], aq[2], aq[3], aq_base + ks * 32);
#pragma unroll
                for (int g = 0; g < 4; g++) {
                    uint32_t bkh[4], bkl[4];
                    LDSM_X4(bkh[0], bkh[1], bkh[2], bkh[3],
                            bk_base + kb + g * (16 * ASTR) + ks * 32);
                    LDSM_X4(bkl[0], bkl[1], bkl[2], bkl[3],
                            bk_base + kb + 9216 + g * (16 * ASTR) + ks * 32);
                    MMAF16(s[2 * g],     aq, bkh[0], bkh[1]);
                    MMAF16(s[2 * g],     aq, bkl[0], bkl[1]);
                    MMAF16(s[2 * g + 1], aq, bkh[2], bkh[3]);
                    MMAF16(s[2 * g + 1], aq, bkl[2], bkl[3]);
                }
            }

            // ---- mask + causal ----
            const int lc = 2 * (lane & 3);
#pragma unroll
            for (int j = 0; j < 8; j++) {
                const float mj0 = msk[j * 8 + lc];
                const float mj1 = msk[j * 8 + lc + 1];
                s[j][0] += mj0; s[j][1] += mj1;
                s[j][2] += mj0; s[j][3] += mj1;
            }
            if (kt * 64 + 63 > qrow_w) {
                const int r1g = r0g + 8;
#pragma unroll
                for (int j = 0; j < 8; j++) {
                    const int c0 = kt * 64 + j * 8 + lc;
                    if (c0     > r0g) s[j][0] = -1e30f;
                    if (c0 + 1 > r0g) s[j][1] = -1e30f;
                    if (c0     > r1g) s[j][2] = -1e30f;
                    if (c0 + 1 > r1g) s[j][3] = -1e30f;
                }
            }

            // ---- online softmax (exp2 domain) ----
            float rm0 = -1e30f, rm1 = -1e30f;
#pragma unroll
            for (int j = 0; j < 8; j++) {
                rm0 = fmaxf(rm0, fmaxf(s[j][0], s[j][1]));
                rm1 = fmaxf(rm1, fmaxf(s[j][2], s[j][3]));
            }
            rm0 = fmaxf(rm0, __shfl_xor_sync(0xffffffffu, rm0, 1));
            rm0 = fmaxf(rm0, __shfl_xor_sync(0xffffffffu, rm0, 2));
            rm1 = fmaxf(rm1, __shfl_xor_sync(0xffffffffu, rm1, 1));
            rm1 = fmaxf(rm1, __shfl_xor_sync(0xffffffffu, rm1, 2));
            const float mn0 = fmaxf(m0, rm0), mn1 = fmaxf(m1, rm1);
            const float al0 = ex2(m0 - mn0), al1 = ex2(m1 - mn1);
            m0 = mn0; m1 = mn1;
            float ls0 = 0.0f, ls1 = 0.0f;
#pragma unroll
            for (int j = 0; j < 8; j++) {
                s[j][0] = ex2(s[j][0] - mn0); ls0 += s[j][0];
                s[j][1] = ex2(s[j][1] - mn0); ls0 += s[j][1];
                s[j][2] = ex2(s[j][2] - mn1); ls1 += s[j][2];
                s[j][3] = ex2(s[j][3] - mn1); ls1 += s[j][3];
            }
            ls0 += __shfl_xor_sync(0xffffffffu, ls0, 1);
            ls0 += __shfl_xor_sync(0xffffffffu, ls0, 2);
            ls1 += __shfl_xor_sync(0xffffffffu, ls1, 1);
            ls1 += __shfl_xor_sync(0xffffffffu, ls1, 2);
            l0 = l0 * al0 + ls0;
            l1 = l1 * al1 + ls1;
#pragma unroll
            for (int j = 0; j < 8; j++) {
                of[j][0] *= al0; of[j][1] *= al0;
                of[j][2] *= al1; of[j][3] *= al1;
            }

            // ---- O += P @ V (bf16 3-product, unchanged) ----
#pragma unroll
            for (int kt2 = 0; kt2 < 4; kt2++) {
                uint32_t aph[4], apl[4];
                {
                    const float* p0 = s[2 * kt2];
                    const float* p1 = s[2 * kt2 + 1];
                    float hl[8];
#pragma unroll
                    for (int e = 0; e < 4; e++) {
                        hl[e]     = p0[e] - __bfloat162float(__float2bfloat16(p0[e]));
                        hl[4 + e] = p1[e] - __bfloat162float(__float2bfloat16(p1[e]));
                    }
                    aph[0] = packbf(p0[0], p0[1]); aph[1] = packbf(p0[2], p0[3]);
                    aph[2] = packbf(p1[0], p1[1]); aph[3] = packbf(p1[2], p1[3]);
                    apl[0] = packbf(hl[0], hl[1]); apl[1] = packbf(hl[2], hl[3]);
                    apl[2] = packbf(hl[4], hl[5]); apl[3] = packbf(hl[6], hl[7]);
                }
#pragma unroll
                for (int g = 0; g < 4; g++) {
                    uint32_t bvh[4], bvl[4];
                    LDSM_X4(bvh[0], bvh[1], bvh[2], bvh[3],
                            bv_base + kb + g * (16 * ASTR) + kt2 * 32);
                    LDSM_X4(bvl[0], bvl[1], bvl[2], bvl[3],
                            bv_base + kb + 9216 + g * (16 * ASTR) + kt2 * 32);
                    MMA16816(of[2 * g],     aph, bvh[0], bvh[1]);
                    MMA16816(of[2 * g],     aph, bvl[0], bvl[1]);
                    MMA16816(of[2 * g],     apl, bvh[0], bvh[1]);
                    MMA16816(of[2 * g + 1], aph, bvh[2], bvh[3]);
                    MMA16816(of[2 * g + 1], aph, bvl[2], bvl[3]);
                    MMA16816(of[2 * g + 1], apl, bvh[2], bvh[3]);
                }
            }
        }

        // ---- normalize + store single fp16 row-major [B*T, D] ----
        const float inv0 = 1.0f / l0, inv1 = 1.0f / l1;
        const size_t obase = ((size_t)(b * TSEQ) + r0g) * DMODEL + h * DHEAD + 2 * (lane & 3);
#pragma unroll
        for (int j = 0; j < 8; j++) {
            *reinterpret_cast<uint32_t*>(ao + obase + j * 8) =
                packhf(of[j][0] * inv0, of[j][1] * inv0);
            *reinterpret_cast<uint32_t*>(ao + obase + (size_t)8 * DMODEL + j * 8) =
                packhf(of[j][2] * inv1, of[j][3] * inv1);
        }
    }
}

// ---------------------------------------------------------------------------
extern "C" void kernel_launch(void* const* d_in, const int* in_sizes, int n_in,
                              void* d_out, int out_size)
{
    const float* x     = (const float*)d_in[0];
    const float* Wqkv  = (const float*)d_in[1];
    const float* bqkv  = (const float*)d_in[2];
    const float* Wproj = (const float*)d_in[3];
    const float* bproj = (const float*)d_in[4];
    const int*   mask  = (const int*)d_in[5];
    float* out = (float*)d_out;

    __half *x16, *wq16, *wp16, *ao16, *qf, *kfh, *kfl;
    __nv_bfloat16 *vh, *vl, *vth, *vtl;
    cudaGetSymbolAddress((void**)&x16,  g_x16);
    cudaGetSymbolAddress((void**)&wq16, g_wq16);
    cudaGetSymbolAddress((void**)&wp16, g_wp16);
    cudaGetSymbolAddress((void**)&ao16, g_ao16);
    cudaGetSymbolAddress((void**)&qf,  g_qf);
    cudaGetSymbolAddress((void**)&kfh, g_k16h);
    cudaGetSymbolAddress((void**)&kfl, g_k16l);
    cudaGetSymbolAddress((void**)&vh, g_vh);   cudaGetSymbolAddress((void**)&vl, g_vl);
    cudaGetSymbolAddress((void**)&vth, g_vth); cudaGetSymbolAddress((void**)&vtl, g_vtl);

    cudaFuncSetAttribute(attn_hmma,
                         cudaFuncAttributeMaxDynamicSharedMemorySize, ATTN_SMEM);
    cudaFuncSetAttribute(gemm_f16<0>,
                         cudaFuncAttributeMaxDynamicSharedMemorySize, GEMM_SMEM);
    cudaFuncSetAttribute(gemm_f16<1>,
                         cudaFuncAttributeMaxDynamicSharedMemorySize, GEMM_SMEM);

    // Convert input and weights (weights transposed to [N][K]) to fp16
    convert_h<<<(MROWS * DMODEL) / 1024, 256>>>(x, x16);
    convert_wT<<<dim3(QKV_N / 32, DMODEL / 32), dim3(32, 8)>>>(
        Wqkv, wq16, DMODEL, QKV_N);
    convert_wT<<<dim3(DMODEL / 32, DMODEL / 32), dim3(32, 8)>>>(
        Wproj, wp16, DMODEL, DMODEL);

    // 1) QKV GEMM (fp16 single-product, k64) -> Q f16 / K split-f16 / V split-bf16
    gemm_f16<1><<<dim3(QKV_N / 128, MROWS / 128), 128, GEMM_SMEM>>>(
        x16, wq16, bqkv, nullptr, qf, kfh, kfl, vh, vl, QKV_N);

    // 2) V transpose
    transpose_v<<<dim3(32, 128), dim3(32, 8)>>>(vh, vl, vth, vtl);

    // 3) Fused causal attention (S: fp16 2-product; PV: bf16 3-product)
    attn_hmma<<<dim3(4, BATCH * NH), 256, ATTN_SMEM>>>(
        qf, kfh, kfl, vth, vtl, mask, ao16);

    // 4) out = attn @ Wproj + bproj (fp16 single-product, k64)
    gemm_f16<0><<<dim3(DMODEL / 128, MROWS / 128), 128, GEMM_SMEM>>>(
        ao16, wp16, bproj, out,
        nullptr, nullptr, nullptr, nullptr, nullptr, DMODEL);
}

// round 12
// speedup vs baseline: 1.1481x; 1.1481x over previous
#include <cuda_runtime.h>
#include <cuda_bf16.h>
#include <cuda_fp16.h>
#include <math.h>
#include <cstdint>

// Problem constants
#define BATCH 4
#define TSEQ  1024
#define DMODEL 1024
#define NH 16
#define DHEAD 64
#define QKV_N 3072   // 3*DMODEL
#define MROWS 4096   // BATCH*TSEQ
#define KDIM 1024    // K is 1024 for both GEMMs
#define NTK  32      // k-tiles (KDIM/32)

// Q scale: 1/sqrt(64) * log2(e)  (softmax done in exp2 domain)
#define QSCALE (0.125f * 1.44269504088896f)

// ---------------------------------------------------------------------------
// Scratch (device globals: allocation-free)
// ---------------------------------------------------------------------------
__device__ __half g_x16[(size_t)MROWS * DMODEL];         // x fp16 row-major
__device__ __half g_wq16[(size_t)QKV_N * DMODEL];        // Wqkv^T fp16 [N][K]
__device__ __half g_wp16[(size_t)DMODEL * DMODEL];       // Wproj^T fp16 [N][K]
__device__ __half g_ao16[(size_t)MROWS * DMODEL];        // attn out fp16
__device__ __half g_qf[(size_t)MROWS * DMODEL];          // Q scaled, single fp16
__device__ __half g_k16h[(size_t)MROWS * DMODEL];        // K fp16 hi
__device__ __half g_k16l[(size_t)MROWS * DMODEL];        // K fp16 lo
__device__ __half g_v16h[(size_t)MROWS * DMODEL];        // V fp16 hi [row][h*64+dh]
__device__ __half g_v16l[(size_t)MROWS * DMODEL];        // V fp16 lo
__device__ __half g_vth[(size_t)MROWS * DMODEL];         // V^T hi [bh][dh][t]
__device__ __half g_vtl[(size_t)MROWS * DMODEL];         // V^T lo

// ---------------------------------------------------------------------------
// PTX helpers (base ISA only — compute_103 virtual arch, no tcgen05)
// ---------------------------------------------------------------------------
__device__ __forceinline__ uint32_t smem_to_u32(const void* p) {
    uint32_t a;
    asm("{ .reg .u64 t; cvta.to.shared.u64 t, %1; cvt.u32.u64 %0, t; }"
        : "=r"(a) : "l"(p));
    return a;
}

#define CP_ASYNC16(smem, gptr) \
    asm volatile("cp.async.cg.shared.global [%0], [%1], 16;" \
        :: "r"(smem), "l"(gptr) : "memory")
#define CP_COMMIT() asm volatile("cp.async.commit_group;" ::: "memory")
#define CP_WAIT(n)  asm volatile("cp.async.wait_group %0;" :: "n"(n) : "memory")

#define LDSM_X4(r0, r1, r2, r3, addr) \
    asm volatile("ldmatrix.sync.aligned.m8n8.x4.shared.b16 {%0,%1,%2,%3}, [%4];" \
        : "=r"(r0), "=r"(r1), "=r"(r2), "=r"(r3) : "r"(addr))

#define MMAF16(c, a, b0, b1) \
    asm volatile("mma.sync.aligned.m16n8k16.row.col.f32.f16.f16.f32 " \
        "{%0,%1,%2,%3}, {%4,%5,%6,%7}, {%8,%9}, {%0,%1,%2,%3};" \
        : "+f"((c)[0]), "+f"((c)[1]), "+f"((c)[2]), "+f"((c)[3]) \
        : "r"((a)[0]), "r"((a)[1]), "r"((a)[2]), "r"((a)[3]), \
          "r"(b0), "r"(b1))

// pack two floats to f16x2 (lo addr half = first arg)
__device__ __forceinline__ uint32_t packhf(float lo, float hi) {
    uint32_t r;
    asm("cvt.rn.f16x2.f32 %0, %1, %2;" : "=r"(r) : "f"(hi), "f"(lo));
    return r;
}
__device__ __forceinline__ float ex2(float x) {
    float r;
    asm("ex2.approx.f32 %0, %1;" : "=f"(r) : "f"(x));
    return r;
}

// Swizzled byte offset within one 8KB matrix tile (128 rows x 32 fp16):
// row-pair lines of 128B, chunk3 = (r&1)*4 + ch, XOR (r>>1)&7. (verified R7+)
__device__ __forceinline__ uint32_t sw_off(int r, int ch) {
    const uint32_t chunk3 = (uint32_t)(((r & 1) << 2) | ch);
    return (uint32_t)((r >> 1) * 128) + ((chunk3 ^ ((uint32_t)(r >> 1) & 7u)) << 4);
}

// ---------------------------------------------------------------------------
// FP16 single-product HMMA GEMM: C = A[M,K] @ (B[N,K])^T + bias
// CTA 128x128, K-tile 32, 5-stage cp.async (swizzled smem, 16KB/stage),
// 2 CTAs/SM, 4 warps (2x2), warp tile 64x64.  (round-10 proven config)
// MODE 0: fp32 C out.  MODE 1: QKV epilogue -> qf16 / K split-f16 / V split-f16
// ---------------------------------------------------------------------------
#define MATB   8192
#define STAGEB 16384
#define NSTAGE 5
#define GEMM_SMEM (NSTAGE * STAGEB)

template <int MODE>
__global__ __launch_bounds__(128, 2) void gemm_f16(
    const __half* __restrict__ A, const __half* __restrict__ B,
    const float* __restrict__ bias, float* __restrict__ C,
    __half* __restrict__ qf,
    __half* __restrict__ kfh, __half* __restrict__ kfl,
    __half* __restrict__ vfh, __half* __restrict__ vfl,
    int Ntot)
{
    extern __shared__ char dsm[];
    const uint32_t sb = smem_to_u32(dsm);

    const int t    = threadIdx.x;
    const int lane = t & 31;
    const int wid  = t >> 5;
    const int wm   = wid >> 1;
    const int wn   = wid & 1;
    const int bm   = blockIdx.y << 7;
    const int bn   = blockIdx.x << 7;

    // cp.async plan: 2 matrices x 512 chunks(16B) / 128 thr = 8/thread
    const int rbase = t >> 2;
    const int ch0   = t & 3;
    uint32_t soff[8];
    const __half* gp[8];
#pragma unroll
    for (int m = 0; m < 2; m++)
#pragma unroll
        for (int hh = 0; hh < 4; hh++) {
            const int r = rbase + hh * 32;
            soff[m * 4 + hh] = (uint32_t)(m * MATB) + sw_off(r, ch0);
            gp[m * 4 + hh]   = (m ? B : A) +
                (size_t)((m ? bn : bm) + r) * KDIM + ch0 * 8;
        }

    const uint32_t a_base = sw_off(wm * 64 + (lane & 15), lane >> 4);
    const uint32_t b_base = (uint32_t)MATB +
        sw_off(wn * 64 + (lane & 7) + ((lane >> 4) << 3), (lane >> 3) & 1);

    float acc[4][8][4];
#pragma unroll
    for (int mi = 0; mi < 4; mi++)
#pragma unroll
        for (int ni = 0; ni < 8; ni++)
#pragma unroll
            for (int e = 0; e < 4; e++) acc[mi][ni][e] = 0.0f;

    // prologue: stages 0..3
#pragma unroll
    for (int s = 0; s < NSTAGE - 1; s++) {
        const uint32_t st = sb + (uint32_t)s * STAGEB;
        const int ko = s * 32;
#pragma unroll
        for (int i = 0; i < 8; i++) CP_ASYNC16(st + soff[i], gp[i] + ko);
        CP_COMMIT();
    }

    int buf = 0, nbuf = NSTAGE - 1;
#pragma unroll 1
    for (int kt = 0; kt < NTK; kt++) {
        CP_WAIT(NSTAGE - 2);
        __syncthreads();

        if (kt + NSTAGE - 1 < NTK) {
            const uint32_t st = sb + (uint32_t)nbuf * STAGEB;
            const int ko = (kt + NSTAGE - 1) * 32;
#pragma unroll
            for (int i = 0; i < 8; i++) CP_ASYNC16(st + soff[i], gp[i] + ko);
        }
        CP_COMMIT();

        const uint32_t stg = sb + (uint32_t)buf * STAGEB;
        buf = (buf == NSTAGE - 1) ? 0 : buf + 1;
        nbuf = (nbuf == NSTAGE - 1) ? 0 : nbuf + 1;

#pragma unroll
        for (int ks = 0; ks < 2; ks++) {
            const uint32_t ksx = (uint32_t)(ks << 5);
            uint32_t ah[4][4];
#pragma unroll
            for (int mi = 0; mi < 4; mi++) {
                const uint32_t ao = (a_base + (uint32_t)(mi * 1024)) ^ ksx;
                LDSM_X4(ah[mi][0], ah[mi][1], ah[mi][2], ah[mi][3], stg + ao);
            }
            uint32_t rbh[4][4];
#pragma unroll
            for (int g = 0; g < 4; g++) {
                const uint32_t bo = (b_base + (uint32_t)(g * 1024)) ^ ksx;
                LDSM_X4(rbh[g][0], rbh[g][1], rbh[g][2], rbh[g][3], stg + bo);
            }
#pragma unroll
            for (int mi = 0; mi < 4; mi++)
#pragma unroll
                for (int ni = 0; ni < 8; ni++) {
                    const int g = ni >> 1, u = (ni & 1) * 2;
                    MMAF16(acc[mi][ni], ah[mi], rbh[g][u], rbh[g][u + 1]);
                }
        }
    }

    // ---- epilogue ----
    const int er = bm + wm * 64 + (lane >> 2);
    const int ec = bn + wn * 64 + (lane & 3) * 2;

    if (MODE == 0) {
#pragma unroll
        for (int ni = 0; ni < 8; ni++) {
            const int col = ec + ni * 8;
            const float2 bv = *reinterpret_cast<const float2*>(bias + col);
#pragma unroll
            for (int mi = 0; mi < 4; mi++) {
                const int r0 = er + mi * 16;
                float2 o0, o1;
                o0.x = acc[mi][ni][0] + bv.x;
                o0.y = acc[mi][ni][1] + bv.y;
                o1.x = acc[mi][ni][2] + bv.x;
                o1.y = acc[mi][ni][3] + bv.y;
                *reinterpret_cast<float2*>(C + (size_t)r0 * Ntot + col) = o0;
                *reinterpret_cast<float2*>(C + (size_t)(r0 + 8) * Ntot + col) = o1;
            }
        }
    } else {
        // seg 0 = Q (scaled, single fp16); 1 = K (split fp16); 2 = V (split fp16)
        const int seg = bn >> 10;
        const int ecl = ec & 1023;
        __half *H = nullptr, *L = nullptr;
        if (seg == 1)      { H = kfh; L = kfl; }
        else if (seg == 2) { H = vfh; L = vfl; }
#pragma unroll
        for (int ni = 0; ni < 8; ni++) {
            const int col = ec + ni * 8;
            const float2 bv = *reinterpret_cast<const float2*>(bias + col);
            const int cl = ecl + ni * 8;
#pragma unroll
            for (int mi = 0; mi < 4; mi++) {
                const int r0 = er + mi * 16;
                float v00 = acc[mi][ni][0] + bv.x;
                float v01 = acc[mi][ni][1] + bv.y;
                float v10 = acc[mi][ni][2] + bv.x;
                float v11 = acc[mi][ni][3] + bv.y;
                if (seg == 0) {
                    v00 *= QSCALE; v01 *= QSCALE; v10 *= QSCALE; v11 *= QSCALE;
                    *reinterpret_cast<uint32_t*>(qf + (size_t)r0 * 1024 + cl) =
                        packhf(v00, v01);
                    *reinterpret_cast<uint32_t*>(qf + (size_t)(r0 + 8) * 1024 + cl) =
                        packhf(v10, v11);
                } else {
                    const float h00 = __half2float(__float2half_rn(v00));
                    const float h01 = __half2float(__float2half_rn(v01));
                    const float h10 = __half2float(__float2half_rn(v10));
                    const float h11 = __half2float(__float2half_rn(v11));
                    *reinterpret_cast<uint32_t*>(H + (size_t)r0 * 1024 + cl) =
                        packhf(v00, v01);
                    *reinterpret_cast<uint32_t*>(L + (size_t)r0 * 1024 + cl) =
                        packhf(v00 - h00, v01 - h01);
                    *reinterpret_cast<uint32_t*>(H + (size_t)(r0 + 8) * 1024 + cl) =
                        packhf(v10, v11);
                    *reinterpret_cast<uint32_t*>(L + (size_t)(r0 + 8) * 1024 + cl) =
                        packhf(v10 - h10, v11 - h11);
                }
            }
        }
    }
}

// ---------------------------------------------------------------------------
// fp32 -> fp16 convert, 4 elems/thread
// ---------------------------------------------------------------------------
__global__ __launch_bounds__(256) void convert_h(
    const float* __restrict__ A, __half* __restrict__ H)
{
    const int i = blockIdx.x * blockDim.x + threadIdx.x;
    const float4 v = reinterpret_cast<const float4*>(A)[i];
    uint2 o;
    o.x = packhf(v.x, v.y);
    o.y = packhf(v.z, v.w);
    *reinterpret_cast<uint2*>(H + (size_t)i * 4) = o;
}

// ---------------------------------------------------------------------------
// W[K][N] fp32 -> W^T[N][K] fp16 (transpose + convert), block (32,8)
// ---------------------------------------------------------------------------
__global__ __launch_bounds__(256) void convert_wT(
    const float* __restrict__ W, __half* __restrict__ T, int K, int N)
{
    __shared__ float tile[32][33];
    const int tx = threadIdx.x, ty = threadIdx.y;
    const int n0 = blockIdx.x * 32, k0 = blockIdx.y * 32;
#pragma unroll
    for (int i = 0; i < 4; i++)
        tile[ty + i * 8][tx] = W[(size_t)(k0 + ty + i * 8) * N + n0 + tx];
    __syncthreads();
#pragma unroll
    for (int i = 0; i < 4; i++) {
        const float v = tile[tx][ty + i * 8];
        T[(size_t)(n0 + ty + i * 8) * K + k0 + tx] = __float2half_rn(v);
    }
}

// ---------------------------------------------------------------------------
// V transpose (fp16): vfh/vfl [B*T][1024] -> vth/vtl [(b*16+h)*64+dh][1024]
// ---------------------------------------------------------------------------
__global__ __launch_bounds__(256) void transpose_v(
    const __half* __restrict__ vfh, const __half* __restrict__ vfl,
    __half* __restrict__ vth, __half* __restrict__ vtl)
{
    __shared__ __half th[32][33], tl[32][33];
    const int tx = threadIdx.x, ty = threadIdx.y;
    const int c0 = blockIdx.x * 32;
    const int r0 = blockIdx.y * 32;
#pragma unroll
    for (int i = 0; i < 4; i++) {
        const size_t src = (size_t)(r0 + ty + i * 8) * 1024 + c0 + tx;
        th[ty + i * 8][tx] = vfh[src];
        tl[ty + i * 8][tx] = vfl[src];
    }
    __syncthreads();
    const int b = r0 >> 10;
    const int tbase = (r0 & 1023) + tx;
#pragma unroll
    for (int i = 0; i < 4; i++) {
        const int cp = c0 + ty + i * 8;
        const int hh = cp >> 6, dh = cp & 63;
        const size_t dst = (size_t)(((b * 16 + hh) * 64) + dh) * 1024 + tbase;
        vth[dst] = th[tx][ty + i * 8];
        vtl[dst] = tl[tx][ty + i * 8];
    }
}

// ---------------------------------------------------------------------------
// HMMA flash attention, all fp16 2-product:
//   S  = q_f16 x (Kh+Kl)        (2 products)
//   O += p_f16 x (Vh+Vl)        (2 products, P single fp16)
// Double-buffered K/V, exp2 softmax. Output single fp16 row-major.
// Grid (4, B*H), 2 passes: q-tiles {7-bx, bx} (BQ=128). 8 warps x 16 rows.
// ---------------------------------------------------------------------------
#define ASTR 144
#define Q_OFF  0             // 18432: Q single fp16 (scaled)
#define K_OFF  18432         // 2 bufs x (Kh 9216 + Kl 9216)
#define V_OFF  55296         // 2 bufs x (Vth 9216 + Vtl 9216)
#define KVBUF  18432
#define MSK_OFF 92160
#define ATTN_SMEM (92160 + 512)

__global__ __launch_bounds__(256, 2) void attn_hmma(
    const __half* __restrict__ qf,
    const __half* __restrict__ kfh, const __half* __restrict__ kfl,
    const __half* __restrict__ vth, const __half* __restrict__ vtl,
    const int* __restrict__ mask,
    __half* __restrict__ ao)
{
    extern __shared__ char smc[];
    const uint32_t sb = smem_to_u32(smc);

    const int t    = threadIdx.x;
    const int lane = t & 31;
    const int w    = t >> 5;
    const int bh   = blockIdx.y;
    const int b    = bh >> 4;
    const int h    = bh & 15;
    float* msk_s = (float*)(smc + MSK_OFF);

    const uint32_t aq_base = sb + Q_OFF +
        (uint32_t)((16 * w + (lane & 15)) * ASTR + (lane >> 4) * 16);
    const uint32_t bk_base = sb + K_OFF +
        (uint32_t)(((lane & 7) + ((lane >> 4) << 3)) * ASTR + ((lane >> 3) & 1) * 16);
    const uint32_t bv_base = sb + V_OFF +
        (uint32_t)(((lane & 7) + ((lane >> 4) << 3)) * ASTR + ((lane >> 3) & 1) * 16);

#pragma unroll 1
    for (int pass = 0; pass < 2; pass++) {
        const int qt = pass ? (int)blockIdx.x : 7 - (int)blockIdx.x;
        __syncthreads();

        // ---- Q tile: 128 rows x 64 fp16 = 1024 chunks ----
#pragma unroll
        for (int p = 0; p < 4; p++) {
            const int idx = t + (p << 8);
            const int row = idx >> 3;
            const int ch  = idx & 7;
            const __half* src = qf +
                (size_t)(b * 1024 + qt * 128 + row) * 1024 + h * 64 + ch * 8;
            CP_ASYNC16(sb + Q_OFF + row * ASTR + ch * 16, src);
        }
        CP_COMMIT();

        const int kmax = 2 * qt + 1;

        // ---- prologue: K/V for kt=0 into buffer 0, mask[0] ----
#pragma unroll
        for (int p = 0; p < 8; p++) {
            const int c   = t + (p << 8);
            const int m   = c >> 9;          // 0=Kh 1=Kl 2=Vth 3=Vtl
            const int idx = c & 511;
            const int row = idx >> 3;
            const int ch  = idx & 7;
            const void* src;
            uint32_t dst;
            if (m == 0) {
                src = kfh + (size_t)(b * 1024 + row) * 1024 + h * 64 + ch * 8;
                dst = sb + K_OFF + row * ASTR + ch * 16;
            } else if (m == 1) {
                src = kfl + (size_t)(b * 1024 + row) * 1024 + h * 64 + ch * 8;
                dst = sb + K_OFF + 9216 + row * ASTR + ch * 16;
            } else if (m == 2) {
                src = vth + (size_t)(bh * 64 + row) * 1024 + ch * 8;
                dst = sb + V_OFF + row * ASTR + ch * 16;
            } else {
                src = vtl + (size_t)(bh * 64 + row) * 1024 + ch * 8;
                dst = sb + V_OFF + 9216 + row * ASTR + ch * 16;
            }
            CP_ASYNC16(dst, src);
        }
        if (t < 64)
            msk_s[t] = (mask[b * TSEQ + t] != 0) ? 0.0f : -1e30f;
        CP_COMMIT();

        float m0 = -1e30f, m1 = -1e30f, l0 = 0.0f, l1 = 0.0f;
        float of[8][4];
#pragma unroll
        for (int j = 0; j < 8; j++)
#pragma unroll
            for (int e = 0; e < 4; e++) of[j][e] = 0.0f;

        const int qrow_w = qt * 128 + 16 * w;
        const int r0g = qrow_w + (lane >> 2);

#pragma unroll 1
        for (int kt = 0; kt <= kmax; kt++) {
            CP_WAIT(0);
            __syncthreads();

            if (kt < kmax) {
                const uint32_t kb = (uint32_t)(((kt + 1) & 1) * KVBUF);
#pragma unroll
                for (int p = 0; p < 8; p++) {
                    const int c   = t + (p << 8);
                    const int m   = c >> 9;
                    const int idx = c & 511;
                    const int row = idx >> 3;
                    const int ch  = idx & 7;
                    const void* src;
                    uint32_t dst;
                    if (m == 0) {
                        src = kfh + (size_t)(b * 1024 + (kt + 1) * 64 + row) * 1024 + h * 64 + ch * 8;
                        dst = sb + K_OFF + kb + row * ASTR + ch * 16;
                    } else if (m == 1) {
                        src = kfl + (size_t)(b * 1024 + (kt + 1) * 64 + row) * 1024 + h * 64 + ch * 8;
                        dst = sb + K_OFF + kb + 9216 + row * ASTR + ch * 16;
                    } else if (m == 2) {
                        src = vth + (size_t)(bh * 64 + row) * 1024 + (kt + 1) * 64 + ch * 8;
                        dst = sb + V_OFF + kb + row * ASTR + ch * 16;
                    } else {
                        src = vtl + (size_t)(bh * 64 + row) * 1024 + (kt + 1) * 64 + ch * 8;
                        dst = sb + V_OFF + kb + 9216 + row * ASTR + ch * 16;
                    }
                    CP_ASYNC16(dst, src);
                }
                if (t < 64)
                    msk_s[((kt + 1) & 1) * 64 + t] =
                        (mask[b * TSEQ + (kt + 1) * 64 + t] != 0) ? 0.0f : -1e30f;
            }
            CP_COMMIT();

            const uint32_t kb = (uint32_t)((kt & 1) * KVBUF);
            const float* msk = msk_s + (kt & 1) * 64;

            // ---- S = q @ (Kh + Kl)^T ----
            float s[8][4];
#pragma unroll
            for (int j = 0; j < 8; j++)
#pragma unroll
                for (int e = 0; e < 4; e++) s[j][e] = 0.0f;

#pragma unroll
            for (int ks = 0; ks < 4; ks++) {
                uint32_t aq[4];
                LDSM_X4(aq[0], aq[1], aq[2], aq[3], aq_base + ks * 32);
#pragma unroll
                for (int g = 0; g < 4; g++) {
                    uint32_t bkh[4], bkl[4];
                    LDSM_X4(bkh[0], bkh[1], bkh[2], bkh[3],
                            bk_base + kb + g * (16 * ASTR) + ks * 32);
                    LDSM_X4(bkl[0], bkl[1], bkl[2], bkl[3],
                            bk_base + kb + 9216 + g * (16 * ASTR) + ks * 32);
                    MMAF16(s[2 * g],     aq, bkh[0], bkh[1]);
                    MMAF16(s[2 * g],     aq, bkl[0], bkl[1]);
                    MMAF16(s[2 * g + 1], aq, bkh[2], bkh[3]);
                    MMAF16(s[2 * g + 1], aq, bkl[2], bkl[3]);
                }
            }

            // ---- mask + causal ----
            const int lc = 2 * (lane & 3);
#pragma unroll
            for (int j = 0; j < 8; j++) {
                const float mj0 = msk[j * 8 + lc];
                const float mj1 = msk[j * 8 + lc + 1];
                s[j][0] += mj0; s[j][1] += mj1;
                s[j][2] += mj0; s[j][3] += mj1;
            }
            if (kt * 64 + 63 > qrow_w) {
                const int r1g = r0g + 8;
#pragma unroll
                for (int j = 0; j < 8; j++) {
                    const int c0 = kt * 64 + j * 8 + lc;
                    if (c0     > r0g) s[j][0] = -1e30f;
                    if (c0 + 1 > r0g) s[j][1] = -1e30f;
                    if (c0     > r1g) s[j][2] = -1e30f;
                    if (c0 + 1 > r1g) s[j][3] = -1e30f;
                }
            }

            // ---- online softmax (exp2 domain) ----
            float rm0 = -1e30f, rm1 = -1e30f;
#pragma unroll
            for (int j = 0; j < 8; j++) {
                rm0 = fmaxf(rm0, fmaxf(s[j][0], s[j][1]));
                rm1 = fmaxf(rm1, fmaxf(s[j][2], s[j][3]));
            }
            rm0 = fmaxf(rm0, __shfl_xor_sync(0xffffffffu, rm0, 1));
            rm0 = fmaxf(rm0, __shfl_xor_sync(0xffffffffu, rm0, 2));
            rm1 = fmaxf(rm1, __shfl_xor_sync(0xffffffffu, rm1, 1));
            rm1 = fmaxf(rm1, __shfl_xor_sync(0xffffffffu, rm1, 2));
            const float mn0 = fmaxf(m0, rm0), mn1 = fmaxf(m1, rm1);
            const float al0 = ex2(m0 - mn0), al1 = ex2(m1 - mn1);
            m0 = mn0; m1 = mn1;
            float ls0 = 0.0f, ls1 = 0.0f;
#pragma unroll
            for (int j = 0; j < 8; j++) {
                s[j][0] = ex2(s[j][0] - mn0); ls0 += s[j][0];
                s[j][1] = ex2(s[j][1] - mn0); ls0 += s[j][1];
                s[j][2] = ex2(s[j][2] - mn1); ls1 += s[j][2];
                s[j][3] = ex2(s[j][3] - mn1); ls1 += s[j][3];
            }
            ls0 += __shfl_xor_sync(0xffffffffu, ls0, 1);
            ls0 += __shfl_xor_sync(0xffffffffu, ls0, 2);
            ls1 += __shfl_xor_sync(0xffffffffu, ls1, 1);
            ls1 += __shfl_xor_sync(0xffffffffu, ls1, 2);
            l0 = l0 * al0 + ls0;
            l1 = l1 * al1 + ls1;
#pragma unroll
            for (int j = 0; j < 8; j++) {
                of[j][0] *= al0; of[j][1] *= al0;
                of[j][2] *= al1; of[j][3] *= al1;
            }

            // ---- O += p_f16 @ (Vh + Vl) (2 products, P single fp16) ----
#pragma unroll
            for (int kt2 = 0; kt2 < 4; kt2++) {
                uint32_t ap[4];
                {
                    const float* p0 = s[2 * kt2];
                    const float* p1 = s[2 * kt2 + 1];
                    ap[0] = packhf(p0[0], p0[1]); ap[1] = packhf(p0[2], p0[3]);
                    ap[2] = packhf(p1[0], p1[1]); ap[3] = packhf(p1[2], p1[3]);
                }
#pragma unroll
                for (int g = 0; g < 4; g++) {
                    uint32_t bvh[4], bvl[4];
                    LDSM_X4(bvh[0], bvh[1], bvh[2], bvh[3],
                            bv_base + kb + g * (16 * ASTR) + kt2 * 32);
                    LDSM_X4(bvl[0], bvl[1], bvl[2], bvl[3],
                            bv_base + kb + 9216 + g * (16 * ASTR) + kt2 * 32);
                    MMAF16(of[2 * g],     ap, bvh[0], bvh[1]);
                    MMAF16(of[2 * g],     ap, bvl[0], bvl[1]);
                    MMAF16(of[2 * g + 1], ap, bvh[2], bvh[3]);
                    MMAF16(of[2 * g + 1], ap, bvl[2], bvl[3]);
                }
            }
        }

        // ---- normalize + store single fp16 row-major [B*T, D] ----
        const float inv0 = 1.0f / l0, inv1 = 1.0f / l1;
        const size_t obase = ((size_t)(b * TSEQ) + r0g) * DMODEL + h * DHEAD + 2 * (lane & 3);
#pragma unroll
        for (int j = 0; j < 8; j++) {
            *reinterpret_cast<uint32_t*>(ao + obase + j * 8) =
                packhf(of[j][0] * inv0, of[j][1] * inv0);
            *reinterpret_cast<uint32_t*>(ao + obase + (size_t)8 * DMODEL + j * 8) =
                packhf(of[j][2] * inv1, of[j][3] * inv1);
        }
    }
}

// ---------------------------------------------------------------------------
extern "C" void kernel_launch(void* const* d_in, const int* in_sizes, int n_in,
                              void* d_out, int out_size)
{
    const float* x     = (const float*)d_in[0];
    const float* Wqkv  = (const float*)d_in[1];
    const float* bqkv  = (const float*)d_in[2];
    const float* Wproj = (const float*)d_in[3];
    const float* bproj = (const float*)d_in[4];
    const int*   mask  = (const int*)d_in[5];
    float* out = (float*)d_out;

    __half *x16, *wq16, *wp16, *ao16, *qf, *kfh, *kfl, *vfh, *vfl, *vth, *vtl;
    cudaGetSymbolAddress((void**)&x16,  g_x16);
    cudaGetSymbolAddress((void**)&wq16, g_wq16);
    cudaGetSymbolAddress((void**)&wp16, g_wp16);
    cudaGetSymbolAddress((void**)&ao16, g_ao16);
    cudaGetSymbolAddress((void**)&qf,  g_qf);
    cudaGetSymbolAddress((void**)&kfh, g_k16h);
    cudaGetSymbolAddress((void**)&kfl, g_k16l);
    cudaGetSymbolAddress((void**)&vfh, g_v16h);
    cudaGetSymbolAddress((void**)&vfl, g_v16l);
    cudaGetSymbolAddress((void**)&vth, g_vth);
    cudaGetSymbolAddress((void**)&vtl, g_vtl);

    cudaFuncSetAttribute(attn_hmma,
                         cudaFuncAttributeMaxDynamicSharedMemorySize, ATTN_SMEM);
    cudaFuncSetAttribute(gemm_f16<0>,
                         cudaFuncAttributeMaxDynamicSharedMemorySize, GEMM_SMEM);
    cudaFuncSetAttribute(gemm_f16<1>,
                         cudaFuncAttributeMaxDynamicSharedMemorySize, GEMM_SMEM);

    // Convert input and weights (weights transposed to [N][K]) to fp16
    convert_h<<<(MROWS * DMODEL) / 1024, 256>>>(x, x16);
    convert_wT<<<dim3(QKV_N / 32, DMODEL / 32), dim3(32, 8)>>>(
        Wqkv, wq16, DMODEL, QKV_N);
    convert_wT<<<dim3(DMODEL / 32, DMODEL / 32), dim3(32, 8)>>>(
        Wproj, wp16, DMODEL, DMODEL);

    // 1) QKV GEMM (fp16 single-product, k32/5-stage) -> Q f16 / K,V split-f16
    gemm_f16<1><<<dim3(QKV_N / 128, MROWS / 128), 128, GEMM_SMEM>>>(
        x16, wq16, bqkv, nullptr, qf, kfh, kfl, vfh, vfl, QKV_N);

    // 2) V transpose (fp16)
    transpose_v<<<dim3(32, 128), dim3(32, 8)>>>(vfh, vfl, vth, vtl);

    // 3) Fused causal attention (S & PV: fp16 2-product)
    attn_hmma<<<dim3(4, BATCH * NH), 256, ATTN_SMEM>>>(
        qf, kfh, kfl, vth, vtl, mask, ao16);

    // 4) out = attn @ Wproj + bproj (fp16 single-product)
    gemm_f16<0><<<dim3(DMODEL / 128, MROWS / 128), 128, GEMM_SMEM>>>(
        ao16, wp16, bproj, out,
        nullptr, nullptr, nullptr, nullptr, nullptr, DMODEL);
}

// round 13
// speedup vs baseline: 1.2577x; 1.0954x over previous
#include <cuda_runtime.h>
#include <cuda_bf16.h>
#include <cuda_fp16.h>
#include <math.h>
#include <cstdint>

// Problem constants
#define BATCH 4
#define TSEQ  1024
#define DMODEL 1024
#define NH 16
#define DHEAD 64
#define QKV_N 3072   // 3*DMODEL
#define MROWS 4096   // BATCH*TSEQ
#define KDIM 1024    // K is 1024 for both GEMMs
#define NTK  32      // k-tiles (KDIM/32)

// Q scale: 1/sqrt(64) * log2(e)  (softmax done in exp2 domain)
#define QSCALE (0.125f * 1.44269504088896f)

// ---------------------------------------------------------------------------
// Scratch (device globals: allocation-free)
// ---------------------------------------------------------------------------
__device__ __half g_x16[(size_t)MROWS * DMODEL];         // x fp16 row-major
__device__ __half g_wq16[(size_t)QKV_N * DMODEL];        // Wqkv^T fp16 [N][K]
__device__ __half g_wp16[(size_t)DMODEL * DMODEL];       // Wproj^T fp16 [N][K]
__device__ __half g_ao16[(size_t)MROWS * DMODEL];        // attn out fp16
__device__ __half g_qf[(size_t)MROWS * DMODEL];          // Q scaled, single fp16
__device__ __half g_kf[(size_t)MROWS * DMODEL];          // K single fp16
__device__ __half g_v16h[(size_t)MROWS * DMODEL];        // V fp16 hi [row][h*64+dh]
__device__ __half g_v16l[(size_t)MROWS * DMODEL];        // V fp16 lo
__device__ __half g_vth[(size_t)MROWS * DMODEL];         // V^T hi [bh][dh][t]
__device__ __half g_vtl[(size_t)MROWS * DMODEL];         // V^T lo

// ---------------------------------------------------------------------------
// PTX helpers (base ISA only — compute_103 virtual arch, no tcgen05)
// ---------------------------------------------------------------------------
__device__ __forceinline__ uint32_t smem_to_u32(const void* p) {
    uint32_t a;
    asm("{ .reg .u64 t; cvta.to.shared.u64 t, %1; cvt.u32.u64 %0, t; }"
        : "=r"(a) : "l"(p));
    return a;
}

#define CP_ASYNC16(smem, gptr) \
    asm volatile("cp.async.cg.shared.global [%0], [%1], 16;" \
        :: "r"(smem), "l"(gptr) : "memory")
#define CP_COMMIT() asm volatile("cp.async.commit_group;" ::: "memory")
#define CP_WAIT(n)  asm volatile("cp.async.wait_group %0;" :: "n"(n) : "memory")

#define LDSM_X4(r0, r1, r2, r3, addr) \
    asm volatile("ldmatrix.sync.aligned.m8n8.x4.shared.b16 {%0,%1,%2,%3}, [%4];" \
        : "=r"(r0), "=r"(r1), "=r"(r2), "=r"(r3) : "r"(addr))

#define MMAF16(c, a, b0, b1) \
    asm volatile("mma.sync.aligned.m16n8k16.row.col.f32.f16.f16.f32 " \
        "{%0,%1,%2,%3}, {%4,%5,%6,%7}, {%8,%9}, {%0,%1,%2,%3};" \
        : "+f"((c)[0]), "+f"((c)[1]), "+f"((c)[2]), "+f"((c)[3]) \
        : "r"((a)[0]), "r"((a)[1]), "r"((a)[2]), "r"((a)[3]), \
          "r"(b0), "r"(b1))

// pack two floats to f16x2 (lo addr half = first arg)
__device__ __forceinline__ uint32_t packhf(float lo, float hi) {
    uint32_t r;
    asm("cvt.rn.f16x2.f32 %0, %1, %2;" : "=r"(r) : "f"(hi), "f"(lo));
    return r;
}
__device__ __forceinline__ float ex2(float x) {
    float r;
    asm("ex2.approx.f32 %0, %1;" : "=f"(r) : "f"(x));
    return r;
}

// Swizzled byte offset within one 8KB matrix tile (128 rows x 32 fp16):
// row-pair lines of 128B, chunk3 = (r&1)*4 + ch, XOR (r>>1)&7. (verified R7+)
__device__ __forceinline__ uint32_t sw_off(int r, int ch) {
    const uint32_t chunk3 = (uint32_t)(((r & 1) << 2) | ch);
    return (uint32_t)((r >> 1) * 128) + ((chunk3 ^ ((uint32_t)(r >> 1) & 7u)) << 4);
}

// ---------------------------------------------------------------------------
// FP16 single-product HMMA GEMM: C = A[M,K] @ (B[N,K])^T + bias
// CTA 128x128, K-tile 32, 5-stage cp.async (swizzled smem, 16KB/stage),
// 2 CTAs/SM, 4 warps (2x2), warp tile 64x64.  (round-10/12 proven config)
// MODE 0: fp32 C out.  MODE 1: QKV epilogue -> Q f16 / K f16 / V split-f16
// ---------------------------------------------------------------------------
#define MATB   8192
#define STAGEB 16384
#define NSTAGE 5
#define GEMM_SMEM (NSTAGE * STAGEB)

template <int MODE>
__global__ __launch_bounds__(128, 2) void gemm_f16(
    const __half* __restrict__ A, const __half* __restrict__ B,
    const float* __restrict__ bias, float* __restrict__ C,
    __half* __restrict__ qf, __half* __restrict__ kf,
    __half* __restrict__ vfh, __half* __restrict__ vfl,
    int Ntot)
{
    extern __shared__ char dsm[];
    const uint32_t sb = smem_to_u32(dsm);

    const int t    = threadIdx.x;
    const int lane = t & 31;
    const int wid  = t >> 5;
    const int wm   = wid >> 1;
    const int wn   = wid & 1;
    const int bm   = blockIdx.y << 7;
    const int bn   = blockIdx.x << 7;

    // cp.async plan: 2 matrices x 512 chunks(16B) / 128 thr = 8/thread
    const int rbase = t >> 2;
    const int ch0   = t & 3;
    uint32_t soff[8];
    const __half* gp[8];
#pragma unroll
    for (int m = 0; m < 2; m++)
#pragma unroll
        for (int hh = 0; hh < 4; hh++) {
            const int r = rbase + hh * 32;
            soff[m * 4 + hh] = (uint32_t)(m * MATB) + sw_off(r, ch0);
            gp[m * 4 + hh]   = (m ? B : A) +
                (size_t)((m ? bn : bm) + r) * KDIM + ch0 * 8;
        }

    const uint32_t a_base = sw_off(wm * 64 + (lane & 15), lane >> 4);
    const uint32_t b_base = (uint32_t)MATB +
        sw_off(wn * 64 + (lane & 7) + ((lane >> 4) << 3), (lane >> 3) & 1);

    float acc[4][8][4];
#pragma unroll
    for (int mi = 0; mi < 4; mi++)
#pragma unroll
        for (int ni = 0; ni < 8; ni++)
#pragma unroll
            for (int e = 0; e < 4; e++) acc[mi][ni][e] = 0.0f;

    // prologue: stages 0..3
#pragma unroll
    for (int s = 0; s < NSTAGE - 1; s++) {
        const uint32_t st = sb + (uint32_t)s * STAGEB;
        const int ko = s * 32;
#pragma unroll
        for (int i = 0; i < 8; i++) CP_ASYNC16(st + soff[i], gp[i] + ko);
        CP_COMMIT();
    }

    int buf = 0, nbuf = NSTAGE - 1;
#pragma unroll 1
    for (int kt = 0; kt < NTK; kt++) {
        CP_WAIT(NSTAGE - 2);
        __syncthreads();

        if (kt + NSTAGE - 1 < NTK) {
            const uint32_t st = sb + (uint32_t)nbuf * STAGEB;
            const int ko = (kt + NSTAGE - 1) * 32;
#pragma unroll
            for (int i = 0; i < 8; i++) CP_ASYNC16(st + soff[i], gp[i] + ko);
        }
        CP_COMMIT();

        const uint32_t stg = sb + (uint32_t)buf * STAGEB;
        buf = (buf == NSTAGE - 1) ? 0 : buf + 1;
        nbuf = (nbuf == NSTAGE - 1) ? 0 : nbuf + 1;

#pragma unroll
        for (int ks = 0; ks < 2; ks++) {
            const uint32_t ksx = (uint32_t)(ks << 5);
            uint32_t ah[4][4];
#pragma unroll
            for (int mi = 0; mi < 4; mi++) {
                const uint32_t ao = (a_base + (uint32_t)(mi * 1024)) ^ ksx;
                LDSM_X4(ah[mi][0], ah[mi][1], ah[mi][2], ah[mi][3], stg + ao);
            }
            uint32_t rbh[4][4];
#pragma unroll
            for (int g = 0; g < 4; g++) {
                const uint32_t bo = (b_base + (uint32_t)(g * 1024)) ^ ksx;
                LDSM_X4(rbh[g][0], rbh[g][1], rbh[g][2], rbh[g][3], stg + bo);
            }
#pragma unroll
            for (int mi = 0; mi < 4; mi++)
#pragma unroll
                for (int ni = 0; ni < 8; ni++) {
                    const int g = ni >> 1, u = (ni & 1) * 2;
                    MMAF16(acc[mi][ni], ah[mi], rbh[g][u], rbh[g][u + 1]);
                }
        }
    }

    // ---- epilogue ----
    const int er = bm + wm * 64 + (lane >> 2);
    const int ec = bn + wn * 64 + (lane & 3) * 2;

    if (MODE == 0) {
#pragma unroll
        for (int ni = 0; ni < 8; ni++) {
            const int col = ec + ni * 8;
            const float2 bv = *reinterpret_cast<const float2*>(bias + col);
#pragma unroll
            for (int mi = 0; mi < 4; mi++) {
                const int r0 = er + mi * 16;
                float2 o0, o1;
                o0.x = acc[mi][ni][0] + bv.x;
                o0.y = acc[mi][ni][1] + bv.y;
                o1.x = acc[mi][ni][2] + bv.x;
                o1.y = acc[mi][ni][3] + bv.y;
                *reinterpret_cast<float2*>(C + (size_t)r0 * Ntot + col) = o0;
                *reinterpret_cast<float2*>(C + (size_t)(r0 + 8) * Ntot + col) = o1;
            }
        }
    } else {
        // seg 0 = Q (scaled f16); 1 = K (single f16); 2 = V (split f16)
        const int seg = bn >> 10;
        const int ecl = ec & 1023;
#pragma unroll
        for (int ni = 0; ni < 8; ni++) {
            const int col = ec + ni * 8;
            const float2 bv = *reinterpret_cast<const float2*>(bias + col);
            const int cl = ecl + ni * 8;
#pragma unroll
            for (int mi = 0; mi < 4; mi++) {
                const int r0 = er + mi * 16;
                float v00 = acc[mi][ni][0] + bv.x;
                float v01 = acc[mi][ni][1] + bv.y;
                float v10 = acc[mi][ni][2] + bv.x;
                float v11 = acc[mi][ni][3] + bv.y;
                if (seg == 0) {
                    v00 *= QSCALE; v01 *= QSCALE; v10 *= QSCALE; v11 *= QSCALE;
                    *reinterpret_cast<uint32_t*>(qf + (size_t)r0 * 1024 + cl) =
                        packhf(v00, v01);
                    *reinterpret_cast<uint32_t*>(qf + (size_t)(r0 + 8) * 1024 + cl) =
                        packhf(v10, v11);
                } else if (seg == 1) {
                    *reinterpret_cast<uint32_t*>(kf + (size_t)r0 * 1024 + cl) =
                        packhf(v00, v01);
                    *reinterpret_cast<uint32_t*>(kf + (size_t)(r0 + 8) * 1024 + cl) =
                        packhf(v10, v11);
                } else {
                    const float h00 = __half2float(__float2half_rn(v00));
                    const float h01 = __half2float(__float2half_rn(v01));
                    const float h10 = __half2float(__float2half_rn(v10));
                    const float h11 = __half2float(__float2half_rn(v11));
                    *reinterpret_cast<uint32_t*>(vfh + (size_t)r0 * 1024 + cl) =
                        packhf(v00, v01);
                    *reinterpret_cast<uint32_t*>(vfl + (size_t)r0 * 1024 + cl) =
                        packhf(v00 - h00, v01 - h01);
                    *reinterpret_cast<uint32_t*>(vfh + (size_t)(r0 + 8) * 1024 + cl) =
                        packhf(v10, v11);
                    *reinterpret_cast<uint32_t*>(vfl + (size_t)(r0 + 8) * 1024 + cl) =
                        packhf(v10 - h10, v11 - h11);
                }
            }
        }
    }
}

// ---------------------------------------------------------------------------
// fp32 -> fp16 convert, 4 elems/thread
// ---------------------------------------------------------------------------
__global__ __launch_bounds__(256) void convert_h(
    const float* __restrict__ A, __half* __restrict__ H)
{
    const int i = blockIdx.x * blockDim.x + threadIdx.x;
    const float4 v = reinterpret_cast<const float4*>(A)[i];
    uint2 o;
    o.x = packhf(v.x, v.y);
    o.y = packhf(v.z, v.w);
    *reinterpret_cast<uint2*>(H + (size_t)i * 4) = o;
}

// ---------------------------------------------------------------------------
// W[K][N] fp32 -> W^T[N][K] fp16 (transpose + convert), block (32,8)
// ---------------------------------------------------------------------------
__global__ __launch_bounds__(256) void convert_wT(
    const float* __restrict__ W, __half* __restrict__ T, int K, int N)
{
    __shared__ float tile[32][33];
    const int tx = threadIdx.x, ty = threadIdx.y;
    const int n0 = blockIdx.x * 32, k0 = blockIdx.y * 32;
#pragma unroll
    for (int i = 0; i < 4; i++)
        tile[ty + i * 8][tx] = W[(size_t)(k0 + ty + i * 8) * N + n0 + tx];
    __syncthreads();
#pragma unroll
    for (int i = 0; i < 4; i++) {
        const float v = tile[tx][ty + i * 8];
        T[(size_t)(n0 + ty + i * 8) * K + k0 + tx] = __float2half_rn(v);
    }
}

// ---------------------------------------------------------------------------
// V transpose (fp16): vfh/vfl [B*T][1024] -> vth/vtl [(b*16+h)*64+dh][1024]
// ---------------------------------------------------------------------------
__global__ __launch_bounds__(256) void transpose_v(
    const __half* __restrict__ vfh, const __half* __restrict__ vfl,
    __half* __restrict__ vth, __half* __restrict__ vtl)
{
    __shared__ __half th[32][33], tl[32][33];
    const int tx = threadIdx.x, ty = threadIdx.y;
    const int c0 = blockIdx.x * 32;
    const int r0 = blockIdx.y * 32;
#pragma unroll
    for (int i = 0; i < 4; i++) {
        const size_t src = (size_t)(r0 + ty + i * 8) * 1024 + c0 + tx;
        th[ty + i * 8][tx] = vfh[src];
        tl[ty + i * 8][tx] = vfl[src];
    }
    __syncthreads();
    const int b = r0 >> 10;
    const int tbase = (r0 & 1023) + tx;
#pragma unroll
    for (int i = 0; i < 4; i++) {
        const int cp = c0 + ty + i * 8;
        const int hh = cp >> 6, dh = cp & 63;
        const size_t dst = (size_t)(((b * 16 + hh) * 64) + dh) * 1024 + tbase;
        vth[dst] = th[tx][ty + i * 8];
        vtl[dst] = tl[tx][ty + i * 8];
    }
}

// ---------------------------------------------------------------------------
// HMMA flash attention:
//   S  = q_f16 x k_f16          (1 product)
//   O += p_f16 x (Vh+Vl)        (2 products, P single fp16)
// Double-buffered K/V, exp2 softmax. Output single fp16 row-major.
// Grid (4, B*H), 2 passes: q-tiles {7-bx, bx} (BQ=128). 8 warps x 16 rows.
// ---------------------------------------------------------------------------
#define ASTR 144
#define Q_OFF  0             // 18432: Q single fp16 (scaled)
#define K_OFF  18432         // 2 bufs x 9216 (K single fp16)
#define V_OFF  36864         // 2 bufs x (Vth 9216 + Vtl 9216)
#define KBUF   9216
#define VBUF   18432
#define MSK_OFF 73728
#define ATTN_SMEM (73728 + 512)

__global__ __launch_bounds__(256, 2) void attn_hmma(
    const __half* __restrict__ qf, const __half* __restrict__ kf,
    const __half* __restrict__ vth, const __half* __restrict__ vtl,
    const int* __restrict__ mask,
    __half* __restrict__ ao)
{
    extern __shared__ char smc[];
    const uint32_t sb = smem_to_u32(smc);

    const int t    = threadIdx.x;
    const int lane = t & 31;
    const int w    = t >> 5;
    const int bh   = blockIdx.y;
    const int b    = bh >> 4;
    const int h    = bh & 15;
    float* msk_s = (float*)(smc + MSK_OFF);

    const uint32_t aq_base = sb + Q_OFF +
        (uint32_t)((16 * w + (lane & 15)) * ASTR + (lane >> 4) * 16);
    const uint32_t bk_base = sb + K_OFF +
        (uint32_t)(((lane & 7) + ((lane >> 4) << 3)) * ASTR + ((lane >> 3) & 1) * 16);
    const uint32_t bv_base = sb + V_OFF +
        (uint32_t)(((lane & 7) + ((lane >> 4) << 3)) * ASTR + ((lane >> 3) & 1) * 16);

#pragma unroll 1
    for (int pass = 0; pass < 2; pass++) {
        const int qt = pass ? (int)blockIdx.x : 7 - (int)blockIdx.x;
        __syncthreads();

        // ---- Q tile: 128 rows x 64 fp16 = 1024 chunks ----
#pragma unroll
        for (int p = 0; p < 4; p++) {
            const int idx = t + (p << 8);
            const int row = idx >> 3;
            const int ch  = idx & 7;
            const __half* src = qf +
                (size_t)(b * 1024 + qt * 128 + row) * 1024 + h * 64 + ch * 8;
            CP_ASYNC16(sb + Q_OFF + row * ASTR + ch * 16, src);
        }
        CP_COMMIT();

        const int kmax = 2 * qt + 1;

        // ---- prologue: K/V for kt=0 into buffer 0, mask[0] ----
        // 1536 chunks: m = 0:K (512), 1:Vth (512), 2:Vtl (512)
#pragma unroll
        for (int p = 0; p < 6; p++) {
            const int c   = t + (p << 8);
            const int m   = c >> 9;
            const int idx = c & 511;
            const int row = idx >> 3;
            const int ch  = idx & 7;
            const void* src;
            uint32_t dst;
            if (m == 0) {
                src = kf + (size_t)(b * 1024 + row) * 1024 + h * 64 + ch * 8;
                dst = sb + K_OFF + row * ASTR + ch * 16;
            } else if (m == 1) {
                src = vth + (size_t)(bh * 64 + row) * 1024 + ch * 8;
                dst = sb + V_OFF + row * ASTR + ch * 16;
            } else {
                src = vtl + (size_t)(bh * 64 + row) * 1024 + ch * 8;
                dst = sb + V_OFF + 9216 + row * ASTR + ch * 16;
            }
            CP_ASYNC16(dst, src);
        }
        if (t < 64)
            msk_s[t] = (mask[b * TSEQ + t] != 0) ? 0.0f : -1e30f;
        CP_COMMIT();

        float m0 = -1e30f, m1 = -1e30f, l0 = 0.0f, l1 = 0.0f;
        float of[8][4];
#pragma unroll
        for (int j = 0; j < 8; j++)
#pragma unroll
            for (int e = 0; e < 4; e++) of[j][e] = 0.0f;

        const int qrow_w = qt * 128 + 16 * w;
        const int r0g = qrow_w + (lane >> 2);

#pragma unroll 1
        for (int kt = 0; kt <= kmax; kt++) {
            CP_WAIT(0);
            __syncthreads();

            if (kt < kmax) {
                const uint32_t kbK = (uint32_t)(((kt + 1) & 1) * KBUF);
                const uint32_t kbV = (uint32_t)(((kt + 1) & 1) * VBUF);
#pragma unroll
                for (int p = 0; p < 6; p++) {
                    const int c   = t + (p << 8);
                    const int m   = c >> 9;
                    const int idx = c & 511;
                    const int row = idx >> 3;
                    const int ch  = idx & 7;
                    const void* src;
                    uint32_t dst;
                    if (m == 0) {
                        src = kf + (size_t)(b * 1024 + (kt + 1) * 64 + row) * 1024 + h * 64 + ch * 8;
                        dst = sb + K_OFF + kbK + row * ASTR + ch * 16;
                    } else if (m == 1) {
                        src = vth + (size_t)(bh * 64 + row) * 1024 + (kt + 1) * 64 + ch * 8;
                        dst = sb + V_OFF + kbV + row * ASTR + ch * 16;
                    } else {
                        src = vtl + (size_t)(bh * 64 + row) * 1024 + (kt + 1) * 64 + ch * 8;
                        dst = sb + V_OFF + kbV + 9216 + row * ASTR + ch * 16;
                    }
                    CP_ASYNC16(dst, src);
                }
                if (t < 64)
                    msk_s[((kt + 1) & 1) * 64 + t] =
                        (mask[b * TSEQ + (kt + 1) * 64 + t] != 0) ? 0.0f : -1e30f;
            }
            CP_COMMIT();

            const uint32_t kbK = (uint32_t)((kt & 1) * KBUF);
            const uint32_t kbV = (uint32_t)((kt & 1) * VBUF);
            const float* msk = msk_s + (kt & 1) * 64;

            // ---- S = q @ k^T (1 product) ----
            float s[8][4];
#pragma unroll
            for (int j = 0; j < 8; j++)
#pragma unroll
                for (int e = 0; e < 4; e++) s[j][e] = 0.0f;

#pragma unroll
            for (int ks = 0; ks < 4; ks++) {
                uint32_t aq[4];
                LDSM_X4(aq[0], aq[1], aq[2], aq[3], aq_base + ks * 32);
#pragma unroll
                for (int g = 0; g < 4; g++) {
                    uint32_t bk[4];
                    LDSM_X4(bk[0], bk[1], bk[2], bk[3],
                            bk_base + kbK + g * (16 * ASTR) + ks * 32);
                    MMAF16(s[2 * g],     aq, bk[0], bk[1]);
                    MMAF16(s[2 * g + 1], aq, bk[2], bk[3]);
                }
            }

            // ---- mask + causal ----
            const int lc = 2 * (lane & 3);
#pragma unroll
            for (int j = 0; j < 8; j++) {
                const float mj0 = msk[j * 8 + lc];
                const float mj1 = msk[j * 8 + lc + 1];
                s[j][0] += mj0; s[j][1] += mj1;
                s[j][2] += mj0; s[j][3] += mj1;
            }
            if (kt * 64 + 63 > qrow_w) {
                const int r1g = r0g + 8;
#pragma unroll
                for (int j = 0; j < 8; j++) {
                    const int c0 = kt * 64 + j * 8 + lc;
                    if (c0     > r0g) s[j][0] = -1e30f;
                    if (c0 + 1 > r0g) s[j][1] = -1e30f;
                    if (c0     > r1g) s[j][2] = -1e30f;
                    if (c0 + 1 > r1g) s[j][3] = -1e30f;
                }
            }

            // ---- online softmax (exp2 domain) ----
            float rm0 = -1e30f, rm1 = -1e30f;
#pragma unroll
            for (int j = 0; j < 8; j++) {
                rm0 = fmaxf(rm0, fmaxf(s[j][0], s[j][1]));
                rm1 = fmaxf(rm1, fmaxf(s[j][2], s[j][3]));
            }
            rm0 = fmaxf(rm0, __shfl_xor_sync(0xffffffffu, rm0, 1));
            rm0 = fmaxf(rm0, __shfl_xor_sync(0xffffffffu, rm0, 2));
            rm1 = fmaxf(rm1, __shfl_xor_sync(0xffffffffu, rm1, 1));
            rm1 = fmaxf(rm1, __shfl_xor_sync(0xffffffffu, rm1, 2));
            const float mn0 = fmaxf(m0, rm0), mn1 = fmaxf(m1, rm1);
            const float al0 = ex2(m0 - mn0), al1 = ex2(m1 - mn1);
            m0 = mn0; m1 = mn1;
            float ls0 = 0.0f, ls1 = 0.0f;
#pragma unroll
            for (int j = 0; j < 8; j++) {
                s[j][0] = ex2(s[j][0] - mn0); ls0 += s[j][0];
                s[j][1] = ex2(s[j][1] - mn0); ls0 += s[j][1];
                s[j][2] = ex2(s[j][2] - mn1); ls1 += s[j][2];
                s[j][3] = ex2(s[j][3] - mn1); ls1 += s[j][3];
            }
            ls0 += __shfl_xor_sync(0xffffffffu, ls0, 1);
            ls0 += __shfl_xor_sync(0xffffffffu, ls0, 2);
            ls1 += __shfl_xor_sync(0xffffffffu, ls1, 1);
            ls1 += __shfl_xor_sync(0xffffffffu, ls1, 2);
            l0 = l0 * al0 + ls0;
            l1 = l1 * al1 + ls1;
#pragma unroll
            for (int j = 0; j < 8; j++) {
                of[j][0] *= al0; of[j][1] *= al0;
                of[j][2] *= al1; of[j][3] *= al1;
            }

            // ---- O += p_f16 @ (Vh + Vl) ----
#pragma unroll
            for (int kt2 = 0; kt2 < 4; kt2++) {
                uint32_t ap[4];
                {
                    const float* p0 = s[2 * kt2];
                    const float* p1 = s[2 * kt2 + 1];
                    ap[0] = packhf(p0[0], p0[1]); ap[1] = packhf(p0[2], p0[3]);
                    ap[2] = packhf(p1[0], p1[1]); ap[3] = packhf(p1[2], p1[3]);
                }
#pragma unroll
                for (int g = 0; g < 4; g++) {
                    uint32_t bvh[4], bvl[4];
                    LDSM_X4(bvh[0], bvh[1], bvh[2], bvh[3],
                            bv_base + kbV + g * (16 * ASTR) + kt2 * 32);
                    LDSM_X4(bvl[0], bvl[1], bvl[2], bvl[3],
                            bv_base + kbV + 9216 + g * (16 * ASTR) + kt2 * 32);
                    MMAF16(of[2 * g],     ap, bvh[0], bvh[1]);
                    MMAF16(of[2 * g],     ap, bvl[0], bvl[1]);
                    MMAF16(of[2 * g + 1], ap, bvh[2], bvh[3]);
                    MMAF16(of[2 * g + 1], ap, bvl[2], bvl[3]);
                }
            }
        }

        // ---- normalize + store single fp16 row-major [B*T, D] ----
        const float inv0 = 1.0f / l0, inv1 = 1.0f / l1;
        const size_t obase = ((size_t)(b * TSEQ) + r0g) * DMODEL + h * DHEAD + 2 * (lane & 3);
#pragma unroll
        for (int j = 0; j < 8; j++) {
            *reinterpret_cast<uint32_t*>(ao + obase + j * 8) =
                packhf(of[j][0] * inv0, of[j][1] * inv0);
            *reinterpret_cast<uint32_t*>(ao + obase + (size_t)8 * DMODEL + j * 8) =
                packhf(of[j][2] * inv1, of[j][3] * inv1);
        }
    }
}

// ---------------------------------------------------------------------------
extern "C" void kernel_launch(void* const* d_in, const int* in_sizes, int n_in,
                              void* d_out, int out_size)
{
    const float* x     = (const float*)d_in[0];
    const float* Wqkv  = (const float*)d_in[1];
    const float* bqkv  = (const float*)d_in[2];
    const float* Wproj = (const float*)d_in[3];
    const float* bproj = (const float*)d_in[4];
    const int*   mask  = (const int*)d_in[5];
    float* out = (float*)d_out;

    __half *x16, *wq16, *wp16, *ao16, *qf, *kf, *vfh, *vfl, *vth, *vtl;
    cudaGetSymbolAddress((void**)&x16,  g_x16);
    cudaGetSymbolAddress((void**)&wq16, g_wq16);
    cudaGetSymbolAddress((void**)&wp16, g_wp16);
    cudaGetSymbolAddress((void**)&ao16, g_ao16);
    cudaGetSymbolAddress((void**)&qf,  g_qf);
    cudaGetSymbolAddress((void**)&kf,  g_kf);
    cudaGetSymbolAddress((void**)&vfh, g_v16h);
    cudaGetSymbolAddress((void**)&vfl, g_v16l);
    cudaGetSymbolAddress((void**)&vth, g_vth);
    cudaGetSymbolAddress((void**)&vtl, g_vtl);

    cudaFuncSetAttribute(attn_hmma,
                         cudaFuncAttributeMaxDynamicSharedMemorySize, ATTN_SMEM);
    cudaFuncSetAttribute(gemm_f16<0>,
                         cudaFuncAttributeMaxDynamicSharedMemorySize, GEMM_SMEM);
    cudaFuncSetAttribute(gemm_f16<1>,
                         cudaFuncAttributeMaxDynamicSharedMemorySize, GEMM_SMEM);

    // Convert input and weights (weights transposed to [N][K]) to fp16
    convert_h<<<(MROWS * DMODEL) / 1024, 256>>>(x, x16);
    convert_wT<<<dim3(QKV_N / 32, DMODEL / 32), dim3(32, 8)>>>(
        Wqkv, wq16, DMODEL, QKV_N);
    convert_wT<<<dim3(DMODEL / 32, DMODEL / 32), dim3(32, 8)>>>(
        Wproj, wp16, DMODEL, DMODEL);

    // 1) QKV GEMM (fp16 single-product) -> Q f16 / K f16 / V split-f16
    gemm_f16<1><<<dim3(QKV_N / 128, MROWS / 128), 128, GEMM_SMEM>>>(
        x16, wq16, bqkv, nullptr, qf, kf, vfh, vfl, QKV_N);

    // 2) V transpose (fp16)
    transpose_v<<<dim3(32, 128), dim3(32, 8)>>>(vfh, vfl, vth, vtl);

    // 3) Fused causal attention (S: fp16 1-product; PV: fp16 2-product)
    attn_hmma<<<dim3(4, BATCH * NH), 256, ATTN_SMEM>>>(
        qf, kf, vth, vtl, mask, ao16);

    // 4) out = attn @ Wproj + bproj (fp16 single-product)
    gemm_f16<0><<<dim3(DMODEL / 128, MROWS / 128), 128, GEMM_SMEM>>>(
        ao16, wp16, bproj, out,
        nullptr, nullptr, nullptr, nullptr, DMODEL);
}

// round 14
// speedup vs baseline: 1.4176x; 1.1272x over previous
#include <cuda_runtime.h>
#include <cuda_bf16.h>
#include <cuda_fp16.h>
#include <math.h>
#include <cstdint>

// Problem constants
#define BATCH 4
#define TSEQ  1024
#define DMODEL 1024
#define NH 16
#define DHEAD 64
#define QKV_N 3072   // 3*DMODEL
#define MROWS 4096   // BATCH*TSEQ
#define KDIM 1024    // K is 1024 for both GEMMs
#define NTK  32      // k-tiles (KDIM/32)

// Q scale: 1/sqrt(64) * log2(e)  (softmax done in exp2 domain)
#define QSCALE (0.125f * 1.44269504088896f)

// ---------------------------------------------------------------------------
// Scratch (device globals: allocation-free)
// ---------------------------------------------------------------------------
__device__ __half g_x16[(size_t)MROWS * DMODEL];         // x fp16 row-major
__device__ __half g_wq16[(size_t)QKV_N * DMODEL];        // Wqkv^T fp16 [N][K]
__device__ __half g_wp16[(size_t)DMODEL * DMODEL];       // Wproj^T fp16 [N][K]
__device__ __half g_ao16[(size_t)MROWS * DMODEL];        // attn out fp16
__device__ __half g_qf[(size_t)MROWS * DMODEL];          // Q scaled, single fp16
__device__ __half g_kf[(size_t)MROWS * DMODEL];          // K single fp16
__device__ __half g_vf[(size_t)MROWS * DMODEL];          // V single fp16
__device__ __half g_vt[(size_t)MROWS * DMODEL];          // V^T [bh][dh][t]

// ---------------------------------------------------------------------------
// PTX helpers (base ISA only — compute_103 virtual arch, no tcgen05)
// ---------------------------------------------------------------------------
__device__ __forceinline__ uint32_t smem_to_u32(const void* p) {
    uint32_t a;
    asm("{ .reg .u64 t; cvta.to.shared.u64 t, %1; cvt.u32.u64 %0, t; }"
        : "=r"(a) : "l"(p));
    return a;
}

#define CP_ASYNC16(smem, gptr) \
    asm volatile("cp.async.cg.shared.global [%0], [%1], 16;" \
        :: "r"(smem), "l"(gptr) : "memory")
#define CP_COMMIT() asm volatile("cp.async.commit_group;" ::: "memory")
#define CP_WAIT(n)  asm volatile("cp.async.wait_group %0;" :: "n"(n) : "memory")

#define LDSM_X4(r0, r1, r2, r3, addr) \
    asm volatile("ldmatrix.sync.aligned.m8n8.x4.shared.b16 {%0,%1,%2,%3}, [%4];" \
        : "=r"(r0), "=r"(r1), "=r"(r2), "=r"(r3) : "r"(addr))

#define MMAF16(c, a, b0, b1) \
    asm volatile("mma.sync.aligned.m16n8k16.row.col.f32.f16.f16.f32 " \
        "{%0,%1,%2,%3}, {%4,%5,%6,%7}, {%8,%9}, {%0,%1,%2,%3};" \
        : "+f"((c)[0]), "+f"((c)[1]), "+f"((c)[2]), "+f"((c)[3]) \
        : "r"((a)[0]), "r"((a)[1]), "r"((a)[2]), "r"((a)[3]), \
          "r"(b0), "r"(b1))

// pack two floats to f16x2 (lo addr half = first arg)
__device__ __forceinline__ uint32_t packhf(float lo, float hi) {
    uint32_t r;
    asm("cvt.rn.f16x2.f32 %0, %1, %2;" : "=r"(r) : "f"(hi), "f"(lo));
    return r;
}
__device__ __forceinline__ float ex2(float x) {
    float r;
    asm("ex2.approx.f32 %0, %1;" : "=f"(r) : "f"(x));
    return r;
}

// Swizzled byte offset within one 8KB matrix tile (128 rows x 32 fp16):
// row-pair lines of 128B, chunk3 = (r&1)*4 + ch, XOR (r>>1)&7. (verified R7+)
__device__ __forceinline__ uint32_t sw_off(int r, int ch) {
    const uint32_t chunk3 = (uint32_t)(((r & 1) << 2) | ch);
    return (uint32_t)((r >> 1) * 128) + ((chunk3 ^ ((uint32_t)(r >> 1) & 7u)) << 4);
}

// ---------------------------------------------------------------------------
// FP16 single-product HMMA GEMM: C = A[M,K] @ (B[N,K])^T + bias
// CTA 128x128, K-tile 32, 5-stage cp.async (swizzled smem, 16KB/stage),
// 2 CTAs/SM, 4 warps (2x2), warp tile 64x64.  (round-10/12 proven config)
// MODE 0: fp32 C out.  MODE 1: QKV epilogue -> Q f16 / K f16 / V f16
// ---------------------------------------------------------------------------
#define MATB   8192
#define STAGEB 16384
#define NSTAGE 5
#define GEMM_SMEM (NSTAGE * STAGEB)

template <int MODE>
__global__ __launch_bounds__(128, 2) void gemm_f16(
    const __half* __restrict__ A, const __half* __restrict__ B,
    const float* __restrict__ bias, float* __restrict__ C,
    __half* __restrict__ qf, __half* __restrict__ kf,
    __half* __restrict__ vf,
    int Ntot)
{
    extern __shared__ char dsm[];
    const uint32_t sb = smem_to_u32(dsm);

    const int t    = threadIdx.x;
    const int lane = t & 31;
    const int wid  = t >> 5;
    const int wm   = wid >> 1;
    const int wn   = wid & 1;
    const int bm   = blockIdx.y << 7;
    const int bn   = blockIdx.x << 7;

    // cp.async plan: 2 matrices x 512 chunks(16B) / 128 thr = 8/thread
    const int rbase = t >> 2;
    const int ch0   = t & 3;
    uint32_t soff[8];
    const __half* gp[8];
#pragma unroll
    for (int m = 0; m < 2; m++)
#pragma unroll
        for (int hh = 0; hh < 4; hh++) {
            const int r = rbase + hh * 32;
            soff[m * 4 + hh] = (uint32_t)(m * MATB) + sw_off(r, ch0);
            gp[m * 4 + hh]   = (m ? B : A) +
                (size_t)((m ? bn : bm) + r) * KDIM + ch0 * 8;
        }

    const uint32_t a_base = sw_off(wm * 64 + (lane & 15), lane >> 4);
    const uint32_t b_base = (uint32_t)MATB +
        sw_off(wn * 64 + (lane & 7) + ((lane >> 4) << 3), (lane >> 3) & 1);

    float acc[4][8][4];
#pragma unroll
    for (int mi = 0; mi < 4; mi++)
#pragma unroll
        for (int ni = 0; ni < 8; ni++)
#pragma unroll
            for (int e = 0; e < 4; e++) acc[mi][ni][e] = 0.0f;

    // prologue: stages 0..3
#pragma unroll
    for (int s = 0; s < NSTAGE - 1; s++) {
        const uint32_t st = sb + (uint32_t)s * STAGEB;
        const int ko = s * 32;
#pragma unroll
        for (int i = 0; i < 8; i++) CP_ASYNC16(st + soff[i], gp[i] + ko);
        CP_COMMIT();
    }

    int buf = 0, nbuf = NSTAGE - 1;
#pragma unroll 1
    for (int kt = 0; kt < NTK; kt++) {
        CP_WAIT(NSTAGE - 2);
        __syncthreads();

        if (kt + NSTAGE - 1 < NTK) {
            const uint32_t st = sb + (uint32_t)nbuf * STAGEB;
            const int ko = (kt + NSTAGE - 1) * 32;
#pragma unroll
            for (int i = 0; i < 8; i++) CP_ASYNC16(st + soff[i], gp[i] + ko);
        }
        CP_COMMIT();

        const uint32_t stg = sb + (uint32_t)buf * STAGEB;
        buf = (buf == NSTAGE - 1) ? 0 : buf + 1;
        nbuf = (nbuf == NSTAGE - 1) ? 0 : nbuf + 1;

#pragma unroll
        for (int ks = 0; ks < 2; ks++) {
            const uint32_t ksx = (uint32_t)(ks << 5);
            uint32_t ah[4][4];
#pragma unroll
            for (int mi = 0; mi < 4; mi++) {
                const uint32_t ao = (a_base + (uint32_t)(mi * 1024)) ^ ksx;
                LDSM_X4(ah[mi][0], ah[mi][1], ah[mi][2], ah[mi][3], stg + ao);
            }
            uint32_t rbh[4][4];
#pragma unroll
            for (int g = 0; g < 4; g++) {
                const uint32_t bo = (b_base + (uint32_t)(g * 1024)) ^ ksx;
                LDSM_X4(rbh[g][0], rbh[g][1], rbh[g][2], rbh[g][3], stg + bo);
            }
#pragma unroll
            for (int mi = 0; mi < 4; mi++)
#pragma unroll
                for (int ni = 0; ni < 8; ni++) {
                    const int g = ni >> 1, u = (ni & 1) * 2;
                    MMAF16(acc[mi][ni], ah[mi], rbh[g][u], rbh[g][u + 1]);
                }
        }
    }

    // ---- epilogue ----
    const int er = bm + wm * 64 + (lane >> 2);
    const int ec = bn + wn * 64 + (lane & 3) * 2;

    if (MODE == 0) {
#pragma unroll
        for (int ni = 0; ni < 8; ni++) {
            const int col = ec + ni * 8;
            const float2 bv = *reinterpret_cast<const float2*>(bias + col);
#pragma unroll
            for (int mi = 0; mi < 4; mi++) {
                const int r0 = er + mi * 16;
                float2 o0, o1;
                o0.x = acc[mi][ni][0] + bv.x;
                o0.y = acc[mi][ni][1] + bv.y;
                o1.x = acc[mi][ni][2] + bv.x;
                o1.y = acc[mi][ni][3] + bv.y;
                *reinterpret_cast<float2*>(C + (size_t)r0 * Ntot + col) = o0;
                *reinterpret_cast<float2*>(C + (size_t)(r0 + 8) * Ntot + col) = o1;
            }
        }
    } else {
        // seg 0 = Q (scaled f16); 1 = K (f16); 2 = V (f16)
        const int seg = bn >> 10;
        const int ecl = ec & 1023;
        __half* D = (seg == 0) ? qf : (seg == 1) ? kf : vf;
        const float scale = (seg == 0) ? QSCALE : 1.0f;
#pragma unroll
        for (int ni = 0; ni < 8; ni++) {
            const int col = ec + ni * 8;
            const float2 bv = *reinterpret_cast<const float2*>(bias + col);
            const int cl = ecl + ni * 8;
#pragma unroll
            for (int mi = 0; mi < 4; mi++) {
                const int r0 = er + mi * 16;
                const float v00 = (acc[mi][ni][0] + bv.x) * scale;
                const float v01 = (acc[mi][ni][1] + bv.y) * scale;
                const float v10 = (acc[mi][ni][2] + bv.x) * scale;
                const float v11 = (acc[mi][ni][3] + bv.y) * scale;
                *reinterpret_cast<uint32_t*>(D + (size_t)r0 * 1024 + cl) =
                    packhf(v00, v01);
                *reinterpret_cast<uint32_t*>(D + (size_t)(r0 + 8) * 1024 + cl) =
                    packhf(v10, v11);
            }
        }
    }
}

// ---------------------------------------------------------------------------
// fp32 -> fp16 convert, 4 elems/thread
// ---------------------------------------------------------------------------
__global__ __launch_bounds__(256) void convert_h(
    const float* __restrict__ A, __half* __restrict__ H)
{
    const int i = blockIdx.x * blockDim.x + threadIdx.x;
    const float4 v = reinterpret_cast<const float4*>(A)[i];
    uint2 o;
    o.x = packhf(v.x, v.y);
    o.y = packhf(v.z, v.w);
    *reinterpret_cast<uint2*>(H + (size_t)i * 4) = o;
}

// ---------------------------------------------------------------------------
// W[K][N] fp32 -> W^T[N][K] fp16 (transpose + convert), block (32,8)
// ---------------------------------------------------------------------------
__global__ __launch_bounds__(256) void convert_wT(
    const float* __restrict__ W, __half* __restrict__ T, int K, int N)
{
    __shared__ float tile[32][33];
    const int tx = threadIdx.x, ty = threadIdx.y;
    const int n0 = blockIdx.x * 32, k0 = blockIdx.y * 32;
#pragma unroll
    for (int i = 0; i < 4; i++)
        tile[ty + i * 8][tx] = W[(size_t)(k0 + ty + i * 8) * N + n0 + tx];
    __syncthreads();
#pragma unroll
    for (int i = 0; i < 4; i++) {
        const float v = tile[tx][ty + i * 8];
        T[(size_t)(n0 + ty + i * 8) * K + k0 + tx] = __float2half_rn(v);
    }
}

// ---------------------------------------------------------------------------
// V transpose (fp16): vf [B*T][1024] -> vt [(b*16+h)*64+dh][1024] (col = t)
// ---------------------------------------------------------------------------
__global__ __launch_bounds__(256) void transpose_v(
    const __half* __restrict__ vf, __half* __restrict__ vt)
{
    __shared__ __half th[32][33];
    const int tx = threadIdx.x, ty = threadIdx.y;
    const int c0 = blockIdx.x * 32;
    const int r0 = blockIdx.y * 32;
#pragma unroll
    for (int i = 0; i < 4; i++) {
        const size_t src = (size_t)(r0 + ty + i * 8) * 1024 + c0 + tx;
        th[ty + i * 8][tx] = vf[src];
    }
    __syncthreads();
    const int b = r0 >> 10;
    const int tbase = (r0 & 1023) + tx;
#pragma unroll
    for (int i = 0; i < 4; i++) {
        const int cp = c0 + ty + i * 8;
        const int hh = cp >> 6, dh = cp & 63;
        const size_t dst = (size_t)(((b * 16 + hh) * 64) + dh) * 1024 + tbase;
        vt[dst] = th[tx][ty + i * 8];
    }
}

// ---------------------------------------------------------------------------
// HMMA flash attention, all single fp16 products:
//   S  = q_f16 x k_f16          (1 product)
//   O += p_f16 x v_f16          (1 product)
// Double-buffered K/V, exp2 softmax. Output single fp16 row-major.
// Grid (4, B*H), 2 passes: q-tiles {7-bx, bx} (BQ=128). 8 warps x 16 rows.
// ---------------------------------------------------------------------------
#define ASTR 144
#define Q_OFF  0             // 18432: Q single fp16 (scaled)
#define K_OFF  18432         // 2 bufs x 9216
#define V_OFF  36864         // 2 bufs x 9216
#define KVB    9216
#define MSK_OFF 55296
#define ATTN_SMEM (55296 + 512)

__global__ __launch_bounds__(256, 2) void attn_hmma(
    const __half* __restrict__ qf, const __half* __restrict__ kf,
    const __half* __restrict__ vt,
    const int* __restrict__ mask,
    __half* __restrict__ ao)
{
    extern __shared__ char smc[];
    const uint32_t sb = smem_to_u32(smc);

    const int t    = threadIdx.x;
    const int lane = t & 31;
    const int w    = t >> 5;
    const int bh   = blockIdx.y;
    const int b    = bh >> 4;
    const int h    = bh & 15;
    float* msk_s = (float*)(smc + MSK_OFF);

    const uint32_t aq_base = sb + Q_OFF +
        (uint32_t)((16 * w + (lane & 15)) * ASTR + (lane >> 4) * 16);
    const uint32_t bk_base = sb + K_OFF +
        (uint32_t)(((lane & 7) + ((lane >> 4) << 3)) * ASTR + ((lane >> 3) & 1) * 16);
    const uint32_t bv_base = sb + V_OFF +
        (uint32_t)(((lane & 7) + ((lane >> 4) << 3)) * ASTR + ((lane >> 3) & 1) * 16);

#pragma unroll 1
    for (int pass = 0; pass < 2; pass++) {
        const int qt = pass ? (int)blockIdx.x : 7 - (int)blockIdx.x;
        __syncthreads();

        // ---- Q tile: 128 rows x 64 fp16 = 1024 chunks ----
#pragma unroll
        for (int p = 0; p < 4; p++) {
            const int idx = t + (p << 8);
            const int row = idx >> 3;
            const int ch  = idx & 7;
            const __half* src = qf +
                (size_t)(b * 1024 + qt * 128 + row) * 1024 + h * 64 + ch * 8;
            CP_ASYNC16(sb + Q_OFF + row * ASTR + ch * 16, src);
        }
        CP_COMMIT();

        const int kmax = 2 * qt + 1;

        // ---- prologue: K/V for kt=0 into buffer 0, mask[0] ----
        // 1024 chunks: m = 0:K (512), 1:Vt (512)
#pragma unroll
        for (int p = 0; p < 4; p++) {
            const int c   = t + (p << 8);
            const int m   = c >> 9;
            const int idx = c & 511;
            const int row = idx >> 3;
            const int ch  = idx & 7;
            const void* src;
            uint32_t dst;
            if (m == 0) {
                src = kf + (size_t)(b * 1024 + row) * 1024 + h * 64 + ch * 8;
                dst = sb + K_OFF + row * ASTR + ch * 16;
            } else {
                src = vt + (size_t)(bh * 64 + row) * 1024 + ch * 8;
                dst = sb + V_OFF + row * ASTR + ch * 16;
            }
            CP_ASYNC16(dst, src);
        }
        if (t < 64)
            msk_s[t] = (mask[b * TSEQ + t] != 0) ? 0.0f : -1e30f;
        CP_COMMIT();

        float m0 = -1e30f, m1 = -1e30f, l0 = 0.0f, l1 = 0.0f;
        float of[8][4];
#pragma unroll
        for (int j = 0; j < 8; j++)
#pragma unroll
            for (int e = 0; e < 4; e++) of[j][e] = 0.0f;

        const int qrow_w = qt * 128 + 16 * w;
        const int r0g = qrow_w + (lane >> 2);

#pragma unroll 1
        for (int kt = 0; kt <= kmax; kt++) {
            CP_WAIT(0);
            __syncthreads();

            if (kt < kmax) {
                const uint32_t kb = (uint32_t)(((kt + 1) & 1) * KVB);
#pragma unroll
                for (int p = 0; p < 4; p++) {
                    const int c   = t + (p << 8);
                    const int m   = c >> 9;
                    const int idx = c & 511;
                    const int row = idx >> 3;
                    const int ch  = idx & 7;
                    const void* src;
                    uint32_t dst;
                    if (m == 0) {
                        src = kf + (size_t)(b * 1024 + (kt + 1) * 64 + row) * 1024 + h * 64 + ch * 8;
                        dst = sb + K_OFF + kb + row * ASTR + ch * 16;
                    } else {
                        src = vt + (size_t)(bh * 64 + row) * 1024 + (kt + 1) * 64 + ch * 8;
                        dst = sb + V_OFF + kb + row * ASTR + ch * 16;
                    }
                    CP_ASYNC16(dst, src);
                }
                if (t < 64)
                    msk_s[((kt + 1) & 1) * 64 + t] =
                        (mask[b * TSEQ + (kt + 1) * 64 + t] != 0) ? 0.0f : -1e30f;
            }
            CP_COMMIT();

            const uint32_t kb = (uint32_t)((kt & 1) * KVB);
            const float* msk = msk_s + (kt & 1) * 64;

            // ---- S = q @ k^T (1 product) ----
            float s[8][4];
#pragma unroll
            for (int j = 0; j < 8; j++)
#pragma unroll
                for (int e = 0; e < 4; e++) s[j][e] = 0.0f;

#pragma unroll
            for (int ks = 0; ks < 4; ks++) {
                uint32_t aq[4];
                LDSM_X4(aq[0], aq[1], aq[2], aq[3], aq_base + ks * 32);
#pragma unroll
                for (int g = 0; g < 4; g++) {
                    uint32_t bk[4];
                    LDSM_X4(bk[0], bk[1], bk[2], bk[3],
                            bk_base + kb + g * (16 * ASTR) + ks * 32);
                    MMAF16(s[2 * g],     aq, bk[0], bk[1]);
                    MMAF16(s[2 * g + 1], aq, bk[2], bk[3]);
                }
            }

            // ---- mask + causal ----
            const int lc = 2 * (lane & 3);
#pragma unroll
            for (int j = 0; j < 8; j++) {
                const float mj0 = msk[j * 8 + lc];
                const float mj1 = msk[j * 8 + lc + 1];
                s[j][0] += mj0; s[j][1] += mj1;
                s[j][2] += mj0; s[j][3] += mj1;
            }
            if (kt * 64 + 63 > qrow_w) {
                const int r1g = r0g + 8;
#pragma unroll
                for (int j = 0; j < 8; j++) {
                    const int c0 = kt * 64 + j * 8 + lc;
                    if (c0     > r0g) s[j][0] = -1e30f;
                    if (c0 + 1 > r0g) s[j][1] = -1e30f;
                    if (c0     > r1g) s[j][2] = -1e30f;
                    if (c0 + 1 > r1g) s[j][3] = -1e30f;
                }
            }

            // ---- online softmax (exp2 domain) ----
            float rm0 = -1e30f, rm1 = -1e30f;
#pragma unroll
            for (int j = 0; j < 8; j++) {
                rm0 = fmaxf(rm0, fmaxf(s[j][0], s[j][1]));
                rm1 = fmaxf(rm1, fmaxf(s[j][2], s[j][3]));
            }
            rm0 = fmaxf(rm0, __shfl_xor_sync(0xffffffffu, rm0, 1));
            rm0 = fmaxf(rm0, __shfl_xor_sync(0xffffffffu, rm0, 2));
            rm1 = fmaxf(rm1, __shfl_xor_sync(0xffffffffu, rm1, 1));
            rm1 = fmaxf(rm1, __shfl_xor_sync(0xffffffffu, rm1, 2));
            const float mn0 = fmaxf(m0, rm0), mn1 = fmaxf(m1, rm1);
            const float al0 = ex2(m0 - mn0), al1 = ex2(m1 - mn1);
            m0 = mn0; m1 = mn1;
            float ls0 = 0.0f, ls1 = 0.0f;
#pragma unroll
            for (int j = 0; j < 8; j++) {
                s[j][0] = ex2(s[j][0] - mn0); ls0 += s[j][0];
                s[j][1] = ex2(s[j][1] - mn0); ls0 += s[j][1];
                s[j][2] = ex2(s[j][2] - mn1); ls1 += s[j][2];
                s[j][3] = ex2(s[j][3] - mn1); ls1 += s[j][3];
            }
            ls0 += __shfl_xor_sync(0xffffffffu, ls0, 1);
            ls0 += __shfl_xor_sync(0xffffffffu, ls0, 2);
            ls1 += __shfl_xor_sync(0xffffffffu, ls1, 1);
            ls1 += __shfl_xor_sync(0xffffffffu, ls1, 2);
            l0 = l0 * al0 + ls0;
            l1 = l1 * al1 + ls1;
#pragma unroll
            for (int j = 0; j < 8; j++) {
                of[j][0] *= al0; of[j][1] *= al0;
                of[j][2] *= al1; of[j][3] *= al1;
            }

            // ---- O += p_f16 @ v_f16 (1 product) ----
#pragma unroll
            for (int kt2 = 0; kt2 < 4; kt2++) {
                uint32_t ap[4];
                {
                    const float* p0 = s[2 * kt2];
                    const float* p1 = s[2 * kt2 + 1];
                    ap[0] = packhf(p0[0], p0[1]); ap[1] = packhf(p0[2], p0[3]);
                    ap[2] = packhf(p1[0], p1[1]); ap[3] = packhf(p1[2], p1[3]);
                }
#pragma unroll
                for (int g = 0; g < 4; g++) {
                    uint32_t bv[4];
                    LDSM_X4(bv[0], bv[1], bv[2], bv[3],
                            bv_base + kb + g * (16 * ASTR) + kt2 * 32);
                    MMAF16(of[2 * g],     ap, bv[0], bv[1]);
                    MMAF16(of[2 * g + 1], ap, bv[2], bv[3]);
                }
            }
        }

        // ---- normalize + store single fp16 row-major [B*T, D] ----
        const float inv0 = 1.0f / l0, inv1 = 1.0f / l1;
        const size_t obase = ((size_t)(b * TSEQ) + r0g) * DMODEL + h * DHEAD + 2 * (lane & 3);
#pragma unroll
        for (int j = 0; j < 8; j++) {
            *reinterpret_cast<uint32_t*>(ao + obase + j * 8) =
                packhf(of[j][0] * inv0, of[j][1] * inv0);
            *reinterpret_cast<uint32_t*>(ao + obase + (size_t)8 * DMODEL + j * 8) =
                packhf(of[j][2] * inv1, of[j][3] * inv1);
        }
    }
}

// ---------------------------------------------------------------------------
extern "C" void kernel_launch(void* const* d_in, const int* in_sizes, int n_in,
                              void* d_out, int out_size)
{
    const float* x     = (const float*)d_in[0];
    const float* Wqkv  = (const float*)d_in[1];
    const float* bqkv  = (const float*)d_in[2];
    const float* Wproj = (const float*)d_in[3];
    const float* bproj = (const float*)d_in[4];
    const int*   mask  = (const int*)d_in[5];
    float* out = (float*)d_out;

    __half *x16, *wq16, *wp16, *ao16, *qf, *kf, *vf, *vt;
    cudaGetSymbolAddress((void**)&x16,  g_x16);
    cudaGetSymbolAddress((void**)&wq16, g_wq16);
    cudaGetSymbolAddress((void**)&wp16, g_wp16);
    cudaGetSymbolAddress((void**)&ao16, g_ao16);
    cudaGetSymbolAddress((void**)&qf,  g_qf);
    cudaGetSymbolAddress((void**)&kf,  g_kf);
    cudaGetSymbolAddress((void**)&vf,  g_vf);
    cudaGetSymbolAddress((void**)&vt,  g_vt);

    cudaFuncSetAttribute(attn_hmma,
                         cudaFuncAttributeMaxDynamicSharedMemorySize, ATTN_SMEM);
    cudaFuncSetAttribute(gemm_f16<0>,
                         cudaFuncAttributeMaxDynamicSharedMemorySize, GEMM_SMEM);
    cudaFuncSetAttribute(gemm_f16<1>,
                         cudaFuncAttributeMaxDynamicSharedMemorySize, GEMM_SMEM);

    // Convert input and weights (weights transposed to [N][K]) to fp16
    convert_h<<<(MROWS * DMODEL) / 1024, 256>>>(x, x16);
    convert_wT<<<dim3(QKV_N / 32, DMODEL / 32), dim3(32, 8)>>>(
        Wqkv, wq16, DMODEL, QKV_N);
    convert_wT<<<dim3(DMODEL / 32, DMODEL / 32), dim3(32, 8)>>>(
        Wproj, wp16, DMODEL, DMODEL);

    // 1) QKV GEMM (fp16 single-product) -> Q/K/V single fp16
    gemm_f16<1><<<dim3(QKV_N / 128, MROWS / 128), 128, GEMM_SMEM>>>(
        x16, wq16, bqkv, nullptr, qf, kf, vf, QKV_N);

    // 2) V transpose (fp16, single)
    transpose_v<<<dim3(32, 128), dim3(32, 8)>>>(vf, vt);

    // 3) Fused causal attention (S & PV: single fp16 product)
    attn_hmma<<<dim3(4, BATCH * NH), 256, ATTN_SMEM>>>(
        qf, kf, vt, mask, ao16);

    // 4) out = attn @ Wproj + bproj (fp16 single-product)
    gemm_f16<0><<<dim3(DMODEL / 128, MROWS / 128), 128, GEMM_SMEM>>>(
        ao16, wp16, bproj, out,
        nullptr, nullptr, nullptr, DMODEL);
}

// round 15
// speedup vs baseline: 1.4358x; 1.0128x over previous
#include <cuda_runtime.h>
#include <cuda_bf16.h>
#include <cuda_fp16.h>
#include <math.h>
#include <cstdint>

// Problem constants
#define BATCH 4
#define TSEQ  1024
#define DMODEL 1024
#define NH 16
#define DHEAD 64
#define QKV_N 3072   // 3*DMODEL
#define MROWS 4096   // BATCH*TSEQ
#define KDIM 1024    // K is 1024 for both GEMMs
#define NTK  32      // k-tiles (KDIM/32)

// Q scale: 1/sqrt(64) * log2(e)  (softmax done in exp2 domain)
#define QSCALE (0.125f * 1.44269504088896f)

// ---------------------------------------------------------------------------
// Scratch (device globals: allocation-free)
// ---------------------------------------------------------------------------
__device__ __half g_x16[(size_t)MROWS * DMODEL];         // x fp16 row-major
__device__ __half g_wq16[(size_t)QKV_N * DMODEL];        // Wqkv^T fp16 [N][K]
__device__ __half g_wp16[(size_t)DMODEL * DMODEL];       // Wproj^T fp16 [N][K]
__device__ __half g_ao16[(size_t)MROWS * DMODEL];        // attn out fp16
__device__ __half g_qf[(size_t)MROWS * DMODEL];          // Q scaled, single fp16
__device__ __half g_kf[(size_t)MROWS * DMODEL];          // K single fp16
__device__ __half g_vf[(size_t)MROWS * DMODEL];          // V single fp16
__device__ __half g_vt[(size_t)MROWS * DMODEL];          // V^T [bh][dh][t]

// ---------------------------------------------------------------------------
// PTX helpers (base ISA only — compute_103 virtual arch, no tcgen05)
// ---------------------------------------------------------------------------
__device__ __forceinline__ uint32_t smem_to_u32(const void* p) {
    uint32_t a;
    asm("{ .reg .u64 t; cvta.to.shared.u64 t, %1; cvt.u32.u64 %0, t; }"
        : "=r"(a) : "l"(p));
    return a;
}

#define CP_ASYNC16(smem, gptr) \
    asm volatile("cp.async.cg.shared.global [%0], [%1], 16;" \
        :: "r"(smem), "l"(gptr) : "memory")
#define CP_COMMIT() asm volatile("cp.async.commit_group;" ::: "memory")
#define CP_WAIT(n)  asm volatile("cp.async.wait_group %0;" :: "n"(n) : "memory")

#define LDSM_X4(r0, r1, r2, r3, addr) \
    asm volatile("ldmatrix.sync.aligned.m8n8.x4.shared.b16 {%0,%1,%2,%3}, [%4];" \
        : "=r"(r0), "=r"(r1), "=r"(r2), "=r"(r3) : "r"(addr))

#define MMAF16(c, a, b0, b1) \
    asm volatile("mma.sync.aligned.m16n8k16.row.col.f32.f16.f16.f32 " \
        "{%0,%1,%2,%3}, {%4,%5,%6,%7}, {%8,%9}, {%0,%1,%2,%3};" \
        : "+f"((c)[0]), "+f"((c)[1]), "+f"((c)[2]), "+f"((c)[3]) \
        : "r"((a)[0]), "r"((a)[1]), "r"((a)[2]), "r"((a)[3]), \
          "r"(b0), "r"(b1))

// pack two floats to f16x2 (lo addr half = first arg)
__device__ __forceinline__ uint32_t packhf(float lo, float hi) {
    uint32_t r;
    asm("cvt.rn.f16x2.f32 %0, %1, %2;" : "=r"(r) : "f"(hi), "f"(lo));
    return r;
}
__device__ __forceinline__ float ex2(float x) {
    float r;
    asm("ex2.approx.f32 %0, %1;" : "=f"(r) : "f"(x));
    return r;
}

// Swizzled byte offset within one 8KB matrix tile (128 rows x 32 fp16):
// row-pair lines of 128B, chunk3 = (r&1)*4 + ch, XOR (r>>1)&7. (verified R7+)
__device__ __forceinline__ uint32_t sw_off(int r, int ch) {
    const uint32_t chunk3 = (uint32_t)(((r & 1) << 2) | ch);
    return (uint32_t)((r >> 1) * 128) + ((chunk3 ^ ((uint32_t)(r >> 1) & 7u)) << 4);
}

// ---------------------------------------------------------------------------
// FP16 single-product HMMA GEMM: C = A[M,K] @ (B[N,K])^T + bias
// CTA 128x128, K-tile 32, 5-stage cp.async (swizzled smem, 16KB/stage),
// 2 CTAs/SM, 4 warps (2x2), warp tile 64x64.
// Full k-tile fragments hoisted ahead of MMAs for load/MMA overlap.
// MODE 0: fp32 C out.  MODE 1: QKV epilogue -> Q f16 / K f16 / V f16
// ---------------------------------------------------------------------------
#define MATB   8192
#define STAGEB 16384
#define NSTAGE 5
#define GEMM_SMEM (NSTAGE * STAGEB)

template <int MODE>
__global__ __launch_bounds__(128, 2) void gemm_f16(
    const __half* __restrict__ A, const __half* __restrict__ B,
    const float* __restrict__ bias, float* __restrict__ C,
    __half* __restrict__ qf, __half* __restrict__ kf,
    __half* __restrict__ vf,
    int Ntot)
{
    extern __shared__ char dsm[];
    const uint32_t sb = smem_to_u32(dsm);

    const int t    = threadIdx.x;
    const int lane = t & 31;
    const int wid  = t >> 5;
    const int wm   = wid >> 1;
    const int wn   = wid & 1;
    const int bm   = blockIdx.y << 7;
    const int bn   = blockIdx.x << 7;

    // cp.async plan: 2 matrices x 512 chunks(16B) / 128 thr = 8/thread
    const int rbase = t >> 2;
    const int ch0   = t & 3;
    uint32_t soff[8];
    const __half* gp[8];
#pragma unroll
    for (int m = 0; m < 2; m++)
#pragma unroll
        for (int hh = 0; hh < 4; hh++) {
            const int r = rbase + hh * 32;
            soff[m * 4 + hh] = (uint32_t)(m * MATB) + sw_off(r, ch0);
            gp[m * 4 + hh]   = (m ? B : A) +
                (size_t)((m ? bn : bm) + r) * KDIM + ch0 * 8;
        }

    const uint32_t a_base = sw_off(wm * 64 + (lane & 15), lane >> 4);
    const uint32_t b_base = (uint32_t)MATB +
        sw_off(wn * 64 + (lane & 7) + ((lane >> 4) << 3), (lane >> 3) & 1);

    float acc[4][8][4];
#pragma unroll
    for (int mi = 0; mi < 4; mi++)
#pragma unroll
        for (int ni = 0; ni < 8; ni++)
#pragma unroll
            for (int e = 0; e < 4; e++) acc[mi][ni][e] = 0.0f;

    // prologue: stages 0..3
#pragma unroll
    for (int s = 0; s < NSTAGE - 1; s++) {
        const uint32_t st = sb + (uint32_t)s * STAGEB;
        const int ko = s * 32;
#pragma unroll
        for (int i = 0; i < 8; i++) CP_ASYNC16(st + soff[i], gp[i] + ko);
        CP_COMMIT();
    }

    int buf = 0, nbuf = NSTAGE - 1;
#pragma unroll 1
    for (int kt = 0; kt < NTK; kt++) {
        CP_WAIT(NSTAGE - 2);
        __syncthreads();

        if (kt + NSTAGE - 1 < NTK) {
            const uint32_t st = sb + (uint32_t)nbuf * STAGEB;
            const int ko = (kt + NSTAGE - 1) * 32;
#pragma unroll
            for (int i = 0; i < 8; i++) CP_ASYNC16(st + soff[i], gp[i] + ko);
        }
        CP_COMMIT();

        const uint32_t stg = sb + (uint32_t)buf * STAGEB;
        buf = (buf == NSTAGE - 1) ? 0 : buf + 1;
        nbuf = (nbuf == NSTAGE - 1) ? 0 : nbuf + 1;

        // ---- hoist ALL fragment loads for the k32 tile ----
        uint32_t ah[2][4][4], rbh[2][4][4];
#pragma unroll
        for (int ks = 0; ks < 2; ks++) {
            const uint32_t ksx = (uint32_t)(ks << 5);
#pragma unroll
            for (int mi = 0; mi < 4; mi++) {
                const uint32_t ao = (a_base + (uint32_t)(mi * 1024)) ^ ksx;
                LDSM_X4(ah[ks][mi][0], ah[ks][mi][1], ah[ks][mi][2], ah[ks][mi][3],
                        stg + ao);
            }
#pragma unroll
            for (int g = 0; g < 4; g++) {
                const uint32_t bo = (b_base + (uint32_t)(g * 1024)) ^ ksx;
                LDSM_X4(rbh[ks][g][0], rbh[ks][g][1], rbh[ks][g][2], rbh[ks][g][3],
                        stg + bo);
            }
        }
        // ---- 64 MMAs ----
#pragma unroll
        for (int ks = 0; ks < 2; ks++)
#pragma unroll
            for (int mi = 0; mi < 4; mi++)
#pragma unroll
                for (int ni = 0; ni < 8; ni++) {
                    const int g = ni >> 1, u = (ni & 1) * 2;
                    MMAF16(acc[mi][ni], ah[ks][mi], rbh[ks][g][u], rbh[ks][g][u + 1]);
                }
    }

    // ---- epilogue ----
    const int er = bm + wm * 64 + (lane >> 2);
    const int ec = bn + wn * 64 + (lane & 3) * 2;

    if (MODE == 0) {
#pragma unroll
        for (int ni = 0; ni < 8; ni++) {
            const int col = ec + ni * 8;
            const float2 bv = *reinterpret_cast<const float2*>(bias + col);
#pragma unroll
            for (int mi = 0; mi < 4; mi++) {
                const int r0 = er + mi * 16;
                float2 o0, o1;
                o0.x = acc[mi][ni][0] + bv.x;
                o0.y = acc[mi][ni][1] + bv.y;
                o1.x = acc[mi][ni][2] + bv.x;
                o1.y = acc[mi][ni][3] + bv.y;
                *reinterpret_cast<float2*>(C + (size_t)r0 * Ntot + col) = o0;
                *reinterpret_cast<float2*>(C + (size_t)(r0 + 8) * Ntot + col) = o1;
            }
        }
    } else {
        // seg 0 = Q (scaled f16); 1 = K (f16); 2 = V (f16)
        const int seg = bn >> 10;
        const int ecl = ec & 1023;
        __half* D = (seg == 0) ? qf : (seg == 1) ? kf : vf;
        const float scale = (seg == 0) ? QSCALE : 1.0f;
#pragma unroll
        for (int ni = 0; ni < 8; ni++) {
            const int col = ec + ni * 8;
            const float2 bv = *reinterpret_cast<const float2*>(bias + col);
            const int cl = ecl + ni * 8;
#pragma unroll
            for (int mi = 0; mi < 4; mi++) {
                const int r0 = er + mi * 16;
                const float v00 = (acc[mi][ni][0] + bv.x) * scale;
                const float v01 = (acc[mi][ni][1] + bv.y) * scale;
                const float v10 = (acc[mi][ni][2] + bv.x) * scale;
                const float v11 = (acc[mi][ni][3] + bv.y) * scale;
                *reinterpret_cast<uint32_t*>(D + (size_t)r0 * 1024 + cl) =
                    packhf(v00, v01);
                *reinterpret_cast<uint32_t*>(D + (size_t)(r0 + 8) * 1024 + cl) =
                    packhf(v10, v11);
            }
        }
    }
}

// ---------------------------------------------------------------------------
// fp32 -> fp16 convert, 4 elems/thread
// ---------------------------------------------------------------------------
__global__ __launch_bounds__(256) void convert_h(
    const float* __restrict__ A, __half* __restrict__ H)
{
    const int i = blockIdx.x * blockDim.x + threadIdx.x;
    const float4 v = reinterpret_cast<const float4*>(A)[i];
    uint2 o;
    o.x = packhf(v.x, v.y);
    o.y = packhf(v.z, v.w);
    *reinterpret_cast<uint2*>(H + (size_t)i * 4) = o;
}

// ---------------------------------------------------------------------------
// Both weight transposes in ONE launch (z selects matrix).
// W[K][N] fp32 -> W^T[N][K] fp16, block (32,8).
// ---------------------------------------------------------------------------
__global__ __launch_bounds__(256) void convert_wT2(
    const float* __restrict__ W0, __half* __restrict__ T0, int N0,
    const float* __restrict__ W1, __half* __restrict__ T1, int N1, int K)
{
    const float* W = blockIdx.z ? W1 : W0;
    __half* T      = blockIdx.z ? T1 : T0;
    const int N    = blockIdx.z ? N1 : N0;
    const int n0 = blockIdx.x * 32;
    if (n0 >= N) return;
    const int k0 = blockIdx.y * 32;

    __shared__ float tile[32][33];
    const int tx = threadIdx.x, ty = threadIdx.y;
#pragma unroll
    for (int i = 0; i < 4; i++)
        tile[ty + i * 8][tx] = W[(size_t)(k0 + ty + i * 8) * N + n0 + tx];
    __syncthreads();
#pragma unroll
    for (int i = 0; i < 4; i++) {
        const float v = tile[tx][ty + i * 8];
        T[(size_t)(n0 + ty + i * 8) * K + k0 + tx] = __float2half_rn(v);
    }
}

// ---------------------------------------------------------------------------
// V transpose (fp16): vf [B*T][1024] -> vt [(b*16+h)*64+dh][1024] (col = t)
// ---------------------------------------------------------------------------
__global__ __launch_bounds__(256) void transpose_v(
    const __half* __restrict__ vf, __half* __restrict__ vt)
{
    __shared__ __half th[32][33];
    const int tx = threadIdx.x, ty = threadIdx.y;
    const int c0 = blockIdx.x * 32;
    const int r0 = blockIdx.y * 32;
#pragma unroll
    for (int i = 0; i < 4; i++) {
        const size_t src = (size_t)(r0 + ty + i * 8) * 1024 + c0 + tx;
        th[ty + i * 8][tx] = vf[src];
    }
    __syncthreads();
    const int b = r0 >> 10;
    const int tbase = (r0 & 1023) + tx;
#pragma unroll
    for (int i = 0; i < 4; i++) {
        const int cp = c0 + ty + i * 8;
        const int hh = cp >> 6, dh = cp & 63;
        const size_t dst = (size_t)(((b * 16 + hh) * 64) + dh) * 1024 + tbase;
        vt[dst] = th[tx][ty + i * 8];
    }
}

// ---------------------------------------------------------------------------
// HMMA flash attention, all single fp16 products:
//   S  = q_f16 x k_f16          (1 product)
//   O += p_f16 x v_f16          (1 product)
// Double-buffered K/V, exp2 softmax. Output single fp16 row-major.
// Grid (4, B*H), 2 passes: q-tiles {7-bx, bx} (BQ=128). 8 warps x 16 rows.
// ---------------------------------------------------------------------------
#define ASTR 144
#define Q_OFF  0             // 18432: Q single fp16 (scaled)
#define K_OFF  18432         // 2 bufs x 9216
#define V_OFF  36864         // 2 bufs x 9216
#define KVB    9216
#define MSK_OFF 55296
#define ATTN_SMEM (55296 + 512)

__global__ __launch_bounds__(256, 2) void attn_hmma(
    const __half* __restrict__ qf, const __half* __restrict__ kf,
    const __half* __restrict__ vt,
    const int* __restrict__ mask,
    __half* __restrict__ ao)
{
    extern __shared__ char smc[];
    const uint32_t sb = smem_to_u32(smc);

    const int t    = threadIdx.x;
    const int lane = t & 31;
    const int w    = t >> 5;
    const int bh   = blockIdx.y;
    const int b    = bh >> 4;
    const int h    = bh & 15;
    float* msk_s = (float*)(smc + MSK_OFF);

    const uint32_t aq_base = sb + Q_OFF +
        (uint32_t)((16 * w + (lane & 15)) * ASTR + (lane >> 4) * 16);
    const uint32_t bk_base = sb + K_OFF +
        (uint32_t)(((lane & 7) + ((lane >> 4) << 3)) * ASTR + ((lane >> 3) & 1) * 16);
    const uint32_t bv_base = sb + V_OFF +
        (uint32_t)(((lane & 7) + ((lane >> 4) << 3)) * ASTR + ((lane >> 3) & 1) * 16);

#pragma unroll 1
    for (int pass = 0; pass < 2; pass++) {
        const int qt = pass ? (int)blockIdx.x : 7 - (int)blockIdx.x;
        __syncthreads();

        // ---- Q tile: 128 rows x 64 fp16 = 1024 chunks ----
#pragma unroll
        for (int p = 0; p < 4; p++) {
            const int idx = t + (p << 8);
            const int row = idx >> 3;
            const int ch  = idx & 7;
            const __half* src = qf +
                (size_t)(b * 1024 + qt * 128 + row) * 1024 + h * 64 + ch * 8;
            CP_ASYNC16(sb + Q_OFF + row * ASTR + ch * 16, src);
        }
        CP_COMMIT();

        const int kmax = 2 * qt + 1;

        // ---- prologue: K/V for kt=0 into buffer 0, mask[0] ----
#pragma unroll
        for (int p = 0; p < 4; p++) {
            const int c   = t + (p << 8);
            const int m   = c >> 9;
            const int idx = c & 511;
            const int row = idx >> 3;
            const int ch  = idx & 7;
            const void* src;
            uint32_t dst;
            if (m == 0) {
                src = kf + (size_t)(b * 1024 + row) * 1024 + h * 64 + ch * 8;
                dst = sb + K_OFF + row * ASTR + ch * 16;
            } else {
                src = vt + (size_t)(bh * 64 + row) * 1024 + ch * 8;
                dst = sb + V_OFF + row * ASTR + ch * 16;
            }
            CP_ASYNC16(dst, src);
        }
        if (t < 64)
            msk_s[t] = (mask[b * TSEQ + t] != 0) ? 0.0f : -1e30f;
        CP_COMMIT();

        float m0 = -1e30f, m1 = -1e30f, l0 = 0.0f, l1 = 0.0f;
        float of[8][4];
#pragma unroll
        for (int j = 0; j < 8; j++)
#pragma unroll
            for (int e = 0; e < 4; e++) of[j][e] = 0.0f;

        const int qrow_w = qt * 128 + 16 * w;
        const int r0g = qrow_w + (lane >> 2);

#pragma unroll 1
        for (int kt = 0; kt <= kmax; kt++) {
            CP_WAIT(0);
            __syncthreads();

            if (kt < kmax) {
                const uint32_t kb = (uint32_t)(((kt + 1) & 1) * KVB);
#pragma unroll
                for (int p = 0; p < 4; p++) {
                    const int c   = t + (p << 8);
                    const int m   = c >> 9;
                    const int idx = c & 511;
                    const int row = idx >> 3;
                    const int ch  = idx & 7;
                    const void* src;
                    uint32_t dst;
                    if (m == 0) {
                        src = kf + (size_t)(b * 1024 + (kt + 1) * 64 + row) * 1024 + h * 64 + ch * 8;
                        dst = sb + K_OFF + kb + row * ASTR + ch * 16;
                    } else {
                        src = vt + (size_t)(bh * 64 + row) * 1024 + (kt + 1) * 64 + ch * 8;
                        dst = sb + V_OFF + kb + row * ASTR + ch * 16;
                    }
                    CP_ASYNC16(dst, src);
                }
                if (t < 64)
                    msk_s[((kt + 1) & 1) * 64 + t] =
                        (mask[b * TSEQ + (kt + 1) * 64 + t] != 0) ? 0.0f : -1e30f;
            }
            CP_COMMIT();

            const uint32_t kb = (uint32_t)((kt & 1) * KVB);
            const float* msk = msk_s + (kt & 1) * 64;

            // ---- S = q @ k^T (1 product) ----
            float s[8][4];
#pragma unroll
            for (int j = 0; j < 8; j++)
#pragma unroll
                for (int e = 0; e < 4; e++) s[j][e] = 0.0f;

#pragma unroll
            for (int ks = 0; ks < 4; ks++) {
                uint32_t aq[4];
                LDSM_X4(aq[0], aq[1], aq[2], aq[3], aq_base + ks * 32);
#pragma unroll
                for (int g = 0; g < 4; g++) {
                    uint32_t bk[4];
                    LDSM_X4(bk[0], bk[1], bk[2], bk[3],
                            bk_base + kb + g * (16 * ASTR) + ks * 32);
                    MMAF16(s[2 * g],     aq, bk[0], bk[1]);
                    MMAF16(s[2 * g + 1], aq, bk[2], bk[3]);
                }
            }

            // ---- mask + causal ----
            const int lc = 2 * (lane & 3);
#pragma unroll
            for (int j = 0; j < 8; j++) {
                const float mj0 = msk[j * 8 + lc];
                const float mj1 = msk[j * 8 + lc + 1];
                s[j][0] += mj0; s[j][1] += mj1;
                s[j][2] += mj0; s[j][3] += mj1;
            }
            if (kt * 64 + 63 > qrow_w) {
                const int r1g = r0g + 8;
#pragma unroll
                for (int j = 0; j < 8; j++) {
                    const int c0 = kt * 64 + j * 8 + lc;
                    if (c0     > r0g) s[j][0] = -1e30f;
                    if (c0 + 1 > r0g) s[j][1] = -1e30f;
                    if (c0     > r1g) s[j][2] = -1e30f;
                    if (c0 + 1 > r1g) s[j][3] = -1e30f;
                }
            }

            // ---- online softmax (exp2 domain) ----
            float rm0 = -1e30f, rm1 = -1e30f;
#pragma unroll
            for (int j = 0; j < 8; j++) {
                rm0 = fmaxf(rm0, fmaxf(s[j][0], s[j][1]));
                rm1 = fmaxf(rm1, fmaxf(s[j][2], s[j][3]));
            }
            rm0 = fmaxf(rm0, __shfl_xor_sync(0xffffffffu, rm0, 1));
            rm0 = fmaxf(rm0, __shfl_xor_sync(0xffffffffu, rm0, 2));
            rm1 = fmaxf(rm1, __shfl_xor_sync(0xffffffffu, rm1, 1));
            rm1 = fmaxf(rm1, __shfl_xor_sync(0xffffffffu, rm1, 2));
            const float mn0 = fmaxf(m0, rm0), mn1 = fmaxf(m1, rm1);
            const float al0 = ex2(m0 - mn0), al1 = ex2(m1 - mn1);
            m0 = mn0; m1 = mn1;
            float ls0 = 0.0f, ls1 = 0.0f;
#pragma unroll
            for (int j = 0; j < 8; j++) {
                s[j][0] = ex2(s[j][0] - mn0); ls0 += s[j][0];
                s[j][1] = ex2(s[j][1] - mn0); ls0 += s[j][1];
                s[j][2] = ex2(s[j][2] - mn1); ls1 += s[j][2];
                s[j][3] = ex2(s[j][3] - mn1); ls1 += s[j][3];
            }
            ls0 += __shfl_xor_sync(0xffffffffu, ls0, 1);
            ls0 += __shfl_xor_sync(0xffffffffu, ls0, 2);
            ls1 += __shfl_xor_sync(0xffffffffu, ls1, 1);
            ls1 += __shfl_xor_sync(0xffffffffu, ls1, 2);
            l0 = l0 * al0 + ls0;
            l1 = l1 * al1 + ls1;
#pragma unroll
            for (int j = 0; j < 8; j++) {
                of[j][0] *= al0; of[j][1] *= al0;
                of[j][2] *= al1; of[j][3] *= al1;
            }

            // ---- O += p_f16 @ v_f16 (1 product) ----
#pragma unroll
            for (int kt2 = 0; kt2 < 4; kt2++) {
                uint32_t ap[4];
                {
                    const float* p0 = s[2 * kt2];
                    const float* p1 = s[2 * kt2 + 1];
                    ap[0] = packhf(p0[0], p0[1]); ap[1] = packhf(p0[2], p0[3]);
                    ap[2] = packhf(p1[0], p1[1]); ap[3] = packhf(p1[2], p1[3]);
                }
#pragma unroll
                for (int g = 0; g < 4; g++) {
                    uint32_t bv[4];
                    LDSM_X4(bv[0], bv[1], bv[2], bv[3],
                            bv_base + kb + g * (16 * ASTR) + kt2 * 32);
                    MMAF16(of[2 * g],     ap, bv[0], bv[1]);
                    MMAF16(of[2 * g + 1], ap, bv[2], bv[3]);
                }
            }
        }

        // ---- normalize + store single fp16 row-major [B*T, D] ----
        const float inv0 = 1.0f / l0, inv1 = 1.0f / l1;
        const size_t obase = ((size_t)(b * TSEQ) + r0g) * DMODEL + h * DHEAD + 2 * (lane & 3);
#pragma unroll
        for (int j = 0; j < 8; j++) {
            *reinterpret_cast<uint32_t*>(ao + obase + j * 8) =
                packhf(of[j][0] * inv0, of[j][1] * inv0);
            *reinterpret_cast<uint32_t*>(ao + obase + (size_t)8 * DMODEL + j * 8) =
                packhf(of[j][2] * inv1, of[j][3] * inv1);
        }
    }
}

// ---------------------------------------------------------------------------
extern "C" void kernel_launch(void* const* d_in, const int* in_sizes, int n_in,
                              void* d_out, int out_size)
{
    const float* x     = (const float*)d_in[0];
    const float* Wqkv  = (const float*)d_in[1];
    const float* bqkv  = (const float*)d_in[2];
    const float* Wproj = (const float*)d_in[3];
    const float* bproj = (const float*)d_in[4];
    const int*   mask  = (const int*)d_in[5];
    float* out = (float*)d_out;

    __half *x16, *wq16, *wp16, *ao16, *qf, *kf, *vf, *vt;
    cudaGetSymbolAddress((void**)&x16,  g_x16);
    cudaGetSymbolAddress((void**)&wq16, g_wq16);
    cudaGetSymbolAddress((void**)&wp16, g_wp16);
    cudaGetSymbolAddress((void**)&ao16, g_ao16);
    cudaGetSymbolAddress((void**)&qf,  g_qf);
    cudaGetSymbolAddress((void**)&kf,  g_kf);
    cudaGetSymbolAddress((void**)&vf,  g_vf);
    cudaGetSymbolAddress((void**)&vt,  g_vt);

    cudaFuncSetAttribute(attn_hmma,
                         cudaFuncAttributeMaxDynamicSharedMemorySize, ATTN_SMEM);
    cudaFuncSetAttribute(gemm_f16<0>,
                         cudaFuncAttributeMaxDynamicSharedMemorySize, GEMM_SMEM);
    cudaFuncSetAttribute(gemm_f16<1>,
                         cudaFuncAttributeMaxDynamicSharedMemorySize, GEMM_SMEM);

    // Convert input and both weights (transposed to [N][K]) to fp16
    convert_h<<<(MROWS * DMODEL) / 1024, 256>>>(x, x16);
    convert_wT2<<<dim3(QKV_N / 32, DMODEL / 32, 2), dim3(32, 8)>>>(
        Wqkv, wq16, QKV_N, Wproj, wp16, DMODEL, DMODEL);

    // 1) QKV GEMM (fp16 single-product) -> Q/K/V single fp16
    gemm_f16<1><<<dim3(QKV_N / 128, MROWS / 128), 128, GEMM_SMEM>>>(
        x16, wq16, bqkv, nullptr, qf, kf, vf, QKV_N);

    // 2) V transpose (fp16, single)
    transpose_v<<<dim3(32, 128), dim3(32, 8)>>>(vf, vt);

    // 3) Fused causal attention (S & PV: single fp16 product)
    attn_hmma<<<dim3(4, BATCH * NH), 256, ATTN_SMEM>>>(
        qf, kf, vt, mask, ao16);

    // 4) out = attn @ Wproj + bproj (fp16 single-product)
    gemm_f16<0><<<dim3(DMODEL / 128, MROWS / 128), 128, GEMM_SMEM>>>(
        ao16, wp16, bproj, out,
        nullptr, nullptr, nullptr, DMODEL);
}

// round 16
// speedup vs baseline: 1.4926x; 1.0396x over previous
#include <cuda_runtime.h>
#include <cuda_bf16.h>
#include <cuda_fp16.h>
#include <math.h>
#include <cstdint>

// Problem constants
#define BATCH 4
#define TSEQ  1024
#define DMODEL 1024
#define NH 16
#define DHEAD 64
#define QKV_N 3072   // 3*DMODEL
#define MROWS 4096   // BATCH*TSEQ
#define KDIM 1024    // K is 1024 for both GEMMs
#define NTK  32      // k-tiles (KDIM/32)

// Q scale: 1/sqrt(64) * log2(e)  (softmax done in exp2 domain)
#define QSCALE (0.125f * 1.44269504088896f)

// ---------------------------------------------------------------------------
// Scratch (device globals: allocation-free)
// ---------------------------------------------------------------------------
__device__ __half g_x16[(size_t)MROWS * DMODEL];         // x fp16 row-major
__device__ __half g_wq16[(size_t)QKV_N * DMODEL];        // Wqkv^T fp16 [N][K]
__device__ __half g_wp16[(size_t)DMODEL * DMODEL];       // Wproj^T fp16 [N][K]
__device__ __half g_ao16[(size_t)MROWS * DMODEL];        // attn out fp16
__device__ __half g_qf[(size_t)MROWS * DMODEL];          // Q scaled, single fp16
__device__ __half g_kf[(size_t)MROWS * DMODEL];          // K single fp16
__device__ __half g_vf[(size_t)MROWS * DMODEL];          // V single fp16

// ---------------------------------------------------------------------------
// PTX helpers (base ISA only — compute_103 virtual arch, no tcgen05)
// ---------------------------------------------------------------------------
__device__ __forceinline__ uint32_t smem_to_u32(const void* p) {
    uint32_t a;
    asm("{ .reg .u64 t; cvta.to.shared.u64 t, %1; cvt.u32.u64 %0, t; }"
        : "=r"(a) : "l"(p));
    return a;
}

#define CP_ASYNC16(smem, gptr) \
    asm volatile("cp.async.cg.shared.global [%0], [%1], 16;" \
        :: "r"(smem), "l"(gptr) : "memory")
#define CP_COMMIT() asm volatile("cp.async.commit_group;" ::: "memory")
#define CP_WAIT(n)  asm volatile("cp.async.wait_group %0;" :: "n"(n) : "memory")

#define LDSM_X4(r0, r1, r2, r3, addr) \
    asm volatile("ldmatrix.sync.aligned.m8n8.x4.shared.b16 {%0,%1,%2,%3}, [%4];" \
        : "=r"(r0), "=r"(r1), "=r"(r2), "=r"(r3) : "r"(addr))

#define LDSM_X4T(r0, r1, r2, r3, addr) \
    asm volatile("ldmatrix.sync.aligned.m8n8.x4.trans.shared.b16 {%0,%1,%2,%3}, [%4];" \
        : "=r"(r0), "=r"(r1), "=r"(r2), "=r"(r3) : "r"(addr))

#define MMAF16(c, a, b0, b1) \
    asm volatile("mma.sync.aligned.m16n8k16.row.col.f32.f16.f16.f32 " \
        "{%0,%1,%2,%3}, {%4,%5,%6,%7}, {%8,%9}, {%0,%1,%2,%3};" \
        : "+f"((c)[0]), "+f"((c)[1]), "+f"((c)[2]), "+f"((c)[3]) \
        : "r"((a)[0]), "r"((a)[1]), "r"((a)[2]), "r"((a)[3]), \
          "r"(b0), "r"(b1))

// pack two floats to f16x2 (lo addr half = first arg)
__device__ __forceinline__ uint32_t packhf(float lo, float hi) {
    uint32_t r;
    asm("cvt.rn.f16x2.f32 %0, %1, %2;" : "=r"(r) : "f"(hi), "f"(lo));
    return r;
}
__device__ __forceinline__ float ex2(float x) {
    float r;
    asm("ex2.approx.f32 %0, %1;" : "=f"(r) : "f"(x));
    return r;
}

// Swizzled byte offset within one 8KB matrix tile (128 rows x 32 fp16):
// row-pair lines of 128B, chunk3 = (r&1)*4 + ch, XOR (r>>1)&7. (verified R7+)
__device__ __forceinline__ uint32_t sw_off(int r, int ch) {
    const uint32_t chunk3 = (uint32_t)(((r & 1) << 2) | ch);
    return (uint32_t)((r >> 1) * 128) + ((chunk3 ^ ((uint32_t)(r >> 1) & 7u)) << 4);
}

// ---------------------------------------------------------------------------
// FP16 single-product HMMA GEMM: C = A[M,K] @ (B[N,K])^T + bias
// CTA 128x128, K-tile 32, 5-stage cp.async (swizzled smem, 16KB/stage),
// 2 CTAs/SM, 4 warps (2x2), warp tile 64x64.
// MODE 0: fp32 C out.  MODE 1: QKV epilogue -> Q f16 / K f16 / V f16
// ---------------------------------------------------------------------------
#define MATB   8192
#define STAGEB 16384
#define NSTAGE 5
#define GEMM_SMEM (NSTAGE * STAGEB)

template <int MODE>
__global__ __launch_bounds__(128, 2) void gemm_f16(
    const __half* __restrict__ A, const __half* __restrict__ B,
    const float* __restrict__ bias, float* __restrict__ C,
    __half* __restrict__ qf, __half* __restrict__ kf,
    __half* __restrict__ vf,
    int Ntot)
{
    extern __shared__ char dsm[];
    const uint32_t sb = smem_to_u32(dsm);

    const int t    = threadIdx.x;
    const int lane = t & 31;
    const int wid  = t >> 5;
    const int wm   = wid >> 1;
    const int wn   = wid & 1;
    const int bm   = blockIdx.y << 7;
    const int bn   = blockIdx.x << 7;

    // cp.async plan: 2 matrices x 512 chunks(16B) / 128 thr = 8/thread
    const int rbase = t >> 2;
    const int ch0   = t & 3;
    uint32_t soff[8];
    const __half* gp[8];
#pragma unroll
    for (int m = 0; m < 2; m++)
#pragma unroll
        for (int hh = 0; hh < 4; hh++) {
            const int r = rbase + hh * 32;
            soff[m * 4 + hh] = (uint32_t)(m * MATB) + sw_off(r, ch0);
            gp[m * 4 + hh]   = (m ? B : A) +
                (size_t)((m ? bn : bm) + r) * KDIM + ch0 * 8;
        }

    const uint32_t a_base = sw_off(wm * 64 + (lane & 15), lane >> 4);
    const uint32_t b_base = (uint32_t)MATB +
        sw_off(wn * 64 + (lane & 7) + ((lane >> 4) << 3), (lane >> 3) & 1);

    float acc[4][8][4];
#pragma unroll
    for (int mi = 0; mi < 4; mi++)
#pragma unroll
        for (int ni = 0; ni < 8; ni++)
#pragma unroll
            for (int e = 0; e < 4; e++) acc[mi][ni][e] = 0.0f;

    // prologue: stages 0..3
#pragma unroll
    for (int s = 0; s < NSTAGE - 1; s++) {
        const uint32_t st = sb + (uint32_t)s * STAGEB;
        const int ko = s * 32;
#pragma unroll
        for (int i = 0; i < 8; i++) CP_ASYNC16(st + soff[i], gp[i] + ko);
        CP_COMMIT();
    }

    int buf = 0, nbuf = NSTAGE - 1;
#pragma unroll 1
    for (int kt = 0; kt < NTK; kt++) {
        CP_WAIT(NSTAGE - 2);
        __syncthreads();

        if (kt + NSTAGE - 1 < NTK) {
            const uint32_t st = sb + (uint32_t)nbuf * STAGEB;
            const int ko = (kt + NSTAGE - 1) * 32;
#pragma unroll
            for (int i = 0; i < 8; i++) CP_ASYNC16(st + soff[i], gp[i] + ko);
        }
        CP_COMMIT();

        const uint32_t stg = sb + (uint32_t)buf * STAGEB;
        buf = (buf == NSTAGE - 1) ? 0 : buf + 1;
        nbuf = (nbuf == NSTAGE - 1) ? 0 : nbuf + 1;

        // ---- hoist ALL fragment loads for the k32 tile ----
        uint32_t ah[2][4][4], rbh[2][4][4];
#pragma unroll
        for (int ks = 0; ks < 2; ks++) {
            const uint32_t ksx = (uint32_t)(ks << 5);
#pragma unroll
            for (int mi = 0; mi < 4; mi++) {
                const uint32_t ao = (a_base + (uint32_t)(mi * 1024)) ^ ksx;
                LDSM_X4(ah[ks][mi][0], ah[ks][mi][1], ah[ks][mi][2], ah[ks][mi][3],
                        stg + ao);
            }
#pragma unroll
            for (int g = 0; g < 4; g++) {
                const uint32_t bo = (b_base + (uint32_t)(g * 1024)) ^ ksx;
                LDSM_X4(rbh[ks][g][0], rbh[ks][g][1], rbh[ks][g][2], rbh[ks][g][3],
                        stg + bo);
            }
        }
        // ---- 64 MMAs ----
#pragma unroll
        for (int ks = 0; ks < 2; ks++)
#pragma unroll
            for (int mi = 0; mi < 4; mi++)
#pragma unroll
                for (int ni = 0; ni < 8; ni++) {
                    const int g = ni >> 1, u = (ni & 1) * 2;
                    MMAF16(acc[mi][ni], ah[ks][mi], rbh[ks][g][u], rbh[ks][g][u + 1]);
                }
    }

    // ---- epilogue ----
    const int er = bm + wm * 64 + (lane >> 2);
    const int ec = bn + wn * 64 + (lane & 3) * 2;

    if (MODE == 0) {
#pragma unroll
        for (int ni = 0; ni < 8; ni++) {
            const int col = ec + ni * 8;
            const float2 bv = *reinterpret_cast<const float2*>(bias + col);
#pragma unroll
            for (int mi = 0; mi < 4; mi++) {
                const int r0 = er + mi * 16;
                float2 o0, o1;
                o0.x = acc[mi][ni][0] + bv.x;
                o0.y = acc[mi][ni][1] + bv.y;
                o1.x = acc[mi][ni][2] + bv.x;
                o1.y = acc[mi][ni][3] + bv.y;
                *reinterpret_cast<float2*>(C + (size_t)r0 * Ntot + col) = o0;
                *reinterpret_cast<float2*>(C + (size_t)(r0 + 8) * Ntot + col) = o1;
            }
        }
    } else {
        // seg 0 = Q (scaled f16); 1 = K (f16); 2 = V (f16)
        const int seg = bn >> 10;
        const int ecl = ec & 1023;
        __half* D = (seg == 0) ? qf : (seg == 1) ? kf : vf;
        const float scale = (seg == 0) ? QSCALE : 1.0f;
#pragma unroll
        for (int ni = 0; ni < 8; ni++) {
            const int col = ec + ni * 8;
            const float2 bv = *reinterpret_cast<const float2*>(bias + col);
            const int cl = ecl + ni * 8;
#pragma unroll
            for (int mi = 0; mi < 4; mi++) {
                const int r0 = er + mi * 16;
                const float v00 = (acc[mi][ni][0] + bv.x) * scale;
                const float v01 = (acc[mi][ni][1] + bv.y) * scale;
                const float v10 = (acc[mi][ni][2] + bv.x) * scale;
                const float v11 = (acc[mi][ni][3] + bv.y) * scale;
                *reinterpret_cast<uint32_t*>(D + (size_t)r0 * 1024 + cl) =
                    packhf(v00, v01);
                *reinterpret_cast<uint32_t*>(D + (size_t)(r0 + 8) * 1024 + cl) =
                    packhf(v10, v11);
            }
        }
    }
}

// ---------------------------------------------------------------------------
// fp32 -> fp16 convert, 4 elems/thread
// ---------------------------------------------------------------------------
__global__ __launch_bounds__(256) void convert_h(
    const float* __restrict__ A, __half* __restrict__ H)
{
    const int i = blockIdx.x * blockDim.x + threadIdx.x;
    const float4 v = reinterpret_cast<const float4*>(A)[i];
    uint2 o;
    o.x = packhf(v.x, v.y);
    o.y = packhf(v.z, v.w);
    *reinterpret_cast<uint2*>(H + (size_t)i * 4) = o;
}

// ---------------------------------------------------------------------------
// Both weight transposes in ONE launch (z selects matrix).
// W[K][N] fp32 -> W^T[N][K] fp16, block (32,8).
// ---------------------------------------------------------------------------
__global__ __launch_bounds__(256) void convert_wT2(
    const float* __restrict__ W0, __half* __restrict__ T0, int N0,
    const float* __restrict__ W1, __half* __restrict__ T1, int N1, int K)
{
    const float* W = blockIdx.z ? W1 : W0;
    __half* T      = blockIdx.z ? T1 : T0;
    const int N    = blockIdx.z ? N1 : N0;
    const int n0 = blockIdx.x * 32;
    if (n0 >= N) return;
    const int k0 = blockIdx.y * 32;

    __shared__ float tile[32][33];
    const int tx = threadIdx.x, ty = threadIdx.y;
#pragma unroll
    for (int i = 0; i < 4; i++)
        tile[ty + i * 8][tx] = W[(size_t)(k0 + ty + i * 8) * N + n0 + tx];
    __syncthreads();
#pragma unroll
    for (int i = 0; i < 4; i++) {
        const float v = tile[tx][ty + i * 8];
        T[(size_t)(n0 + ty + i * 8) * K + k0 + tx] = __float2half_rn(v);
    }
}

// ---------------------------------------------------------------------------
// HMMA flash attention, all single fp16 products:
//   S  = q_f16 x k_f16          (1 product)
//   O += p_f16 x v_f16          (1 product, V loaded via ldmatrix.trans —
//                                no pre-transposed V buffer needed)
// Double-buffered K/V, exp2 softmax. Output single fp16 row-major.
// Grid (4, B*H), 2 passes: q-tiles {7-bx, bx} (BQ=128). 8 warps x 16 rows.
// ---------------------------------------------------------------------------
#define ASTR 144
#define Q_OFF  0             // 18432: Q single fp16 (scaled)
#define K_OFF  18432         // 2 bufs x 9216
#define V_OFF  36864         // 2 bufs x 9216 (V row-major [key][dh])
#define KVB    9216
#define MSK_OFF 55296
#define ATTN_SMEM (55296 + 512)

__global__ __launch_bounds__(256, 2) void attn_hmma(
    const __half* __restrict__ qf, const __half* __restrict__ kf,
    const __half* __restrict__ vf,
    const int* __restrict__ mask,
    __half* __restrict__ ao)
{
    extern __shared__ char smc[];
    const uint32_t sb = smem_to_u32(smc);

    const int t    = threadIdx.x;
    const int lane = t & 31;
    const int w    = t >> 5;
    const int bh   = blockIdx.y;
    const int b    = bh >> 4;
    const int h    = bh & 15;
    float* msk_s = (float*)(smc + MSK_OFF);

    const uint32_t aq_base = sb + Q_OFF +
        (uint32_t)((16 * w + (lane & 15)) * ASTR + (lane >> 4) * 16);
    const uint32_t bk_base = sb + K_OFF +
        (uint32_t)(((lane & 7) + ((lane >> 4) << 3)) * ASTR + ((lane >> 3) & 1) * 16);
    // trans-ldmatrix base for V [key][dh]:
    // lanes 0-7: keys r0..r0+7 @ dh-chunk c; 8-15: keys+8 @ c;
    // 16-23: keys @ c+16B; 24-31: keys+8 @ c+16B
    const uint32_t bv_base = sb + V_OFF +
        (uint32_t)((lane & 7) * ASTR + ((lane >> 3) & 1) * (8 * ASTR) +
                   (lane >> 4) * 16);

#pragma unroll 1
    for (int pass = 0; pass < 2; pass++) {
        const int qt = pass ? (int)blockIdx.x : 7 - (int)blockIdx.x;
        __syncthreads();

        // ---- Q tile: 128 rows x 64 fp16 = 1024 chunks ----
#pragma unroll
        for (int p = 0; p < 4; p++) {
            const int idx = t + (p << 8);
            const int row = idx >> 3;
            const int ch  = idx & 7;
            const __half* src = qf +
                (size_t)(b * 1024 + qt * 128 + row) * 1024 + h * 64 + ch * 8;
            CP_ASYNC16(sb + Q_OFF + row * ASTR + ch * 16, src);
        }
        CP_COMMIT();

        const int kmax = 2 * qt + 1;

        // ---- prologue: K/V for kt=0 into buffer 0, mask[0] ----
        // 1024 chunks: m = 0:K (512), 1:V (512); identical row-major source
#pragma unroll
        for (int p = 0; p < 4; p++) {
            const int c   = t + (p << 8);
            const int m   = c >> 9;
            const int idx = c & 511;
            const int row = idx >> 3;
            const int ch  = idx & 7;
            const __half* base = m ? vf : kf;
            const uint32_t doff = m ? (uint32_t)V_OFF : (uint32_t)K_OFF;
            CP_ASYNC16(sb + doff + row * ASTR + ch * 16,
                       base + (size_t)(b * 1024 + row) * 1024 + h * 64 + ch * 8);
        }
        if (t < 64)
            msk_s[t] = (mask[b * TSEQ + t] != 0) ? 0.0f : -1e30f;
        CP_COMMIT();

        float m0 = -1e30f, m1 = -1e30f, l0 = 0.0f, l1 = 0.0f;
        float of[8][4];
#pragma unroll
        for (int j = 0; j < 8; j++)
#pragma unroll
            for (int e = 0; e < 4; e++) of[j][e] = 0.0f;

        const int qrow_w = qt * 128 + 16 * w;
        const int r0g = qrow_w + (lane >> 2);

#pragma unroll 1
        for (int kt = 0; kt <= kmax; kt++) {
            CP_WAIT(0);
            __syncthreads();

            if (kt < kmax) {
                const uint32_t kb = (uint32_t)(((kt + 1) & 1) * KVB);
#pragma unroll
                for (int p = 0; p < 4; p++) {
                    const int c   = t + (p << 8);
                    const int m   = c >> 9;
                    const int idx = c & 511;
                    const int row = idx >> 3;
                    const int ch  = idx & 7;
                    const __half* base = m ? vf : kf;
                    const uint32_t doff = m ? (uint32_t)V_OFF : (uint32_t)K_OFF;
                    CP_ASYNC16(sb + doff + kb + row * ASTR + ch * 16,
                               base + (size_t)(b * 1024 + (kt + 1) * 64 + row) * 1024 +
                                   h * 64 + ch * 8);
                }
                if (t < 64)
                    msk_s[((kt + 1) & 1) * 64 + t] =
                        (mask[b * TSEQ + (kt + 1) * 64 + t] != 0) ? 0.0f : -1e30f;
            }
            CP_COMMIT();

            const uint32_t kb = (uint32_t)((kt & 1) * KVB);
            const float* msk = msk_s + (kt & 1) * 64;

            // ---- S = q @ k^T (1 product) ----
            float s[8][4];
#pragma unroll
            for (int j = 0; j < 8; j++)
#pragma unroll
                for (int e = 0; e < 4; e++) s[j][e] = 0.0f;

#pragma unroll
            for (int ks = 0; ks < 4; ks++) {
                uint32_t aq[4];
                LDSM_X4(aq[0], aq[1], aq[2], aq[3], aq_base + ks * 32);
#pragma unroll
                for (int g = 0; g < 4; g++) {
                    uint32_t bk[4];
                    LDSM_X4(bk[0], bk[1], bk[2], bk[3],
                            bk_base + kb + g * (16 * ASTR) + ks * 32);
                    MMAF16(s[2 * g],     aq, bk[0], bk[1]);
                    MMAF16(s[2 * g + 1], aq, bk[2], bk[3]);
                }
            }

            // ---- mask + causal ----
            const int lc = 2 * (lane & 3);
#pragma unroll
            for (int j = 0; j < 8; j++) {
                const float mj0 = msk[j * 8 + lc];
                const float mj1 = msk[j * 8 + lc + 1];
                s[j][0] += mj0; s[j][1] += mj1;
                s[j][2] += mj0; s[j][3] += mj1;
            }
            if (kt * 64 + 63 > qrow_w) {
                const int r1g = r0g + 8;
#pragma unroll
                for (int j = 0; j < 8; j++) {
                    const int c0 = kt * 64 + j * 8 + lc;
                    if (c0     > r0g) s[j][0] = -1e30f;
                    if (c0 + 1 > r0g) s[j][1] = -1e30f;
                    if (c0     > r1g) s[j][2] = -1e30f;
                    if (c0 + 1 > r1g) s[j][3] = -1e30f;
                }
            }

            // ---- online softmax (exp2 domain) ----
            float rm0 = -1e30f, rm1 = -1e30f;
#pragma unroll
            for (int j = 0; j < 8; j++) {
                rm0 = fmaxf(rm0, fmaxf(s[j][0], s[j][1]));
                rm1 = fmaxf(rm1, fmaxf(s[j][2], s[j][3]));
            }
            rm0 = fmaxf(rm0, __shfl_xor_sync(0xffffffffu, rm0, 1));
            rm0 = fmaxf(rm0, __shfl_xor_sync(0xffffffffu, rm0, 2));
            rm1 = fmaxf(rm1, __shfl_xor_sync(0xffffffffu, rm1, 1));
            rm1 = fmaxf(rm1, __shfl_xor_sync(0xffffffffu, rm1, 2));
            const float mn0 = fmaxf(m0, rm0), mn1 = fmaxf(m1, rm1);
            const float al0 = ex2(m0 - mn0), al1 = ex2(m1 - mn1);
            m0 = mn0; m1 = mn1;
            float ls0 = 0.0f, ls1 = 0.0f;
#pragma unroll
            for (int j = 0; j < 8; j++) {
                s[j][0] = ex2(s[j][0] - mn0); ls0 += s[j][0];
                s[j][1] = ex2(s[j][1] - mn0); ls0 += s[j][1];
                s[j][2] = ex2(s[j][2] - mn1); ls1 += s[j][2];
                s[j][3] = ex2(s[j][3] - mn1); ls1 += s[j][3];
            }
            ls0 += __shfl_xor_sync(0xffffffffu, ls0, 1);
            ls0 += __shfl_xor_sync(0xffffffffu, ls0, 2);
            ls1 += __shfl_xor_sync(0xffffffffu, ls1, 1);
            ls1 += __shfl_xor_sync(0xffffffffu, ls1, 2);
            l0 = l0 * al0 + ls0;
            l1 = l1 * al1 + ls1;
#pragma unroll
            for (int j = 0; j < 8; j++) {
                of[j][0] *= al0; of[j][1] *= al0;
                of[j][2] *= al1; of[j][3] *= al1;
            }

            // ---- O += p_f16 @ v_f16 (trans-ldmatrix B fragments) ----
#pragma unroll
            for (int kt2 = 0; kt2 < 4; kt2++) {
                uint32_t ap[4];
                {
                    const float* p0 = s[2 * kt2];
                    const float* p1 = s[2 * kt2 + 1];
                    ap[0] = packhf(p0[0], p0[1]); ap[1] = packhf(p0[2], p0[3]);
                    ap[2] = packhf(p1[0], p1[1]); ap[3] = packhf(p1[2], p1[3]);
                }
#pragma unroll
                for (int g = 0; g < 4; g++) {
                    uint32_t bv[4];
                    LDSM_X4T(bv[0], bv[1], bv[2], bv[3],
                             bv_base + kb + (uint32_t)(kt2 * (16 * ASTR) + g * 32));
                    MMAF16(of[2 * g],     ap, bv[0], bv[1]);
                    MMAF16(of[2 * g + 1], ap, bv[2], bv[3]);
                }
            }
        }

        // ---- normalize + store single fp16 row-major [B*T, D] ----
        const float inv0 = 1.0f / l0, inv1 = 1.0f / l1;
        const size_t obase = ((size_t)(b * TSEQ) + r0g) * DMODEL + h * DHEAD + 2 * (lane & 3);
#pragma unroll
        for (int j = 0; j < 8; j++) {
            *reinterpret_cast<uint32_t*>(ao + obase + j * 8) =
                packhf(of[j][0] * inv0, of[j][1] * inv0);
            *reinterpret_cast<uint32_t*>(ao + obase + (size_t)8 * DMODEL + j * 8) =
                packhf(of[j][2] * inv1, of[j][3] * inv1);
        }
    }
}

// ---------------------------------------------------------------------------
extern "C" void kernel_launch(void* const* d_in, const int* in_sizes, int n_in,
                              void* d_out, int out_size)
{
    const float* x     = (const float*)d_in[0];
    const float* Wqkv  = (const float*)d_in[1];
    const float* bqkv  = (const float*)d_in[2];
    const float* Wproj = (const float*)d_in[3];
    const float* bproj = (const float*)d_in[4];
    const int*   mask  = (const int*)d_in[5];
    float* out = (float*)d_out;

    __half *x16, *wq16, *wp16, *ao16, *qf, *kf, *vf;
    cudaGetSymbolAddress((void**)&x16,  g_x16);
    cudaGetSymbolAddress((void**)&wq16, g_wq16);
    cudaGetSymbolAddress((void**)&wp16, g_wp16);
    cudaGetSymbolAddress((void**)&ao16, g_ao16);
    cudaGetSymbolAddress((void**)&qf,  g_qf);
    cudaGetSymbolAddress((void**)&kf,  g_kf);
    cudaGetSymbolAddress((void**)&vf,  g_vf);

    cudaFuncSetAttribute(attn_hmma,
                         cudaFuncAttributeMaxDynamicSharedMemorySize, ATTN_SMEM);
    cudaFuncSetAttribute(gemm_f16<0>,
                         cudaFuncAttributeMaxDynamicSharedMemorySize, GEMM_SMEM);
    cudaFuncSetAttribute(gemm_f16<1>,
                         cudaFuncAttributeMaxDynamicSharedMemorySize, GEMM_SMEM);

    // Convert input and both weights (transposed to [N][K]) to fp16
    convert_h<<<(MROWS * DMODEL) / 1024, 256>>>(x, x16);
    convert_wT2<<<dim3(QKV_N / 32, DMODEL / 32, 2), dim3(32, 8)>>>(
        Wqkv, wq16, QKV_N, Wproj, wp16, DMODEL, DMODEL);

    // 1) QKV GEMM (fp16 single-product) -> Q/K/V single fp16
    gemm_f16<1><<<dim3(QKV_N / 128, MROWS / 128), 128, GEMM_SMEM>>>(
        x16, wq16, bqkv, nullptr, qf, kf, vf, QKV_N);

    // 2) Fused causal attention (V transposed in-register via ldmatrix.trans)
    attn_hmma<<<dim3(4, BATCH * NH), 256, ATTN_SMEM>>>(
        qf, kf, vf, mask, ao16);

    // 3) out = attn @ Wproj + bproj (fp16 single-product)
    gemm_f16<0><<<dim3(DMODEL / 128, MROWS / 128), 128, GEMM_SMEM>>>(
        ao16, wp16, bproj, out,
        nullptr, nullptr, nullptr, DMODEL);
}

// round 17
// speedup vs baseline: 1.5064x; 1.0092x over previous
#include <cuda_runtime.h>
#include <cuda_bf16.h>
#include <cuda_fp16.h>
#include <math.h>
#include <cstdint>

// Problem constants
#define BATCH 4
#define TSEQ  1024
#define DMODEL 1024
#define NH 16
#define DHEAD 64
#define QKV_N 3072   // 3*DMODEL
#define MROWS 4096   // BATCH*TSEQ
#define KDIM 1024    // K is 1024 for both GEMMs
#define NTK  32      // k-tiles (KDIM/32)

// Q scale: 1/sqrt(64) * log2(e)  (softmax done in exp2 domain)
#define QSCALE (0.125f * 1.44269504088896f)

// ---------------------------------------------------------------------------
// Scratch (device globals: allocation-free)
// ---------------------------------------------------------------------------
__device__ __half g_x16[(size_t)MROWS * DMODEL];         // x fp16 row-major
__device__ __half g_wq16[(size_t)QKV_N * DMODEL];        // Wqkv^T fp16 [N][K]
__device__ __half g_wp16[(size_t)DMODEL * DMODEL];       // Wproj^T fp16 [N][K]
__device__ __half g_ao16[(size_t)MROWS * DMODEL];        // attn out fp16
__device__ __half g_qf[(size_t)MROWS * DMODEL];          // Q scaled, single fp16
__device__ __half g_kf[(size_t)MROWS * DMODEL];          // K single fp16
__device__ __half g_vf[(size_t)MROWS * DMODEL];          // V single fp16

// ---------------------------------------------------------------------------
// PTX helpers (base ISA only — compute_103 virtual arch, no tcgen05)
// ---------------------------------------------------------------------------
__device__ __forceinline__ uint32_t smem_to_u32(const void* p) {
    uint32_t a;
    asm("{ .reg .u64 t; cvta.to.shared.u64 t, %1; cvt.u32.u64 %0, t; }"
        : "=r"(a) : "l"(p));
    return a;
}

#define CP_ASYNC16(smem, gptr) \
    asm volatile("cp.async.cg.shared.global [%0], [%1], 16;" \
        :: "r"(smem), "l"(gptr) : "memory")
#define CP_COMMIT() asm volatile("cp.async.commit_group;" ::: "memory")
#define CP_WAIT(n)  asm volatile("cp.async.wait_group %0;" :: "n"(n) : "memory")

#define LDSM_X4(r0, r1, r2, r3, addr) \
    asm volatile("ldmatrix.sync.aligned.m8n8.x4.shared.b16 {%0,%1,%2,%3}, [%4];" \
        : "=r"(r0), "=r"(r1), "=r"(r2), "=r"(r3) : "r"(addr))

#define LDSM_X4T(r0, r1, r2, r3, addr) \
    asm volatile("ldmatrix.sync.aligned.m8n8.x4.trans.shared.b16 {%0,%1,%2,%3}, [%4];" \
        : "=r"(r0), "=r"(r1), "=r"(r2), "=r"(r3) : "r"(addr))

#define MMAF16(c, a, b0, b1) \
    asm volatile("mma.sync.aligned.m16n8k16.row.col.f32.f16.f16.f32 " \
        "{%0,%1,%2,%3}, {%4,%5,%6,%7}, {%8,%9}, {%0,%1,%2,%3};" \
        : "+f"((c)[0]), "+f"((c)[1]), "+f"((c)[2]), "+f"((c)[3]) \
        : "r"((a)[0]), "r"((a)[1]), "r"((a)[2]), "r"((a)[3]), \
          "r"(b0), "r"(b1))

// pack two floats to f16x2 (lo addr half = first arg)
__device__ __forceinline__ uint32_t packhf(float lo, float hi) {
    uint32_t r;
    asm("cvt.rn.f16x2.f32 %0, %1, %2;" : "=r"(r) : "f"(hi), "f"(lo));
    return r;
}
__device__ __forceinline__ float ex2(float x) {
    float r;
    asm("ex2.approx.f32 %0, %1;" : "=f"(r) : "f"(x));
    return r;
}

// Swizzled byte offset within one 8KB matrix tile (128 rows x 32 fp16):
// row-pair lines of 128B, chunk3 = (r&1)*4 + ch, XOR (r>>1)&7. (verified R7+)
__device__ __forceinline__ uint32_t sw_off(int r, int ch) {
    const uint32_t chunk3 = (uint32_t)(((r & 1) << 2) | ch);
    return (uint32_t)((r >> 1) * 128) + ((chunk3 ^ ((uint32_t)(r >> 1) & 7u)) << 4);
}

// ---------------------------------------------------------------------------
// FP16 single-product HMMA GEMM: C = A[M,K] @ (B[N,K])^T + bias
// CTA 128x128, K-tile 32, 5-stage cp.async (swizzled smem, 16KB/stage),
// 2 CTAs/SM, 4 warps (2x2), warp tile 64x64.
// MODE 0: fp32 C out.  MODE 1: QKV epilogue -> Q f16 / K f16 / V f16
// ---------------------------------------------------------------------------
#define MATB   8192
#define STAGEB 16384
#define NSTAGE 5
#define GEMM_SMEM (NSTAGE * STAGEB)

template <int MODE>
__global__ __launch_bounds__(128, 2) void gemm_f16(
    const __half* __restrict__ A, const __half* __restrict__ B,
    const float* __restrict__ bias, float* __restrict__ C,
    __half* __restrict__ qf, __half* __restrict__ kf,
    __half* __restrict__ vf,
    int Ntot)
{
    extern __shared__ char dsm[];
    const uint32_t sb = smem_to_u32(dsm);

    const int t    = threadIdx.x;
    const int lane = t & 31;
    const int wid  = t >> 5;
    const int wm   = wid >> 1;
    const int wn   = wid & 1;
    const int bm   = blockIdx.y << 7;
    const int bn   = blockIdx.x << 7;

    // cp.async plan: 2 matrices x 512 chunks(16B) / 128 thr = 8/thread
    const int rbase = t >> 2;
    const int ch0   = t & 3;
    uint32_t soff[8];
    const __half* gp[8];
#pragma unroll
    for (int m = 0; m < 2; m++)
#pragma unroll
        for (int hh = 0; hh < 4; hh++) {
            const int r = rbase + hh * 32;
            soff[m * 4 + hh] = (uint32_t)(m * MATB) + sw_off(r, ch0);
            gp[m * 4 + hh]   = (m ? B : A) +
                (size_t)((m ? bn : bm) + r) * KDIM + ch0 * 8;
        }

    const uint32_t a_base = sw_off(wm * 64 + (lane & 15), lane >> 4);
    const uint32_t b_base = (uint32_t)MATB +
        sw_off(wn * 64 + (lane & 7) + ((lane >> 4) << 3), (lane >> 3) & 1);

    float acc[4][8][4];
#pragma unroll
    for (int mi = 0; mi < 4; mi++)
#pragma unroll
        for (int ni = 0; ni < 8; ni++)
#pragma unroll
            for (int e = 0; e < 4; e++) acc[mi][ni][e] = 0.0f;

    // prologue: stages 0..3
#pragma unroll
    for (int s = 0; s < NSTAGE - 1; s++) {
        const uint32_t st = sb + (uint32_t)s * STAGEB;
        const int ko = s * 32;
#pragma unroll
        for (int i = 0; i < 8; i++) CP_ASYNC16(st + soff[i], gp[i] + ko);
        CP_COMMIT();
    }

    int buf = 0, nbuf = NSTAGE - 1;
#pragma unroll 1
    for (int kt = 0; kt < NTK; kt++) {
        CP_WAIT(NSTAGE - 2);
        __syncthreads();

        if (kt + NSTAGE - 1 < NTK) {
            const uint32_t st = sb + (uint32_t)nbuf * STAGEB;
            const int ko = (kt + NSTAGE - 1) * 32;
#pragma unroll
            for (int i = 0; i < 8; i++) CP_ASYNC16(st + soff[i], gp[i] + ko);
        }
        CP_COMMIT();

        const uint32_t stg = sb + (uint32_t)buf * STAGEB;
        buf = (buf == NSTAGE - 1) ? 0 : buf + 1;
        nbuf = (nbuf == NSTAGE - 1) ? 0 : nbuf + 1;

        // ---- hoist ALL fragment loads for the k32 tile ----
        uint32_t ah[2][4][4], rbh[2][4][4];
#pragma unroll
        for (int ks = 0; ks < 2; ks++) {
            const uint32_t ksx = (uint32_t)(ks << 5);
#pragma unroll
            for (int mi = 0; mi < 4; mi++) {
                const uint32_t ao = (a_base + (uint32_t)(mi * 1024)) ^ ksx;
                LDSM_X4(ah[ks][mi][0], ah[ks][mi][1], ah[ks][mi][2], ah[ks][mi][3],
                        stg + ao);
            }
#pragma unroll
            for (int g = 0; g < 4; g++) {
                const uint32_t bo = (b_base + (uint32_t)(g * 1024)) ^ ksx;
                LDSM_X4(rbh[ks][g][0], rbh[ks][g][1], rbh[ks][g][2], rbh[ks][g][3],
                        stg + bo);
            }
        }
        // ---- 64 MMAs ----
#pragma unroll
        for (int ks = 0; ks < 2; ks++)
#pragma unroll
            for (int mi = 0; mi < 4; mi++)
#pragma unroll
                for (int ni = 0; ni < 8; ni++) {
                    const int g = ni >> 1, u = (ni & 1) * 2;
                    MMAF16(acc[mi][ni], ah[ks][mi], rbh[ks][g][u], rbh[ks][g][u + 1]);
                }
    }

    // ---- epilogue ----
    const int er = bm + wm * 64 + (lane >> 2);
    const int ec = bn + wn * 64 + (lane & 3) * 2;

    if (MODE == 0) {
#pragma unroll
        for (int ni = 0; ni < 8; ni++) {
            const int col = ec + ni * 8;
            const float2 bv = *reinterpret_cast<const float2*>(bias + col);
#pragma unroll
            for (int mi = 0; mi < 4; mi++) {
                const int r0 = er + mi * 16;
                float2 o0, o1;
                o0.x = acc[mi][ni][0] + bv.x;
                o0.y = acc[mi][ni][1] + bv.y;
                o1.x = acc[mi][ni][2] + bv.x;
                o1.y = acc[mi][ni][3] + bv.y;
                *reinterpret_cast<float2*>(C + (size_t)r0 * Ntot + col) = o0;
                *reinterpret_cast<float2*>(C + (size_t)(r0 + 8) * Ntot + col) = o1;
            }
        }
    } else {
        // seg 0 = Q (scaled f16); 1 = K (f16); 2 = V (f16)
        const int seg = bn >> 10;
        const int ecl = ec & 1023;
        __half* D = (seg == 0) ? qf : (seg == 1) ? kf : vf;
        const float scale = (seg == 0) ? QSCALE : 1.0f;
#pragma unroll
        for (int ni = 0; ni < 8; ni++) {
            const int col = ec + ni * 8;
            const float2 bv = *reinterpret_cast<const float2*>(bias + col);
            const int cl = ecl + ni * 8;
#pragma unroll
            for (int mi = 0; mi < 4; mi++) {
                const int r0 = er + mi * 16;
                const float v00 = (acc[mi][ni][0] + bv.x) * scale;
                const float v01 = (acc[mi][ni][1] + bv.y) * scale;
                const float v10 = (acc[mi][ni][2] + bv.x) * scale;
                const float v11 = (acc[mi][ni][3] + bv.y) * scale;
                *reinterpret_cast<uint32_t*>(D + (size_t)r0 * 1024 + cl) =
                    packhf(v00, v01);
                *reinterpret_cast<uint32_t*>(D + (size_t)(r0 + 8) * 1024 + cl) =
                    packhf(v10, v11);
            }
        }
    }
}

// ---------------------------------------------------------------------------
// fp32 -> fp16 convert, 4 elems/thread
// ---------------------------------------------------------------------------
__global__ __launch_bounds__(256) void convert_h(
    const float* __restrict__ A, __half* __restrict__ H)
{
    const int i = blockIdx.x * blockDim.x + threadIdx.x;
    const float4 v = reinterpret_cast<const float4*>(A)[i];
    uint2 o;
    o.x = packhf(v.x, v.y);
    o.y = packhf(v.z, v.w);
    *reinterpret_cast<uint2*>(H + (size_t)i * 4) = o;
}

// ---------------------------------------------------------------------------
// Both weight transposes in ONE launch (z selects matrix).
// W[K][N] fp32 -> W^T[N][K] fp16, block (32,8).
// ---------------------------------------------------------------------------
__global__ __launch_bounds__(256) void convert_wT2(
    const float* __restrict__ W0, __half* __restrict__ T0, int N0,
    const float* __restrict__ W1, __half* __restrict__ T1, int N1, int K)
{
    const float* W = blockIdx.z ? W1 : W0;
    __half* T      = blockIdx.z ? T1 : T0;
    const int N    = blockIdx.z ? N1 : N0;
    const int n0 = blockIdx.x * 32;
    if (n0 >= N) return;
    const int k0 = blockIdx.y * 32;

    __shared__ float tile[32][33];
    const int tx = threadIdx.x, ty = threadIdx.y;
#pragma unroll
    for (int i = 0; i < 4; i++)
        tile[ty + i * 8][tx] = W[(size_t)(k0 + ty + i * 8) * N + n0 + tx];
    __syncthreads();
#pragma unroll
    for (int i = 0; i < 4; i++) {
        const float v = tile[tx][ty + i * 8];
        T[(size_t)(n0 + ty + i * 8) * K + k0 + tx] = __float2half_rn(v);
    }
}

// ---------------------------------------------------------------------------
// HMMA flash attention, all single fp16 products; V via ldmatrix.trans.
// Softmax: exp2 domain; all-ones-mask fast path via __syncthreads_and;
// l accumulated lane-locally (alpha is quad-uniform), reduced once at end.
// Grid (4, B*H), 2 passes: q-tiles {7-bx, bx} (BQ=128). 8 warps x 16 rows.
// ---------------------------------------------------------------------------
#define ASTR 144
#define Q_OFF  0             // 18432: Q single fp16 (scaled)
#define K_OFF  18432         // 2 bufs x 9216
#define V_OFF  36864         // 2 bufs x 9216 (V row-major [key][dh])
#define KVB    9216
#define MSK_OFF 55296
#define ATTN_SMEM (55296 + 512)

__global__ __launch_bounds__(256, 2) void attn_hmma(
    const __half* __restrict__ qf, const __half* __restrict__ kf,
    const __half* __restrict__ vf,
    const int* __restrict__ mask,
    __half* __restrict__ ao)
{
    extern __shared__ char smc[];
    const uint32_t sb = smem_to_u32(smc);

    const int t    = threadIdx.x;
    const int lane = t & 31;
    const int w    = t >> 5;
    const int bh   = blockIdx.y;
    const int b    = bh >> 4;
    const int h    = bh & 15;
    float* msk_s = (float*)(smc + MSK_OFF);

    const uint32_t aq_base = sb + Q_OFF +
        (uint32_t)((16 * w + (lane & 15)) * ASTR + (lane >> 4) * 16);
    const uint32_t bk_base = sb + K_OFF +
        (uint32_t)(((lane & 7) + ((lane >> 4) << 3)) * ASTR + ((lane >> 3) & 1) * 16);
    const uint32_t bv_base = sb + V_OFF +
        (uint32_t)((lane & 7) * ASTR + ((lane >> 3) & 1) * (8 * ASTR) +
                   (lane >> 4) * 16);

#pragma unroll 1
    for (int pass = 0; pass < 2; pass++) {
        const int qt = pass ? (int)blockIdx.x : 7 - (int)blockIdx.x;
        __syncthreads();

        // ---- Q tile: 128 rows x 64 fp16 = 1024 chunks ----
#pragma unroll
        for (int p = 0; p < 4; p++) {
            const int idx = t + (p << 8);
            const int row = idx >> 3;
            const int ch  = idx & 7;
            const __half* src = qf +
                (size_t)(b * 1024 + qt * 128 + row) * 1024 + h * 64 + ch * 8;
            CP_ASYNC16(sb + Q_OFF + row * ASTR + ch * 16, src);
        }
        CP_COMMIT();

        const int kmax = 2 * qt + 1;

        // ---- prologue: K/V for kt=0 into buffer 0, mask[0] ----
        int nextok = 1;
#pragma unroll
        for (int p = 0; p < 4; p++) {
            const int c   = t + (p << 8);
            const int m   = c >> 9;
            const int idx = c & 511;
            const int row = idx >> 3;
            const int ch  = idx & 7;
            const __half* base = m ? vf : kf;
            const uint32_t doff = m ? (uint32_t)V_OFF : (uint32_t)K_OFF;
            CP_ASYNC16(sb + doff + row * ASTR + ch * 16,
                       base + (size_t)(b * 1024 + row) * 1024 + h * 64 + ch * 8);
        }
        if (t < 64) {
            const int mv = mask[b * TSEQ + t];
            msk_s[t] = mv ? 0.0f : -1e30f;
            nextok = (mv != 0);
        }
        CP_COMMIT();

        float m0 = -1e30f, m1 = -1e30f, l0 = 0.0f, l1 = 0.0f;
        float of[8][4];
#pragma unroll
        for (int j = 0; j < 8; j++)
#pragma unroll
            for (int e = 0; e < 4; e++) of[j][e] = 0.0f;

        const int qrow_w = qt * 128 + 16 * w;
        const int r0g = qrow_w + (lane >> 2);

#pragma unroll 1
        for (int kt = 0; kt <= kmax; kt++) {
            CP_WAIT(0);
            // barrier + all-reduce of the prefetched mask predicate
            const int okcur = __syncthreads_and(nextok);
            nextok = 1;

            if (kt < kmax) {
                const uint32_t kb = (uint32_t)(((kt + 1) & 1) * KVB);
#pragma unroll
                for (int p = 0; p < 4; p++) {
                    const int c   = t + (p << 8);
                    const int m   = c >> 9;
                    const int idx = c & 511;
                    const int row = idx >> 3;
                    const int ch  = idx & 7;
                    const __half* base = m ? vf : kf;
                    const uint32_t doff = m ? (uint32_t)V_OFF : (uint32_t)K_OFF;
                    CP_ASYNC16(sb + doff + kb + row * ASTR + ch * 16,
                               base + (size_t)(b * 1024 + (kt + 1) * 64 + row) * 1024 +
                                   h * 64 + ch * 8);
                }
                if (t < 64) {
                    const int mv = mask[b * TSEQ + (kt + 1) * 64 + t];
                    msk_s[((kt + 1) & 1) * 64 + t] = mv ? 0.0f : -1e30f;
                    nextok = (mv != 0);
                }
            }
            CP_COMMIT();

            const uint32_t kb = (uint32_t)((kt & 1) * KVB);

            // ---- S = q @ k^T (1 product) ----
            float s[8][4];
#pragma unroll
            for (int j = 0; j < 8; j++)
#pragma unroll
                for (int e = 0; e < 4; e++) s[j][e] = 0.0f;

#pragma unroll
            for (int ks = 0; ks < 4; ks++) {
                uint32_t aq[4];
                LDSM_X4(aq[0], aq[1], aq[2], aq[3], aq_base + ks * 32);
#pragma unroll
                for (int g = 0; g < 4; g++) {
                    uint32_t bk[4];
                    LDSM_X4(bk[0], bk[1], bk[2], bk[3],
                            bk_base + kb + g * (16 * ASTR) + ks * 32);
                    MMAF16(s[2 * g],     aq, bk[0], bk[1]);
                    MMAF16(s[2 * g + 1], aq, bk[2], bk[3]);
                }
            }

            // ---- mask (slow path only) + causal ----
            const int lc = 2 * (lane & 3);
            if (!okcur) {
                const float* msk = msk_s + (kt & 1) * 64;
#pragma unroll
                for (int j = 0; j < 8; j++) {
                    const float mj0 = msk[j * 8 + lc];
                    const float mj1 = msk[j * 8 + lc + 1];
                    s[j][0] += mj0; s[j][1] += mj1;
                    s[j][2] += mj0; s[j][3] += mj1;
                }
            }
            if (kt * 64 + 63 > qrow_w) {
                const int r1g = r0g + 8;
#pragma unroll
                for (int j = 0; j < 8; j++) {
                    const int c0 = kt * 64 + j * 8 + lc;
                    if (c0     > r0g) s[j][0] = -1e30f;
                    if (c0 + 1 > r0g) s[j][1] = -1e30f;
                    if (c0     > r1g) s[j][2] = -1e30f;
                    if (c0 + 1 > r1g) s[j][3] = -1e30f;
                }
            }

            // ---- online softmax (exp2 domain; l kept lane-local) ----
            float rm0 = -1e30f, rm1 = -1e30f;
#pragma unroll
            for (int j = 0; j < 8; j++) {
                rm0 = fmaxf(rm0, fmaxf(s[j][0], s[j][1]));
                rm1 = fmaxf(rm1, fmaxf(s[j][2], s[j][3]));
            }
            rm0 = fmaxf(rm0, __shfl_xor_sync(0xffffffffu, rm0, 1));
            rm0 = fmaxf(rm0, __shfl_xor_sync(0xffffffffu, rm0, 2));
            rm1 = fmaxf(rm1, __shfl_xor_sync(0xffffffffu, rm1, 1));
            rm1 = fmaxf(rm1, __shfl_xor_sync(0xffffffffu, rm1, 2));
            const float mn0 = fmaxf(m0, rm0), mn1 = fmaxf(m1, rm1);
            const float al0 = ex2(m0 - mn0), al1 = ex2(m1 - mn1);
            m0 = mn0; m1 = mn1;
            float ls0 = 0.0f, ls1 = 0.0f;
#pragma unroll
            for (int j = 0; j < 8; j++) {
                s[j][0] = ex2(s[j][0] - mn0); ls0 += s[j][0];
                s[j][1] = ex2(s[j][1] - mn0); ls0 += s[j][1];
                s[j][2] = ex2(s[j][2] - mn1); ls1 += s[j][2];
                s[j][3] = ex2(s[j][3] - mn1); ls1 += s[j][3];
            }
            // lane-local l update (alpha is quad-uniform; reduce at end)
            l0 = l0 * al0 + ls0;
            l1 = l1 * al1 + ls1;
#pragma unroll
            for (int j = 0; j < 8; j++) {
                of[j][0] *= al0; of[j][1] *= al0;
                of[j][2] *= al1; of[j][3] *= al1;
            }

            // ---- O += p_f16 @ v_f16 (trans-ldmatrix B fragments) ----
#pragma unroll
            for (int kt2 = 0; kt2 < 4; kt2++) {
                uint32_t ap[4];
                {
                    const float* p0 = s[2 * kt2];
                    const float* p1 = s[2 * kt2 + 1];
                    ap[0] = packhf(p0[0], p0[1]); ap[1] = packhf(p0[2], p0[3]);
                    ap[2] = packhf(p1[0], p1[1]); ap[3] = packhf(p1[2], p1[3]);
                }
#pragma unroll
                for (int g = 0; g < 4; g++) {
                    uint32_t bv[4];
                    LDSM_X4T(bv[0], bv[1], bv[2], bv[3],
                             bv_base + kb + (uint32_t)(kt2 * (16 * ASTR) + g * 32));
                    MMAF16(of[2 * g],     ap, bv[0], bv[1]);
                    MMAF16(of[2 * g + 1], ap, bv[2], bv[3]);
                }
            }
        }

        // ---- final cross-lane l reduction, normalize + store fp16 ----
        l0 += __shfl_xor_sync(0xffffffffu, l0, 1);
        l0 += __shfl_xor_sync(0xffffffffu, l0, 2);
        l1 += __shfl_xor_sync(0xffffffffu, l1, 1);
        l1 += __shfl_xor_sync(0xffffffffu, l1, 2);
        const float inv0 = 1.0f / l0, inv1 = 1.0f / l1;
        const size_t obase = ((size_t)(b * TSEQ) + r0g) * DMODEL + h * DHEAD + 2 * (lane & 3);
#pragma unroll
        for (int j = 0; j < 8; j++) {
            *reinterpret_cast<uint32_t*>(ao + obase + j * 8) =
                packhf(of[j][0] * inv0, of[j][1] * inv0);
            *reinterpret_cast<uint32_t*>(ao + obase + (size_t)8 * DMODEL + j * 8) =
                packhf(of[j][2] * inv1, of[j][3] * inv1);
        }
    }
}

// ---------------------------------------------------------------------------
extern "C" void kernel_launch(void* const* d_in, const int* in_sizes, int n_in,
                              void* d_out, int out_size)
{
    const float* x     = (const float*)d_in[0];
    const float* Wqkv  = (const float*)d_in[1];
    const float* bqkv  = (const float*)d_in[2];
    const float* Wproj = (const float*)d_in[3];
    const float* bproj = (const float*)d_in[4];
    const int*   mask  = (const int*)d_in[5];
    float* out = (float*)d_out;

    __half *x16, *wq16, *wp16, *ao16, *qf, *kf, *vf;
    cudaGetSymbolAddress((void**)&x16,  g_x16);
    cudaGetSymbolAddress((void**)&wq16, g_wq16);
    cudaGetSymbolAddress((void**)&wp16, g_wp16);
    cudaGetSymbolAddress((void**)&ao16, g_ao16);
    cudaGetSymbolAddress((void**)&qf,  g_qf);
    cudaGetSymbolAddress((void**)&kf,  g_kf);
    cudaGetSymbolAddress((void**)&vf,  g_vf);

    cudaFuncSetAttribute(attn_hmma,
                         cudaFuncAttributeMaxDynamicSharedMemorySize, ATTN_SMEM);
    cudaFuncSetAttribute(gemm_f16<0>,
                         cudaFuncAttributeMaxDynamicSharedMemorySize, GEMM_SMEM);
    cudaFuncSetAttribute(gemm_f16<1>,
                         cudaFuncAttributeMaxDynamicSharedMemorySize, GEMM_SMEM);

    // Convert input and both weights (transposed to [N][K]) to fp16
    convert_h<<<(MROWS * DMODEL) / 1024, 256>>>(x, x16);
    convert_wT2<<<dim3(QKV_N / 32, DMODEL / 32, 2), dim3(32, 8)>>>(
        Wqkv, wq16, QKV_N, Wproj, wp16, DMODEL, DMODEL);

    // 1) QKV GEMM (fp16 single-product) -> Q/K/V single fp16
    gemm_f16<1><<<dim3(QKV_N / 128, MROWS / 128), 128, GEMM_SMEM>>>(
        x16, wq16, bqkv, nullptr, qf, kf, vf, QKV_N);

    // 2) Fused causal attention (V transposed in-register via ldmatrix.trans)
    attn_hmma<<<dim3(4, BATCH * NH), 256, ATTN_SMEM>>>(
        qf, kf, vf, mask, ao16);

    // 3) out = attn @ Wproj + bproj (fp16 single-product)
    gemm_f16<0><<<dim3(DMODEL / 128, MROWS / 128), 128, GEMM_SMEM>>>(
        ao16, wp16, bproj, out,
        nullptr, nullptr, nullptr, DMODEL);
}